// round 12
// baseline (speedup 1.0000x reference)
#include <cuda_runtime.h>
#include <math.h>
#include <stdint.h>

#define EXP 4
#define NTOK 2048
#define DIM 512
#define NH 8
#define DHEAD 64
#define FFD 2048
#define NL 4
#define MEMSZ 4096

#define ND_ELEMS (NTOK * DIM)
#define LMD_ELEMS (NL * MEMSZ * DIM)

#define GFLAG_RELU 1
#define GFLAG_ACCUM 2
#define GFLAG_TFOUT 4
#define GFLAG_KREMAP 8

// ---------------- scratch ----------------
__device__ float g_xln[EXP * NTOK * DIM];
__device__ float g_xlnT[EXP * NTOK * DIM];
__device__ float g_x4[EXP * NTOK * DIM];
__device__ float g_qkv4[(size_t)EXP * NTOK * 3 * DIM];
__device__ float g_big[(size_t)EXP * NH * NTOK * NTOK];
__device__ float g_sa4[EXP * NTOK * DIM];
__device__ float g_op4[EXP * NTOK * DIM];
__device__ float g_tmp4[(size_t)EXP * NTOK * FFD];
__device__ float g_x14[EXP * NTOK * DIM];
__device__ float g_x1r4[EXP * NTOK * DIM];
__device__ float g_xor4[EXP * NTOK * DIM];
__device__ float g_xorT[EXP * NTOK * DIM];
__device__ float g_out[EXP * NTOK * DIM];
__device__ float g_retr4[(size_t)EXP * NL * NTOK * DIM];
__device__ float g_retrp4[(size_t)EXP * NTOK * NL * DIM];
__device__ float g_upd4[(size_t)EXP * NL * MEMSZ * DIM];
__device__ float g_glog[EXP];
__device__ float g_vT[(size_t)EXP * NTOK * DIM];
__device__ float g_memT[LMD_ELEMS];
__device__ float g_ipw_r[EXP * 3 * DIM * DIM];
__device__ float g_opw_r[EXP * DIM * DIM];
__device__ float g_w1_r[EXP * FFD * DIM];
__device__ float g_w2_r[EXP * DIM * FFD];
__device__ float g_aggw_r[DIM * NL * DIM];
__device__ float g_mem_r[LMD_ELEMS];

// ---------------- helpers ----------------
__device__ __forceinline__ uint32_t tf(float x) {
    uint32_t u; asm("cvt.rna.tf32.f32 %0, %1;" : "=r"(u) : "f"(x)); return u;
}
__device__ __forceinline__ float tff(float x) { return __uint_as_float(tf(x)); }
__device__ __forceinline__ float4 tff4(float4 v) {
    return make_float4(tff(v.x), tff(v.y), tff(v.z), tff(v.w));
}
__device__ __forceinline__ void mma8(float* c, const uint32_t* a, const uint32_t* b) {
    asm volatile(
        "mma.sync.aligned.m16n8k8.row.col.f32.tf32.tf32.f32 "
        "{%0,%1,%2,%3}, {%4,%5,%6,%7}, {%8,%9}, {%0,%1,%2,%3};"
        : "+f"(c[0]), "+f"(c[1]), "+f"(c[2]), "+f"(c[3])
        : "r"(a[0]), "r"(a[1]), "r"(a[2]), "r"(a[3]), "r"(b[0]), "r"(b[1]));
}
__device__ __forceinline__ void cpa16(uint32_t s, const float* g) {
    asm volatile("cp.async.cg.shared.global [%0], [%1], 16;" :: "r"(s), "l"(g));
}
__device__ __forceinline__ void ldsm4(uint32_t* r, uint32_t a) {
    asm volatile("ldmatrix.sync.aligned.m8n8.x4.shared.b16 {%0,%1,%2,%3}, [%4];"
        : "=r"(r[0]), "=r"(r[1]), "=r"(r[2]), "=r"(r[3]) : "r"(a));
}

__global__ void tfround_k(const float4* __restrict__ s, float4* __restrict__ d, long long n4) {
    long long i = (long long)blockIdx.x * 256 + threadIdx.x;
    if (i < n4) d[i] = tff4(s[i]);
}

template <int ROUND>
__global__ void transpose_k(const float* __restrict__ in, float* __restrict__ out,
                            int rows, int cols, int ldin,
                            long long inB, long long outB) {
    __shared__ float tile[32][33];
    int z = blockIdx.z;
    in += inB * z; out += outB * z;
    int c0 = blockIdx.x * 32, r0 = blockIdx.y * 32;
    int x = threadIdx.x, y = threadIdx.y;
#pragma unroll
    for (int j = 0; j < 32; j += 8)
        tile[y + j][x] = in[(long long)(r0 + y + j) * ldin + c0 + x];
    __syncthreads();
#pragma unroll
    for (int j = 0; j < 32; j += 8) {
        float v = tile[x][y + j];
        out[(long long)(c0 + y + j) * rows + r0 + x] = ROUND ? tff(v) : v;
    }
}

// ---------------- cp.async tf32 mma GEMM, expert-batched z ----------------
template <int MT, int NT, bool ATR, bool BTR, int OCC>
__global__ void __launch_bounds__(256, OCC) gemmCP(
    const float* __restrict__ A, const float* __restrict__ B, float* __restrict__ C,
    int K, int lda, int ldb, int ldc,
    long long aB, long long aBi, long long bB, long long bBi,
    long long cB, long long cBi, int zInner,
    float alpha, const float* __restrict__ bias, long long biasB,
    const float* __restrict__ resid, long long residB, int residLd,
    float clipVal, int flags, int rs, int rl)
{
    constexpr int KC = 16;
    constexpr int AST = 20;
    constexpr int MST = MT + 8;
    constexpr int NST = NT + 8;
    constexpr int ASZ = ATR ? KC * MST : MT * AST;
    constexpr int BSZ = BTR ? KC * NST : NT * AST;
    constexpr int STG = ASZ + BSZ;
    constexpr int MI = MT / 32;
    constexpr int NB = NT / 32;

    extern __shared__ float sm[];
    uint32_t smb = (uint32_t)__cvta_generic_to_shared(sm);

    const int t = threadIdx.x, l = t & 31, w = t >> 5;
    const int bz = blockIdx.z;
    const int zo = bz / zInner, zi = bz - zo * zInner;
    A += aB * zo + aBi * zi;
    B += bB * zo + bBi * zi;
    C += cB * zo + cBi * zi;
    if (bias) bias += biasB * zo;
    if (resid) resid += residB * zo;
    if (rs < 0) rs = zo * rl;
    const int m0 = blockIdx.y * MT, n0 = blockIdx.x * NT;
    const int wm0 = (w >> 2) * (MT / 2), wn0 = (w & 3) * (NT / 4);

    const uint32_t aBase = (uint32_t)(((wm0 + ((l >> 3 & 1) << 3) + (l & 7)) * AST + ((l >> 4) << 2)) * 4);
    const uint32_t bBase4 = (uint32_t)(((wn0 + ((l >> 4) << 3) + (l & 7)) * AST + ((l >> 3 & 1) << 2)) * 4);
    const int atrOff = (l & 3) * MST + wm0 + (l >> 2);
    const int btrOff = (l & 3) * NST + wn0 + (l >> 2);

    float acc[MI][NB][4];
#pragma unroll
    for (int a = 0; a < MI; a++)
#pragma unroll
        for (int b = 0; b < NB; b++)
#pragma unroll
            for (int c = 0; c < 4; c++) acc[a][b][c] = 0.f;

    const int nK = K / KC;
    const bool kRemap = (flags & GFLAG_KREMAP) != 0;

    auto issue = [&](int s, int k0) {
        uint32_t ab = smb + (uint32_t)(s * STG * 4);
        uint32_t bb = ab + ASZ * 4;
        if (!ATR) {
            constexpr int ACH = MT * 4;
#pragma unroll
            for (int c0 = 0; c0 < ACH; c0 += 256) {
                int c = c0 + t;
                int row = c >> 2, kq = c & 3;
                cpa16(ab + (uint32_t)(row * AST + kq * 4) * 4,
                      &A[(long long)(m0 + row) * lda + k0 + kq * 4]);
            }
        } else {
            constexpr int AQ = MT / 4;
            constexpr int ASH = (MT == 128) ? 5 : 4;
            constexpr int ACH = KC * AQ;
#pragma unroll
            for (int c0 = 0; c0 < ACH; c0 += 256) {
                int c = c0 + t;
                int kr = c >> ASH, mq = c & (AQ - 1);
                cpa16(ab + (uint32_t)(kr * MST + mq * 4) * 4,
                      &A[(long long)(k0 + kr) * lda + m0 + mq * 4]);
            }
        }
        if (!BTR) {
            constexpr int BCH = NT * 4;
#pragma unroll
            for (int c0 = 0; c0 < BCH; c0 += 256) {
                int c = c0 + t;
                int row = c >> 2, kq = c & 3;
                int n = n0 + row;
                int g = k0 + kq * 4;
                if (rl) {
                    if (kRemap) { if (g >= rs) g += rl; }
                    else { if (n >= rs) n += rl; }
                }
                cpa16(bb + (uint32_t)(row * AST + kq * 4) * 4,
                      &B[(long long)n * ldb + g]);
            }
        } else {
            constexpr int NQ = NT / 4;
            constexpr int SH = (NT == 128) ? 5 : 4;
            constexpr int BCH = KC * NQ;
#pragma unroll
            for (int c0 = 0; c0 < BCH; c0 += 256) {
                int c = c0 + t;
                int kr = c >> SH, nq = c & (NQ - 1);
                int g = k0 + kr;
                if (rl && g >= rs) g += rl;
                cpa16(bb + (uint32_t)(kr * NST + nq * 4) * 4,
                      &B[(long long)g * ldb + n0 + nq * 4]);
            }
        }
        asm volatile("cp.async.commit_group;" ::: "memory");
    };

    issue(0, 0);
    issue(1, KC);
    issue(2, 2 * KC);

    for (int i = 0; i < nK; i++) {
        asm volatile("cp.async.wait_group 2;" ::: "memory");
        __syncthreads();
        if (i + 3 < nK) issue((i + 3) & 3, (i + 3) * KC);

        const float* Ab = sm + (i & 3) * STG;
        const float* Bb = Ab + ASZ;
        uint32_t abu = smb + (uint32_t)((i & 3) * STG * 4);
        uint32_t bbu = abu + (uint32_t)(ASZ * 4);
#pragma unroll
        for (int kk = 0; kk < 2; kk++) {
            const int kc = kk * 8;
            uint32_t af[MI][4], bf[NB][2];
#pragma unroll
            for (int mi = 0; mi < MI; mi++) {
                if (!ATR) {
                    ldsm4(af[mi], abu + aBase + (uint32_t)((mi * 16 * AST + kc) * 4));
                } else {
                    const uint32_t* ap = (const uint32_t*)&Ab[kc * MST + atrOff + mi * 16];
                    af[mi][0] = ap[0];
                    af[mi][1] = ap[8];
                    af[mi][2] = ap[4 * MST];
                    af[mi][3] = ap[4 * MST + 8];
                }
            }
            if (!BTR) {
#pragma unroll
                for (int nj = 0; nj < NB / 2; nj++) {
                    uint32_t r4[4];
                    ldsm4(r4, bbu + bBase4 + (uint32_t)((nj * 16 * AST + kc) * 4));
                    bf[2 * nj][0] = r4[0]; bf[2 * nj][1] = r4[1];
                    bf[2 * nj + 1][0] = r4[2]; bf[2 * nj + 1][1] = r4[3];
                }
            } else {
#pragma unroll
                for (int ni = 0; ni < NB; ni++) {
                    const uint32_t* bp = (const uint32_t*)&Bb[kc * NST + btrOff + ni * 8];
                    bf[ni][0] = bp[0];
                    bf[ni][1] = bp[4 * NST];
                }
            }
#pragma unroll
            for (int mi = 0; mi < MI; mi++)
#pragma unroll
                for (int ni = 0; ni < NB; ni++) mma8(acc[mi][ni], af[mi], bf[ni]);
        }
    }

    // epilogue
#pragma unroll
    for (int mi = 0; mi < MI; mi++) {
        int row0 = m0 + wm0 + mi * 16 + (l >> 2);
#pragma unroll
        for (int ni = 0; ni < NB; ni++) {
            int col = n0 + wn0 + ni * 8 + (l & 3) * 2;
#pragma unroll
            for (int h = 0; h < 2; h++) {
                int row = row0 + h * 8;
                float vx = alpha * acc[mi][ni][h * 2];
                float vy = alpha * acc[mi][ni][h * 2 + 1];
                if (bias) { vx += bias[col]; vy += bias[col + 1]; }
                if (flags & GFLAG_RELU) { vx = fmaxf(vx, 0.f); vy = fmaxf(vy, 0.f); }
                if (clipVal > 0.f) {
                    vx = fminf(fmaxf(vx, -clipVal), clipVal);
                    vy = fminf(fmaxf(vy, -clipVal), clipVal);
                }
                if (resid) {
                    float2 rv = *(const float2*)&resid[(long long)row * residLd + col];
                    vx += rv.x; vy += rv.y;
                }
                float2* cp = (float2*)&C[(long long)row * ldc + col];
                if (flags & GFLAG_ACCUM) {
                    float2 o = *cp;
                    vx += o.x; vy += o.y;
                }
                if (flags & GFLAG_TFOUT) { vx = tff(vx); vy = tff(vy); }
                *cp = make_float2(vx, vy);
            }
        }
    }
}

// ---------------- reductions ----------------
__device__ __forceinline__ float warpReduceSum(float v) {
#pragma unroll
    for (int o = 16; o; o >>= 1) v += __shfl_xor_sync(0xffffffffu, v, o);
    return v;
}
__device__ __forceinline__ float warpReduceMax(float v) {
#pragma unroll
    for (int o = 16; o; o >>= 1) v = fmaxf(v, __shfl_xor_sync(0xffffffffu, v, o));
    return v;
}

// ---------------- vectorized smem-cached row softmax ----------------
__global__ void softmax_k(float* __restrict__ p, int cols) {
    extern __shared__ float4 sb4[];
    float4* row = (float4*)(p + (long long)blockIdx.x * cols);
    int nc4 = cols >> 2;
    __shared__ float sh[8];
    __shared__ float sb;
    int tid = threadIdx.x, lane = tid & 31, wid = tid >> 5;
    float m = -1e30f;
    for (int i = tid; i < nc4; i += 256) {
        float4 v = row[i]; sb4[i] = v;
        m = fmaxf(m, fmaxf(fmaxf(v.x, v.y), fmaxf(v.z, v.w)));
    }
    m = warpReduceMax(m);
    if (lane == 0) sh[wid] = m;
    __syncthreads();
    if (tid == 0) { float x = sh[0]; for (int q = 1; q < 8; q++) x = fmaxf(x, sh[q]); sb = x; }
    __syncthreads();
    m = sb;
    float s = 0.f;
    for (int i = tid; i < nc4; i += 256) {
        float4 v = sb4[i];
        v.x = expf(v.x - m); v.y = expf(v.y - m); v.z = expf(v.z - m); v.w = expf(v.w - m);
        sb4[i] = v;
        s += v.x + v.y + v.z + v.w;
    }
    s = warpReduceSum(s);
    if (lane == 0) sh[wid] = s;
    __syncthreads();
    if (tid == 0) { float x = 0; for (int q = 0; q < 8; q++) x += sh[q]; sb = 1.f / x; }
    __syncthreads();
    float inv = sb;
    for (int i = tid; i < nc4; i += 256) {
        float4 v = sb4[i];
        row[i] = make_float4(tff(v.x * inv), tff(v.y * inv), tff(v.z * inv), tff(v.w * inv));
    }
}

// ---------------- LayerNorm (vectorized, rounded output) ----------------
__global__ void ln_k(const float* __restrict__ src, float* __restrict__ dst) {
    long long row = blockIdx.x;
    const float4* x = (const float4*)(src + row * DIM);
    float4* y = (float4*)(dst + row * DIM);
    int tid = threadIdx.x, lane = tid & 31, wid = tid >> 5;
    float4 v = x[tid];
    float s = v.x + v.y + v.z + v.w;
    float s2 = v.x * v.x + v.y * v.y + v.z * v.z + v.w * v.w;
    s = warpReduceSum(s); s2 = warpReduceSum(s2);
    __shared__ float sh[2][4]; __shared__ float mv[2];
    if (lane == 0) { sh[0][wid] = s; sh[1][wid] = s2; }
    __syncthreads();
    if (tid == 0) {
        float a = sh[0][0] + sh[0][1] + sh[0][2] + sh[0][3];
        float b = sh[1][0] + sh[1][1] + sh[1][2] + sh[1][3];
        float mean = a / DIM;
        mv[0] = mean; mv[1] = rsqrtf(b / DIM - mean * mean + 1e-5f);
    }
    __syncthreads();
    float mean = mv[0], rstd = mv[1];
    y[tid] = make_float4(tff((v.x - mean) * rstd), tff((v.y - mean) * rstd),
                         tff((v.z - mean) * rstd), tff((v.w - mean) * rstd));
}

__global__ void ln_ra_k(const float* __restrict__ a, const float* __restrict__ b,
                        const float* __restrict__ wAll, const float* __restrict__ bAll,
                        float* __restrict__ dst, float* __restrict__ dstr) {
    long long row = blockIdx.x;
    int e = (int)(row >> 11);
    const float4* xa = (const float4*)(a + row * DIM);
    const float4* xb = (const float4*)(b + row * DIM);
    const float4* w = (const float4*)(wAll + (long long)e * DIM);
    const float4* bb = (const float4*)(bAll + (long long)e * DIM);
    float4* y = (float4*)(dst + row * DIM);
    float4* yr = (float4*)(dstr + row * DIM);
    int tid = threadIdx.x, lane = tid & 31, wid = tid >> 5;
    float4 va = xa[tid], vb = xb[tid];
    float4 v = make_float4(va.x + vb.x, va.y + vb.y, va.z + vb.z, va.w + vb.w);
    float s = v.x + v.y + v.z + v.w;
    float s2 = v.x * v.x + v.y * v.y + v.z * v.z + v.w * v.w;
    s = warpReduceSum(s); s2 = warpReduceSum(s2);
    __shared__ float sh[2][4]; __shared__ float mv[2];
    if (lane == 0) { sh[0][wid] = s; sh[1][wid] = s2; }
    __syncthreads();
    if (tid == 0) {
        float p = sh[0][0] + sh[0][1] + sh[0][2] + sh[0][3];
        float q = sh[1][0] + sh[1][1] + sh[1][2] + sh[1][3];
        float mean = p / DIM;
        mv[0] = mean; mv[1] = rsqrtf(q / DIM - mean * mean + 1e-5f);
    }
    __syncthreads();
    float mean = mv[0], rstd = mv[1];
    float4 ww = w[tid], bbv = bb[tid];
    float4 o = make_float4((v.x - mean) * rstd * ww.x + bbv.x,
                           (v.y - mean) * rstd * ww.y + bbv.y,
                           (v.z - mean) * rstd * ww.z + bbv.z,
                           (v.w - mean) * rstd * ww.w + bbv.w);
    y[tid] = o;
    yr[tid] = tff4(o);
}

__global__ void permute_k(const float4* __restrict__ retr, float4* __restrict__ rp) {
    long long i = (long long)blockIdx.x * 256 + threadIdx.x;
    constexpr int D4 = DIM / 4;
    if (i < (long long)EXP * NL * NTOK * D4) {
        int d4 = (int)(i & (D4 - 1));
        long long r = i >> 7;
        int n = (int)(r & (NTOK - 1));
        long long r2 = r >> 11;
        int lay = (int)(r2 & (NL - 1));
        long long e = r2 >> 2;
        rp[((e * NTOK + n) * NL + lay) * D4 + d4] = tff4(retr[i]);
    }
}

__global__ void zero_k(float* __restrict__ p, long long n) {
    long long i = (long long)blockIdx.x * 256 + threadIdx.x;
    if (i < n) p[i] = 0.f;
}

__global__ void gate_dot_k(const float* __restrict__ outs, const float* __restrict__ gg,
                           float* __restrict__ glog) {
    int e = blockIdx.x;
    constexpr int D4 = DIM / 4;
    long long chunk4 = (long long)(ND_ELEMS / 4) / gridDim.y;
    const float4* base = (const float4*)(outs) + (long long)e * (ND_ELEMS / 4) + (long long)blockIdx.y * chunk4;
    const float4* gg4 = (const float4*)gg;
    float acc = 0.f;
    for (long long i = threadIdx.x; i < chunk4; i += blockDim.x) {
        float4 v = base[i];
        float4 g = gg4[i & (D4 - 1)];
        acc += v.x * g.x + v.y * g.y + v.z * g.z + v.w * g.w;
    }
    acc = warpReduceSum(acc);
    __shared__ float sh[8];
    int lane = threadIdx.x & 31, wid = threadIdx.x >> 5;
    if (lane == 0) sh[wid] = acc;
    __syncthreads();
    if (threadIdx.x == 0) {
        float x = 0;
        for (int q = 0; q < 8; q++) x += sh[q];
        atomicAdd(&glog[e], x);
    }
}

__global__ void gate_softmax_k(const float* __restrict__ glog, float* __restrict__ gw) {
    if (threadIdx.x == 0) {
        float l[EXP], m = -1e30f;
        for (int e = 0; e < EXP; e++) {
            l[e] = fminf(fmaxf(glog[e] / (float)NTOK, -10.f), 10.f);
            m = fmaxf(m, l[e]);
        }
        float s = 0.f;
        for (int e = 0; e < EXP; e++) { l[e] = expf(l[e] - m); s += l[e]; }
        for (int e = 0; e < EXP; e++) gw[e] = l[e] / s;
    }
}

__global__ void fuse_k(const float4* __restrict__ outs, const float* __restrict__ gw,
                       float4* __restrict__ fused) {
    long long i = (long long)blockIdx.x * 256 + threadIdx.x;
    constexpr long long N4 = ND_ELEMS / 4;
    if (i < N4) {
        float4 r = make_float4(0.f, 0.f, 0.f, 0.f);
#pragma unroll
        for (int e = 0; e < EXP; e++) {
            float4 v = outs[(long long)e * N4 + i];
            float gwe = gw[e];
            r.x += gwe * v.x; r.y += gwe * v.y; r.z += gwe * v.z; r.w += gwe * v.w;
        }
        fused[i] = r;
    }
}

__global__ void memupd_k(const float4* __restrict__ mem, const float4* __restrict__ upd4,
                         float4* __restrict__ o) {
    long long i = (long long)blockIdx.x * 256 + threadIdx.x;
    constexpr long long N4 = (long long)LMD_ELEMS / 4;
    if (i < N4) {
        float4 u = upd4[i];
#pragma unroll
        for (int e = 1; e < EXP; e++) {
            float4 v = upd4[(long long)e * N4 + i];
            u.x += v.x; u.y += v.y; u.z += v.z; u.w += v.w;
        }
        float4 mm = mem[i];
        float4 r;
        r.x = 0.9f * mm.x + fminf(fmaxf(0.1f * u.x, -0.1f), 0.1f);
        r.y = 0.9f * mm.y + fminf(fmaxf(0.1f * u.y, -0.1f), 0.1f);
        r.z = 0.9f * mm.z + fminf(fmaxf(0.1f * u.z, -0.1f), 0.1f);
        r.w = 0.9f * mm.w + fminf(fmaxf(0.1f * u.w, -0.1f), 0.1f);
        o[i] = r;
    }
}

// ---------------- host ----------------
static constexpr int stgFl(int MT, int NT, bool ATR, bool BTR) {
    return (ATR ? 16 * (MT + 8) : MT * 20) + (BTR ? 16 * (NT + 8) : NT * 20);
}
#define SMEMB(MT, NT, ATR, BTR) (4 * stgFl(MT, NT, ATR, BTR) * 4)

static void tfround(const float* s, float* d, long long n) {
    long long n4 = n / 4;
    tfround_k<<<(int)((n4 + 255) / 256), 256>>>((const float4*)s, (float4*)d, n4);
}

extern "C" void kernel_launch(void* const* d_in, const int* in_sizes, int n_in,
                              void* d_out, int out_size) {
    const float* tokens   = (const float*)d_in[0];
    const float* memories = (const float*)d_in[1];
    const float* ipw      = (const float*)d_in[2];
    const float* ipb      = (const float*)d_in[3];
    const float* opw      = (const float*)d_in[4];
    const float* opb      = (const float*)d_in[5];
    const float* w1       = (const float*)d_in[6];
    const float* b1       = (const float*)d_in[7];
    const float* w2       = (const float*)d_in[8];
    const float* b2       = (const float*)d_in[9];
    const float* n1w      = (const float*)d_in[10];
    const float* n1b      = (const float*)d_in[11];
    const float* n2w      = (const float*)d_in[12];
    const float* n2b      = (const float*)d_in[13];
    const float* aggw     = (const float*)d_in[14];
    const float* aggb     = (const float*)d_in[15];
    const float* gg       = (const float*)d_in[16];

    float* out = (float*)d_out;
    float* out_fused = out;
    float* out_gw = out + ND_ELEMS;
    float* out_mem = out + ND_ELEMS + EXP;

    static float *p_xln = nullptr, *p_xlnT = nullptr, *p_x4 = nullptr, *p_qkv4 = nullptr,
                 *p_big = nullptr, *p_sa4 = nullptr, *p_op4 = nullptr, *p_tmp4 = nullptr,
                 *p_x14 = nullptr, *p_x1r4 = nullptr, *p_xor4 = nullptr, *p_xorT = nullptr,
                 *p_out = nullptr, *p_retr4 = nullptr, *p_retrp4 = nullptr, *p_upd4 = nullptr,
                 *p_glog = nullptr, *p_vT = nullptr, *p_memT = nullptr,
                 *p_ipw = nullptr, *p_opw = nullptr, *p_w1 = nullptr, *p_w2 = nullptr,
                 *p_aggw = nullptr, *p_mem = nullptr;
    if (!p_xln) {
        cudaGetSymbolAddress((void**)&p_xln, g_xln);
        cudaGetSymbolAddress((void**)&p_xlnT, g_xlnT);
        cudaGetSymbolAddress((void**)&p_x4, g_x4);
        cudaGetSymbolAddress((void**)&p_qkv4, g_qkv4);
        cudaGetSymbolAddress((void**)&p_big, g_big);
        cudaGetSymbolAddress((void**)&p_sa4, g_sa4);
        cudaGetSymbolAddress((void**)&p_op4, g_op4);
        cudaGetSymbolAddress((void**)&p_tmp4, g_tmp4);
        cudaGetSymbolAddress((void**)&p_x14, g_x14);
        cudaGetSymbolAddress((void**)&p_x1r4, g_x1r4);
        cudaGetSymbolAddress((void**)&p_xor4, g_xor4);
        cudaGetSymbolAddress((void**)&p_xorT, g_xorT);
        cudaGetSymbolAddress((void**)&p_out, g_out);
        cudaGetSymbolAddress((void**)&p_retr4, g_retr4);
        cudaGetSymbolAddress((void**)&p_retrp4, g_retrp4);
        cudaGetSymbolAddress((void**)&p_upd4, g_upd4);
        cudaGetSymbolAddress((void**)&p_glog, g_glog);
        cudaGetSymbolAddress((void**)&p_vT, g_vT);
        cudaGetSymbolAddress((void**)&p_memT, g_memT);
        cudaGetSymbolAddress((void**)&p_ipw, g_ipw_r);
        cudaGetSymbolAddress((void**)&p_opw, g_opw_r);
        cudaGetSymbolAddress((void**)&p_w1, g_w1_r);
        cudaGetSymbolAddress((void**)&p_w2, g_w2_r);
        cudaGetSymbolAddress((void**)&p_aggw, g_aggw_r);
        cudaGetSymbolAddress((void**)&p_mem, g_mem_r);
        cudaFuncSetAttribute(gemmCP<64, 128, false, false, 3>, cudaFuncAttributeMaxDynamicSharedMemorySize, SMEMB(64, 128, false, false));
        cudaFuncSetAttribute(gemmCP<64, 64, false, false, 3>,  cudaFuncAttributeMaxDynamicSharedMemorySize, SMEMB(64, 64, false, false));
        cudaFuncSetAttribute(gemmCP<64, 256, false, false, 2>, cudaFuncAttributeMaxDynamicSharedMemorySize, SMEMB(64, 256, false, false));
        cudaFuncSetAttribute(gemmCP<64, 256, true, false, 2>,  cudaFuncAttributeMaxDynamicSharedMemorySize, SMEMB(64, 256, true, false));
    }

    const float inv_sqrt_d = 1.0f / sqrtf((float)DIM);
    const float inv_sqrt_dh = 1.0f / sqrtf((float)DHEAD);

    const long long LLND = ND_ELEMS;
    const long long BIGE = (long long)NH * NTOK * NTOK;
    const long long QKVE = (long long)NTOK * 3 * DIM;

    // launches 1-5 (so the 6th = cross-logits GEMM gets ncu'd)
    zero_k<<<1, 256>>>(p_glog, EXP);
    ln_k<<<EXP * NTOK, 128>>>(tokens, p_xln);
    transpose_k<0><<<dim3(DIM / 32, EXP * NTOK / 32, 1), dim3(32, 8)>>>(
        p_xln, p_xlnT, EXP * NTOK, DIM, DIM, 0, 0);
    tfround(ipw, p_ipw, (long long)EXP * 3 * DIM * DIM);
    tfround(opw, p_opw, (long long)EXP * DIM * DIM);

    // 1. cross logits [e][2048, 6144]   <- 6th launch (ncu target)
    gemmCP<64, 128, false, false, 3><<<dim3(48, 32, EXP), 256, SMEMB(64, 128, false, false)>>>(
        p_xln, p_xln, p_big, DIM, DIM, DIM, 3 * NTOK,
        LLND, 0, 0, 0, (long long)NTOK * 3 * NTOK, 0, 1,
        inv_sqrt_d, nullptr, 0, nullptr, 0, 0, 10.f, 0, -1, NTOK);

    // remaining weight prep (independent of cross/softmax chain)
    tfround(w1, p_w1, (long long)EXP * FFD * DIM);
    tfround(w2, p_w2, (long long)EXP * DIM * FFD);
    tfround(aggw, p_aggw, (long long)DIM * NL * DIM);
    tfround(memories, p_mem, (long long)LMD_ELEMS);
    transpose_k<1><<<dim3(DIM / 32, MEMSZ / 32, NL), dim3(32, 8)>>>(
        memories, p_memT, MEMSZ, DIM, DIM, (long long)MEMSZ * DIM, (long long)MEMSZ * DIM);

    softmax_k<<<EXP * NTOK, 256, 3 * NTOK * 4>>>(p_big, 3 * NTOK);
    // 2. x = probs @ ctx + xln (natural via xlnT, k-remap, rounded)
    gemmCP<64, 128, false, false, 3><<<dim3(4, 32, EXP), 256, SMEMB(64, 128, false, false)>>>(
        p_big, p_xlnT, p_x4, 3 * NTOK, 3 * NTOK, EXP * NTOK, DIM,
        (long long)NTOK * 3 * NTOK, 0, 0, 0, LLND, 0, 1,
        1.f, nullptr, 0, p_xln, LLND, DIM, 0.f, GFLAG_TFOUT | GFLAG_KREMAP, -1, NTOK);
    // 3. qkv (rounded)
    gemmCP<64, 128, false, false, 3><<<dim3(12, 32, EXP), 256, SMEMB(64, 128, false, false)>>>(
        p_x4, p_ipw, p_qkv4, DIM, DIM, DIM, 3 * DIM,
        LLND, 0, (long long)3 * DIM * DIM, 0, QKVE, 0, 1,
        1.f, ipb, 3 * DIM, nullptr, 0, 0, 0.f, GFLAG_TFOUT, 0, 0);
    transpose_k<0><<<dim3(DIM / 32, NTOK / 32, EXP), dim3(32, 8)>>>(
        p_qkv4 + 2 * DIM, p_vT, NTOK, DIM, 3 * DIM, QKVE, LLND);
    // 4. scores [e][h][2048,2048]
    gemmCP<64, 128, false, false, 3><<<dim3(16, 32, EXP * NH), 256, SMEMB(64, 128, false, false)>>>(
        p_qkv4, p_qkv4 + DIM, p_big, DHEAD, 3 * DIM, 3 * DIM, NTOK,
        QKVE, DHEAD, QKVE, DHEAD, BIGE, (long long)NTOK * NTOK, NH,
        inv_sqrt_dh, nullptr, 0, nullptr, 0, 0, 0.f, 0, 0, 0);
    softmax_k<<<EXP * NH * NTOK, 256, NTOK * 4>>>(p_big, NTOK);
    // 5. sa = probs @ v (natural via vT, rounded)
    gemmCP<64, 64, false, false, 3><<<dim3(1, 32, EXP * NH), 256, SMEMB(64, 64, false, false)>>>(
        p_big, p_vT, p_sa4, NTOK, NTOK, NTOK, DIM,
        BIGE, (long long)NTOK * NTOK, LLND, (long long)DHEAD * NTOK, LLND, DHEAD, NH,
        1.f, nullptr, 0, nullptr, 0, 0, 0.f, GFLAG_TFOUT, 0, 0);
    // 6. out_proj
    gemmCP<64, 128, false, false, 3><<<dim3(4, 32, EXP), 256, SMEMB(64, 128, false, false)>>>(
        p_sa4, p_opw, p_op4, DIM, DIM, DIM, DIM,
        LLND, 0, (long long)DIM * DIM, 0, LLND, 0, 1,
        1.f, opb, DIM, nullptr, 0, 0, 0.f, 0, 0, 0);
    ln_ra_k<<<EXP * NTOK, 128>>>(p_x4, p_op4, n1w, n1b, p_x14, p_x1r4);
    // 7. ff1 relu (rounded)
    gemmCP<64, 128, false, false, 3><<<dim3(16, 32, EXP), 256, SMEMB(64, 128, false, false)>>>(
        p_x1r4, p_w1, p_tmp4, DIM, DIM, DIM, FFD,
        LLND, 0, (long long)FFD * DIM, 0, (long long)NTOK * FFD, 0, 1,
        1.f, b1, FFD, nullptr, 0, 0, 0.f, GFLAG_RELU | GFLAG_TFOUT, 0, 0);
    // 8. ff2
    gemmCP<64, 128, false, false, 3><<<dim3(4, 32, EXP), 256, SMEMB(64, 128, false, false)>>>(
        p_tmp4, p_w2, p_sa4, FFD, FFD, FFD, DIM,
        (long long)NTOK * FFD, 0, (long long)DIM * FFD, 0, LLND, 0, 1,
        1.f, b2, DIM, nullptr, 0, 0, 0.f, 0, 0, 0);
    ln_ra_k<<<EXP * NTOK, 128>>>(p_x14, p_sa4, n2w, n2b, p_out, p_xor4);
    transpose_k<0><<<dim3(DIM / 32, NTOK / 32, EXP), dim3(32, 8)>>>(
        p_xor4, p_xorT, NTOK, DIM, DIM, LLND, LLND);
    // 9. memory logits [e][l][2048,4096]  (NT=256)
    gemmCP<64, 256, false, false, 2><<<dim3(16, 32, EXP * NL), 256, SMEMB(64, 256, false, false)>>>(
        p_xor4, p_mem, p_big, DIM, DIM, DIM, MEMSZ,
        LLND, 0, 0, (long long)MEMSZ * DIM, (long long)NL * NTOK * MEMSZ, (long long)NTOK * MEMSZ, NL,
        inv_sqrt_d, nullptr, 0, nullptr, 0, 0, 10.f, 0, 0, 0);
    softmax_k<<<EXP * NL * NTOK, 256, MEMSZ * 4>>>(p_big, MEMSZ);
    // 10. retr (natural via memT, NT=256)
    gemmCP<64, 256, false, false, 2><<<dim3(2, 32, EXP * NL), 256, SMEMB(64, 256, false, false)>>>(
        p_big, p_memT, p_retr4, MEMSZ, MEMSZ, MEMSZ, DIM,
        (long long)NL * NTOK * MEMSZ, (long long)NTOK * MEMSZ, 0, (long long)MEMSZ * DIM,
        (long long)NL * NTOK * DIM, (long long)NTOK * DIM, NL,
        1.f, nullptr, 0, nullptr, 0, 0, 0.f, 0, 0, 0);
    // 11. upd4[e][l] = clip(am^T @ xout, 1)  (ATR + natural B, NT=256)
    gemmCP<64, 256, true, false, 2><<<dim3(2, 64, EXP * NL), 256, SMEMB(64, 256, true, false)>>>(
        p_big, p_xorT, p_upd4, NTOK, MEMSZ, NTOK, DIM,
        (long long)NL * NTOK * MEMSZ, (long long)NTOK * MEMSZ, LLND, 0,
        (long long)LMD_ELEMS, (long long)MEMSZ * DIM, NL,
        1.f, nullptr, 0, nullptr, 0, 0, 1.f, 0, 0, 0);
    permute_k<<<(EXP * NL * ND_ELEMS / 4 + 255) / 256, 256>>>((const float4*)p_retr4, (float4*)p_retrp4);
    // 12. outs += retrp @ aggw^T + aggb
    gemmCP<64, 128, false, false, 3><<<dim3(4, 32, EXP), 256, SMEMB(64, 128, false, false)>>>(
        p_retrp4, p_aggw, p_out, NL * DIM, NL * DIM, NL * DIM, DIM,
        (long long)NTOK * NL * DIM, 0, 0, 0, LLND, 0, 1,
        1.f, aggb, 0, p_out, LLND, DIM, 0.f, 0, 0, 0);

    dim3 ggrid(EXP, 16);
    gate_dot_k<<<ggrid, 256>>>(p_out, gg, p_glog);
    gate_softmax_k<<<1, 32>>>(p_glog, out_gw);
    fuse_k<<<(ND_ELEMS / 4 + 255) / 256, 256>>>((const float4*)p_out, out_gw, (float4*)out_fused);
    memupd_k<<<(LMD_ELEMS / 4 + 255) / 256, 256>>>((const float4*)memories, (const float4*)p_upd4, (float4*)out_mem);

    (void)in_sizes; (void)n_in; (void)out_size;
}

// round 13
// speedup vs baseline: 1.5361x; 1.5361x over previous
#include <cuda_runtime.h>
#include <math.h>
#include <stdint.h>

#define EXP 4
#define NTOK 2048
#define DIM 512
#define NH 8
#define DHEAD 64
#define FFD 2048
#define NL 4
#define MEMSZ 4096

#define ND_ELEMS (NTOK * DIM)
#define LMD_ELEMS (NL * MEMSZ * DIM)

#define GFLAG_RELU 1
#define GFLAG_ACCUM 2
#define GFLAG_TFOUT 4
#define GFLAG_KREMAP 8

// ---------------- scratch ----------------
__device__ float g_xln[EXP * NTOK * DIM];
__device__ float g_xlnT[EXP * NTOK * DIM];
__device__ float g_x4[EXP * NTOK * DIM];
__device__ float g_qkv4[(size_t)EXP * NTOK * 3 * DIM];
__device__ float g_big[(size_t)EXP * NH * NTOK * NTOK];
__device__ float g_sa4[EXP * NTOK * DIM];
__device__ float g_op4[EXP * NTOK * DIM];
__device__ float g_tmp4[(size_t)EXP * NTOK * FFD];
__device__ float g_x14[EXP * NTOK * DIM];
__device__ float g_x1r4[EXP * NTOK * DIM];
__device__ float g_xor4[EXP * NTOK * DIM];
__device__ float g_xorT[EXP * NTOK * DIM];
__device__ float g_out[EXP * NTOK * DIM];
__device__ float g_retr4[(size_t)EXP * NL * NTOK * DIM];
__device__ float g_retrp4[(size_t)EXP * NTOK * NL * DIM];
__device__ float g_upd4[(size_t)EXP * NL * MEMSZ * DIM];
__device__ float g_glog[EXP];
__device__ float g_vT[(size_t)EXP * NTOK * DIM];
__device__ float g_memT[LMD_ELEMS];
__device__ float g_ipw_r[EXP * 3 * DIM * DIM];
__device__ float g_opw_r[EXP * DIM * DIM];
__device__ float g_w1_r[EXP * FFD * DIM];
__device__ float g_w2_r[EXP * DIM * FFD];
__device__ float g_aggw_r[DIM * NL * DIM];
__device__ float g_mem_r[LMD_ELEMS];

// ---------------- helpers ----------------
__device__ __forceinline__ uint32_t tf(float x) {
    uint32_t u; asm("cvt.rna.tf32.f32 %0, %1;" : "=r"(u) : "f"(x)); return u;
}
__device__ __forceinline__ float tff(float x) { return __uint_as_float(tf(x)); }
__device__ __forceinline__ float4 tff4(float4 v) {
    return make_float4(tff(v.x), tff(v.y), tff(v.z), tff(v.w));
}
__device__ __forceinline__ void mma8(float* c, const uint32_t* a, const uint32_t* b) {
    asm volatile(
        "mma.sync.aligned.m16n8k8.row.col.f32.tf32.tf32.f32 "
        "{%0,%1,%2,%3}, {%4,%5,%6,%7}, {%8,%9}, {%0,%1,%2,%3};"
        : "+f"(c[0]), "+f"(c[1]), "+f"(c[2]), "+f"(c[3])
        : "r"(a[0]), "r"(a[1]), "r"(a[2]), "r"(a[3]), "r"(b[0]), "r"(b[1]));
}
__device__ __forceinline__ void cpa16(uint32_t s, const float* g) {
    asm volatile("cp.async.cg.shared.global [%0], [%1], 16;" :: "r"(s), "l"(g));
}
__device__ __forceinline__ void ldsm4(uint32_t* r, uint32_t a) {
    asm volatile("ldmatrix.sync.aligned.m8n8.x4.shared.b16 {%0,%1,%2,%3}, [%4];"
        : "=r"(r[0]), "=r"(r[1]), "=r"(r[2]), "=r"(r[3]) : "r"(a));
}

__global__ void tfround_k(const float4* __restrict__ s, float4* __restrict__ d, long long n4) {
    long long i = (long long)blockIdx.x * 256 + threadIdx.x;
    if (i < n4) d[i] = tff4(s[i]);
}

template <int ROUND>
__global__ void transpose_k(const float* __restrict__ in, float* __restrict__ out,
                            int rows, int cols, int ldin,
                            long long inB, long long outB) {
    __shared__ float tile[32][33];
    int z = blockIdx.z;
    in += inB * z; out += outB * z;
    int c0 = blockIdx.x * 32, r0 = blockIdx.y * 32;
    int x = threadIdx.x, y = threadIdx.y;
#pragma unroll
    for (int j = 0; j < 32; j += 8)
        tile[y + j][x] = in[(long long)(r0 + y + j) * ldin + c0 + x];
    __syncthreads();
#pragma unroll
    for (int j = 0; j < 32; j += 8) {
        float v = tile[x][y + j];
        out[(long long)(c0 + y + j) * rows + r0 + x] = ROUND ? tff(v) : v;
    }
}

// ---------------- cp.async tf32 mma GEMM, expert-batched z ----------------
template <int MT, int NT, bool ATR, bool BTR, int OCC>
__global__ void __launch_bounds__(256, OCC) gemmCP(
    const float* __restrict__ A, const float* __restrict__ B, float* __restrict__ C,
    int K, int lda, int ldb, int ldc,
    long long aB, long long aBi, long long bB, long long bBi,
    long long cB, long long cBi, int zInner,
    float alpha, const float* __restrict__ bias, long long biasB,
    const float* __restrict__ resid, long long residB, int residLd,
    float clipVal, int flags, int rs, int rl)
{
    constexpr int KC = 16;
    constexpr int AST = 20;
    constexpr int MST = MT + 8;
    constexpr int NST = NT + 8;
    constexpr int ASZ = ATR ? KC * MST : MT * AST;
    constexpr int BSZ = BTR ? KC * NST : NT * AST;
    constexpr int STG = ASZ + BSZ;
    constexpr int MI = MT / 32;
    constexpr int NB = NT / 32;

    extern __shared__ float sm[];
    uint32_t smb = (uint32_t)__cvta_generic_to_shared(sm);

    const int t = threadIdx.x, l = t & 31, w = t >> 5;
    const int bz = blockIdx.z;
    const int zo = bz / zInner, zi = bz - zo * zInner;
    A += aB * zo + aBi * zi;
    B += bB * zo + bBi * zi;
    C += cB * zo + cBi * zi;
    if (bias) bias += biasB * zo;
    if (resid) resid += residB * zo;
    if (rs < 0) rs = zo * rl;
    const int m0 = blockIdx.y * MT, n0 = blockIdx.x * NT;
    const int wm0 = (w >> 2) * (MT / 2), wn0 = (w & 3) * (NT / 4);

    const uint32_t aBase = (uint32_t)(((wm0 + ((l >> 3 & 1) << 3) + (l & 7)) * AST + ((l >> 4) << 2)) * 4);
    const uint32_t bBase4 = (uint32_t)(((wn0 + ((l >> 4) << 3) + (l & 7)) * AST + ((l >> 3 & 1) << 2)) * 4);
    const int atrOff = (l & 3) * MST + wm0 + (l >> 2);
    const int btrOff = (l & 3) * NST + wn0 + (l >> 2);

    float acc[MI][NB][4];
#pragma unroll
    for (int a = 0; a < MI; a++)
#pragma unroll
        for (int b = 0; b < NB; b++)
#pragma unroll
            for (int c = 0; c < 4; c++) acc[a][b][c] = 0.f;

    const int nK = K / KC;
    const bool kRemap = (flags & GFLAG_KREMAP) != 0;

    auto issue = [&](int s, int k0) {
        uint32_t ab = smb + (uint32_t)(s * STG * 4);
        uint32_t bb = ab + ASZ * 4;
        if (!ATR) {
            constexpr int ACH = MT * 4;
#pragma unroll
            for (int c0 = 0; c0 < ACH; c0 += 256) {
                int c = c0 + t;
                int row = c >> 2, kq = c & 3;
                cpa16(ab + (uint32_t)(row * AST + kq * 4) * 4,
                      &A[(long long)(m0 + row) * lda + k0 + kq * 4]);
            }
        } else {
            constexpr int AQ = MT / 4;
            constexpr int ASH = (MT == 128) ? 5 : 4;
            constexpr int ACH = KC * AQ;
#pragma unroll
            for (int c0 = 0; c0 < ACH; c0 += 256) {
                int c = c0 + t;
                int kr = c >> ASH, mq = c & (AQ - 1);
                cpa16(ab + (uint32_t)(kr * MST + mq * 4) * 4,
                      &A[(long long)(k0 + kr) * lda + m0 + mq * 4]);
            }
        }
        if (!BTR) {
            constexpr int BCH = NT * 4;
#pragma unroll
            for (int c0 = 0; c0 < BCH; c0 += 256) {
                int c = c0 + t;
                int row = c >> 2, kq = c & 3;
                int n = n0 + row;
                int g = k0 + kq * 4;
                if (rl) {
                    if (kRemap) { if (g >= rs) g += rl; }
                    else { if (n >= rs) n += rl; }
                }
                cpa16(bb + (uint32_t)(row * AST + kq * 4) * 4,
                      &B[(long long)n * ldb + g]);
            }
        } else {
            constexpr int NQ = NT / 4;
            constexpr int SH = (NT == 128) ? 5 : 4;
            constexpr int BCH = KC * NQ;
#pragma unroll
            for (int c0 = 0; c0 < BCH; c0 += 256) {
                int c = c0 + t;
                int kr = c >> SH, nq = c & (NQ - 1);
                int g = k0 + kr;
                if (rl && g >= rs) g += rl;
                cpa16(bb + (uint32_t)(kr * NST + nq * 4) * 4,
                      &B[(long long)g * ldb + n0 + nq * 4]);
            }
        }
        asm volatile("cp.async.commit_group;" ::: "memory");
    };

    issue(0, 0);
    issue(1, KC);
    issue(2, 2 * KC);

    for (int i = 0; i < nK; i++) {
        asm volatile("cp.async.wait_group 2;" ::: "memory");
        __syncthreads();
        if (i + 3 < nK) issue((i + 3) & 3, (i + 3) * KC);

        const float* Ab = sm + (i & 3) * STG;
        const float* Bb = Ab + ASZ;
        uint32_t abu = smb + (uint32_t)((i & 3) * STG * 4);
        uint32_t bbu = abu + (uint32_t)(ASZ * 4);
#pragma unroll
        for (int kk = 0; kk < 2; kk++) {
            const int kc = kk * 8;
            uint32_t af[MI][4], bf[NB][2];
#pragma unroll
            for (int mi = 0; mi < MI; mi++) {
                if (!ATR) {
                    ldsm4(af[mi], abu + aBase + (uint32_t)((mi * 16 * AST + kc) * 4));
                } else {
                    const uint32_t* ap = (const uint32_t*)&Ab[kc * MST + atrOff + mi * 16];
                    af[mi][0] = ap[0];
                    af[mi][1] = ap[8];
                    af[mi][2] = ap[4 * MST];
                    af[mi][3] = ap[4 * MST + 8];
                }
            }
            if (!BTR) {
#pragma unroll
                for (int nj = 0; nj < NB / 2; nj++) {
                    uint32_t r4[4];
                    ldsm4(r4, bbu + bBase4 + (uint32_t)((nj * 16 * AST + kc) * 4));
                    bf[2 * nj][0] = r4[0]; bf[2 * nj][1] = r4[1];
                    bf[2 * nj + 1][0] = r4[2]; bf[2 * nj + 1][1] = r4[3];
                }
            } else {
#pragma unroll
                for (int ni = 0; ni < NB; ni++) {
                    const uint32_t* bp = (const uint32_t*)&Bb[kc * NST + btrOff + ni * 8];
                    bf[ni][0] = bp[0];
                    bf[ni][1] = bp[4 * NST];
                }
            }
#pragma unroll
            for (int mi = 0; mi < MI; mi++)
#pragma unroll
                for (int ni = 0; ni < NB; ni++) mma8(acc[mi][ni], af[mi], bf[ni]);
        }
    }

    // epilogue
#pragma unroll
    for (int mi = 0; mi < MI; mi++) {
        int row0 = m0 + wm0 + mi * 16 + (l >> 2);
#pragma unroll
        for (int ni = 0; ni < NB; ni++) {
            int col = n0 + wn0 + ni * 8 + (l & 3) * 2;
#pragma unroll
            for (int h = 0; h < 2; h++) {
                int row = row0 + h * 8;
                float vx = alpha * acc[mi][ni][h * 2];
                float vy = alpha * acc[mi][ni][h * 2 + 1];
                if (bias) { vx += bias[col]; vy += bias[col + 1]; }
                if (flags & GFLAG_RELU) { vx = fmaxf(vx, 0.f); vy = fmaxf(vy, 0.f); }
                if (clipVal > 0.f) {
                    vx = fminf(fmaxf(vx, -clipVal), clipVal);
                    vy = fminf(fmaxf(vy, -clipVal), clipVal);
                }
                if (resid) {
                    float2 rv = *(const float2*)&resid[(long long)row * residLd + col];
                    vx += rv.x; vy += rv.y;
                }
                float2* cp = (float2*)&C[(long long)row * ldc + col];
                if (flags & GFLAG_ACCUM) {
                    float2 o = *cp;
                    vx += o.x; vy += o.y;
                }
                if (flags & GFLAG_TFOUT) { vx = tff(vx); vy = tff(vy); }
                *cp = make_float2(vx, vy);
            }
        }
    }
}

// ---------------- reductions ----------------
__device__ __forceinline__ float warpReduceSum(float v) {
#pragma unroll
    for (int o = 16; o; o >>= 1) v += __shfl_xor_sync(0xffffffffu, v, o);
    return v;
}
__device__ __forceinline__ float warpReduceMax(float v) {
#pragma unroll
    for (int o = 16; o; o >>= 1) v = fmaxf(v, __shfl_xor_sync(0xffffffffu, v, o));
    return v;
}

// ---------------- vectorized smem-cached row softmax ----------------
__global__ void softmax_k(float* __restrict__ p, int cols) {
    extern __shared__ float4 sb4[];
    float4* row = (float4*)(p + (long long)blockIdx.x * cols);
    int nc4 = cols >> 2;
    __shared__ float sh[8];
    __shared__ float sb;
    int tid = threadIdx.x, lane = tid & 31, wid = tid >> 5;
    float m = -1e30f;
    for (int i = tid; i < nc4; i += 256) {
        float4 v = row[i]; sb4[i] = v;
        m = fmaxf(m, fmaxf(fmaxf(v.x, v.y), fmaxf(v.z, v.w)));
    }
    m = warpReduceMax(m);
    if (lane == 0) sh[wid] = m;
    __syncthreads();
    if (tid == 0) { float x = sh[0]; for (int q = 1; q < 8; q++) x = fmaxf(x, sh[q]); sb = x; }
    __syncthreads();
    m = sb;
    float s = 0.f;
    for (int i = tid; i < nc4; i += 256) {
        float4 v = sb4[i];
        v.x = expf(v.x - m); v.y = expf(v.y - m); v.z = expf(v.z - m); v.w = expf(v.w - m);
        sb4[i] = v;
        s += v.x + v.y + v.z + v.w;
    }
    s = warpReduceSum(s);
    if (lane == 0) sh[wid] = s;
    __syncthreads();
    if (tid == 0) { float x = 0; for (int q = 0; q < 8; q++) x += sh[q]; sb = 1.f / x; }
    __syncthreads();
    float inv = sb;
    for (int i = tid; i < nc4; i += 256) {
        float4 v = sb4[i];
        row[i] = make_float4(tff(v.x * inv), tff(v.y * inv), tff(v.z * inv), tff(v.w * inv));
    }
}

// ---------------- LayerNorm (vectorized, rounded output) ----------------
__global__ void ln_k(const float* __restrict__ src, float* __restrict__ dst) {
    long long row = blockIdx.x;
    const float4* x = (const float4*)(src + row * DIM);
    float4* y = (float4*)(dst + row * DIM);
    int tid = threadIdx.x, lane = tid & 31, wid = tid >> 5;
    float4 v = x[tid];
    float s = v.x + v.y + v.z + v.w;
    float s2 = v.x * v.x + v.y * v.y + v.z * v.z + v.w * v.w;
    s = warpReduceSum(s); s2 = warpReduceSum(s2);
    __shared__ float sh[2][4]; __shared__ float mv[2];
    if (lane == 0) { sh[0][wid] = s; sh[1][wid] = s2; }
    __syncthreads();
    if (tid == 0) {
        float a = sh[0][0] + sh[0][1] + sh[0][2] + sh[0][3];
        float b = sh[1][0] + sh[1][1] + sh[1][2] + sh[1][3];
        float mean = a / DIM;
        mv[0] = mean; mv[1] = rsqrtf(b / DIM - mean * mean + 1e-5f);
    }
    __syncthreads();
    float mean = mv[0], rstd = mv[1];
    y[tid] = make_float4(tff((v.x - mean) * rstd), tff((v.y - mean) * rstd),
                         tff((v.z - mean) * rstd), tff((v.w - mean) * rstd));
}

__global__ void ln_ra_k(const float* __restrict__ a, const float* __restrict__ b,
                        const float* __restrict__ wAll, const float* __restrict__ bAll,
                        float* __restrict__ dst, float* __restrict__ dstr) {
    long long row = blockIdx.x;
    int e = (int)(row >> 11);
    const float4* xa = (const float4*)(a + row * DIM);
    const float4* xb = (const float4*)(b + row * DIM);
    const float4* w = (const float4*)(wAll + (long long)e * DIM);
    const float4* bb = (const float4*)(bAll + (long long)e * DIM);
    float4* y = (float4*)(dst + row * DIM);
    float4* yr = (float4*)(dstr + row * DIM);
    int tid = threadIdx.x, lane = tid & 31, wid = tid >> 5;
    float4 va = xa[tid], vb = xb[tid];
    float4 v = make_float4(va.x + vb.x, va.y + vb.y, va.z + vb.z, va.w + vb.w);
    float s = v.x + v.y + v.z + v.w;
    float s2 = v.x * v.x + v.y * v.y + v.z * v.z + v.w * v.w;
    s = warpReduceSum(s); s2 = warpReduceSum(s2);
    __shared__ float sh[2][4]; __shared__ float mv[2];
    if (lane == 0) { sh[0][wid] = s; sh[1][wid] = s2; }
    __syncthreads();
    if (tid == 0) {
        float p = sh[0][0] + sh[0][1] + sh[0][2] + sh[0][3];
        float q = sh[1][0] + sh[1][1] + sh[1][2] + sh[1][3];
        float mean = p / DIM;
        mv[0] = mean; mv[1] = rsqrtf(q / DIM - mean * mean + 1e-5f);
    }
    __syncthreads();
    float mean = mv[0], rstd = mv[1];
    float4 ww = w[tid], bbv = bb[tid];
    float4 o = make_float4((v.x - mean) * rstd * ww.x + bbv.x,
                           (v.y - mean) * rstd * ww.y + bbv.y,
                           (v.z - mean) * rstd * ww.z + bbv.z,
                           (v.w - mean) * rstd * ww.w + bbv.w);
    y[tid] = o;
    yr[tid] = tff4(o);
}

__global__ void permute_k(const float4* __restrict__ retr, float4* __restrict__ rp) {
    long long i = (long long)blockIdx.x * 256 + threadIdx.x;
    constexpr int D4 = DIM / 4;
    if (i < (long long)EXP * NL * NTOK * D4) {
        int d4 = (int)(i & (D4 - 1));
        long long r = i >> 7;
        int n = (int)(r & (NTOK - 1));
        long long r2 = r >> 11;
        int lay = (int)(r2 & (NL - 1));
        long long e = r2 >> 2;
        rp[((e * NTOK + n) * NL + lay) * D4 + d4] = tff4(retr[i]);
    }
}

__global__ void zero_k(float* __restrict__ p, long long n) {
    long long i = (long long)blockIdx.x * 256 + threadIdx.x;
    if (i < n) p[i] = 0.f;
}

__global__ void gate_dot_k(const float* __restrict__ outs, const float* __restrict__ gg,
                           float* __restrict__ glog) {
    int e = blockIdx.x;
    constexpr int D4 = DIM / 4;
    long long chunk4 = (long long)(ND_ELEMS / 4) / gridDim.y;
    const float4* base = (const float4*)(outs) + (long long)e * (ND_ELEMS / 4) + (long long)blockIdx.y * chunk4;
    const float4* gg4 = (const float4*)gg;
    float acc = 0.f;
    for (long long i = threadIdx.x; i < chunk4; i += blockDim.x) {
        float4 v = base[i];
        float4 g = gg4[i & (D4 - 1)];
        acc += v.x * g.x + v.y * g.y + v.z * g.z + v.w * g.w;
    }
    acc = warpReduceSum(acc);
    __shared__ float sh[8];
    int lane = threadIdx.x & 31, wid = threadIdx.x >> 5;
    if (lane == 0) sh[wid] = acc;
    __syncthreads();
    if (threadIdx.x == 0) {
        float x = 0;
        for (int q = 0; q < 8; q++) x += sh[q];
        atomicAdd(&glog[e], x);
    }
}

__global__ void gate_softmax_k(const float* __restrict__ glog, float* __restrict__ gw) {
    if (threadIdx.x == 0) {
        float l[EXP], m = -1e30f;
        for (int e = 0; e < EXP; e++) {
            l[e] = fminf(fmaxf(glog[e] / (float)NTOK, -10.f), 10.f);
            m = fmaxf(m, l[e]);
        }
        float s = 0.f;
        for (int e = 0; e < EXP; e++) { l[e] = expf(l[e] - m); s += l[e]; }
        for (int e = 0; e < EXP; e++) gw[e] = l[e] / s;
    }
}

__global__ void fuse_k(const float4* __restrict__ outs, const float* __restrict__ gw,
                       float4* __restrict__ fused) {
    long long i = (long long)blockIdx.x * 256 + threadIdx.x;
    constexpr long long N4 = ND_ELEMS / 4;
    if (i < N4) {
        float4 r = make_float4(0.f, 0.f, 0.f, 0.f);
#pragma unroll
        for (int e = 0; e < EXP; e++) {
            float4 v = outs[(long long)e * N4 + i];
            float gwe = gw[e];
            r.x += gwe * v.x; r.y += gwe * v.y; r.z += gwe * v.z; r.w += gwe * v.w;
        }
        fused[i] = r;
    }
}

__global__ void memupd_k(const float4* __restrict__ mem, const float4* __restrict__ upd4,
                         float4* __restrict__ o) {
    long long i = (long long)blockIdx.x * 256 + threadIdx.x;
    constexpr long long N4 = (long long)LMD_ELEMS / 4;
    if (i < N4) {
        float4 u = upd4[i];
#pragma unroll
        for (int e = 1; e < EXP; e++) {
            float4 v = upd4[(long long)e * N4 + i];
            u.x += v.x; u.y += v.y; u.z += v.z; u.w += v.w;
        }
        float4 mm = mem[i];
        float4 r;
        r.x = 0.9f * mm.x + fminf(fmaxf(0.1f * u.x, -0.1f), 0.1f);
        r.y = 0.9f * mm.y + fminf(fmaxf(0.1f * u.y, -0.1f), 0.1f);
        r.z = 0.9f * mm.z + fminf(fmaxf(0.1f * u.z, -0.1f), 0.1f);
        r.w = 0.9f * mm.w + fminf(fmaxf(0.1f * u.w, -0.1f), 0.1f);
        o[i] = r;
    }
}

// ---------------- host ----------------
static constexpr int stgFl(int MT, int NT, bool ATR, bool BTR) {
    return (ATR ? 16 * (MT + 8) : MT * 20) + (BTR ? 16 * (NT + 8) : NT * 20);
}
#define SMEMB(MT, NT, ATR, BTR) (4 * stgFl(MT, NT, ATR, BTR) * 4)

static void tfround(const float* s, float* d, long long n) {
    long long n4 = n / 4;
    tfround_k<<<(int)((n4 + 255) / 256), 256>>>((const float4*)s, (float4*)d, n4);
}

extern "C" void kernel_launch(void* const* d_in, const int* in_sizes, int n_in,
                              void* d_out, int out_size) {
    const float* tokens   = (const float*)d_in[0];
    const float* memories = (const float*)d_in[1];
    const float* ipw      = (const float*)d_in[2];
    const float* ipb      = (const float*)d_in[3];
    const float* opw      = (const float*)d_in[4];
    const float* opb      = (const float*)d_in[5];
    const float* w1       = (const float*)d_in[6];
    const float* b1       = (const float*)d_in[7];
    const float* w2       = (const float*)d_in[8];
    const float* b2       = (const float*)d_in[9];
    const float* n1w      = (const float*)d_in[10];
    const float* n1b      = (const float*)d_in[11];
    const float* n2w      = (const float*)d_in[12];
    const float* n2b      = (const float*)d_in[13];
    const float* aggw     = (const float*)d_in[14];
    const float* aggb     = (const float*)d_in[15];
    const float* gg       = (const float*)d_in[16];

    float* out = (float*)d_out;
    float* out_fused = out;
    float* out_gw = out + ND_ELEMS;
    float* out_mem = out + ND_ELEMS + EXP;

    static float *p_xln = nullptr, *p_xlnT = nullptr, *p_x4 = nullptr, *p_qkv4 = nullptr,
                 *p_big = nullptr, *p_sa4 = nullptr, *p_op4 = nullptr, *p_tmp4 = nullptr,
                 *p_x14 = nullptr, *p_x1r4 = nullptr, *p_xor4 = nullptr, *p_xorT = nullptr,
                 *p_out = nullptr, *p_retr4 = nullptr, *p_retrp4 = nullptr, *p_upd4 = nullptr,
                 *p_glog = nullptr, *p_vT = nullptr, *p_memT = nullptr,
                 *p_ipw = nullptr, *p_opw = nullptr, *p_w1 = nullptr, *p_w2 = nullptr,
                 *p_aggw = nullptr, *p_mem = nullptr;
    if (!p_xln) {
        cudaGetSymbolAddress((void**)&p_xln, g_xln);
        cudaGetSymbolAddress((void**)&p_xlnT, g_xlnT);
        cudaGetSymbolAddress((void**)&p_x4, g_x4);
        cudaGetSymbolAddress((void**)&p_qkv4, g_qkv4);
        cudaGetSymbolAddress((void**)&p_big, g_big);
        cudaGetSymbolAddress((void**)&p_sa4, g_sa4);
        cudaGetSymbolAddress((void**)&p_op4, g_op4);
        cudaGetSymbolAddress((void**)&p_tmp4, g_tmp4);
        cudaGetSymbolAddress((void**)&p_x14, g_x14);
        cudaGetSymbolAddress((void**)&p_x1r4, g_x1r4);
        cudaGetSymbolAddress((void**)&p_xor4, g_xor4);
        cudaGetSymbolAddress((void**)&p_xorT, g_xorT);
        cudaGetSymbolAddress((void**)&p_out, g_out);
        cudaGetSymbolAddress((void**)&p_retr4, g_retr4);
        cudaGetSymbolAddress((void**)&p_retrp4, g_retrp4);
        cudaGetSymbolAddress((void**)&p_upd4, g_upd4);
        cudaGetSymbolAddress((void**)&p_glog, g_glog);
        cudaGetSymbolAddress((void**)&p_vT, g_vT);
        cudaGetSymbolAddress((void**)&p_memT, g_memT);
        cudaGetSymbolAddress((void**)&p_ipw, g_ipw_r);
        cudaGetSymbolAddress((void**)&p_opw, g_opw_r);
        cudaGetSymbolAddress((void**)&p_w1, g_w1_r);
        cudaGetSymbolAddress((void**)&p_w2, g_w2_r);
        cudaGetSymbolAddress((void**)&p_aggw, g_aggw_r);
        cudaGetSymbolAddress((void**)&p_mem, g_mem_r);
        cudaFuncSetAttribute(gemmCP<64, 128, false, false, 3>, cudaFuncAttributeMaxDynamicSharedMemorySize, SMEMB(64, 128, false, false));
        cudaFuncSetAttribute(gemmCP<64, 64, false, false, 3>,  cudaFuncAttributeMaxDynamicSharedMemorySize, SMEMB(64, 64, false, false));
        cudaFuncSetAttribute(gemmCP<64, 128, true, false, 3>,  cudaFuncAttributeMaxDynamicSharedMemorySize, SMEMB(64, 128, true, false));
    }

    const float inv_sqrt_d = 1.0f / sqrtf((float)DIM);
    const float inv_sqrt_dh = 1.0f / sqrtf((float)DHEAD);

    const long long LLND = ND_ELEMS;
    const long long BIGE = (long long)NH * NTOK * NTOK;
    const long long QKVE = (long long)NTOK * 3 * DIM;

    // launches 1-5 (so the 6th = cross-logits GEMM gets ncu'd)
    zero_k<<<1, 256>>>(p_glog, EXP);
    ln_k<<<EXP * NTOK, 128>>>(tokens, p_xln);
    transpose_k<0><<<dim3(DIM / 32, EXP * NTOK / 32, 1), dim3(32, 8)>>>(
        p_xln, p_xlnT, EXP * NTOK, DIM, DIM, 0, 0);
    tfround(ipw, p_ipw, (long long)EXP * 3 * DIM * DIM);
    tfround(opw, p_opw, (long long)EXP * DIM * DIM);

    // 1. cross logits [e][2048, 6144]   <- 6th launch (ncu target)
    gemmCP<64, 128, false, false, 3><<<dim3(48, 32, EXP), 256, SMEMB(64, 128, false, false)>>>(
        p_xln, p_xln, p_big, DIM, DIM, DIM, 3 * NTOK,
        LLND, 0, 0, 0, (long long)NTOK * 3 * NTOK, 0, 1,
        inv_sqrt_d, nullptr, 0, nullptr, 0, 0, 10.f, 0, -1, NTOK);

    // remaining weight prep (independent of cross/softmax chain)
    tfround(w1, p_w1, (long long)EXP * FFD * DIM);
    tfround(w2, p_w2, (long long)EXP * DIM * FFD);
    tfround(aggw, p_aggw, (long long)DIM * NL * DIM);
    tfround(memories, p_mem, (long long)LMD_ELEMS);
    transpose_k<1><<<dim3(DIM / 32, MEMSZ / 32, NL), dim3(32, 8)>>>(
        memories, p_memT, MEMSZ, DIM, DIM, (long long)MEMSZ * DIM, (long long)MEMSZ * DIM);

    softmax_k<<<EXP * NTOK, 256, 3 * NTOK * 4>>>(p_big, 3 * NTOK);
    // 2. x = probs @ ctx + xln (natural via xlnT, k-remap, rounded)
    gemmCP<64, 128, false, false, 3><<<dim3(4, 32, EXP), 256, SMEMB(64, 128, false, false)>>>(
        p_big, p_xlnT, p_x4, 3 * NTOK, 3 * NTOK, EXP * NTOK, DIM,
        (long long)NTOK * 3 * NTOK, 0, 0, 0, LLND, 0, 1,
        1.f, nullptr, 0, p_xln, LLND, DIM, 0.f, GFLAG_TFOUT | GFLAG_KREMAP, -1, NTOK);
    // 3. qkv (rounded)
    gemmCP<64, 128, false, false, 3><<<dim3(12, 32, EXP), 256, SMEMB(64, 128, false, false)>>>(
        p_x4, p_ipw, p_qkv4, DIM, DIM, DIM, 3 * DIM,
        LLND, 0, (long long)3 * DIM * DIM, 0, QKVE, 0, 1,
        1.f, ipb, 3 * DIM, nullptr, 0, 0, 0.f, GFLAG_TFOUT, 0, 0);
    transpose_k<0><<<dim3(DIM / 32, NTOK / 32, EXP), dim3(32, 8)>>>(
        p_qkv4 + 2 * DIM, p_vT, NTOK, DIM, 3 * DIM, QKVE, LLND);
    // 4. scores [e][h][2048,2048]
    gemmCP<64, 128, false, false, 3><<<dim3(16, 32, EXP * NH), 256, SMEMB(64, 128, false, false)>>>(
        p_qkv4, p_qkv4 + DIM, p_big, DHEAD, 3 * DIM, 3 * DIM, NTOK,
        QKVE, DHEAD, QKVE, DHEAD, BIGE, (long long)NTOK * NTOK, NH,
        inv_sqrt_dh, nullptr, 0, nullptr, 0, 0, 0.f, 0, 0, 0);
    softmax_k<<<EXP * NH * NTOK, 256, NTOK * 4>>>(p_big, NTOK);
    // 5. sa = probs @ v (natural via vT, rounded)
    gemmCP<64, 64, false, false, 3><<<dim3(1, 32, EXP * NH), 256, SMEMB(64, 64, false, false)>>>(
        p_big, p_vT, p_sa4, NTOK, NTOK, NTOK, DIM,
        BIGE, (long long)NTOK * NTOK, LLND, (long long)DHEAD * NTOK, LLND, DHEAD, NH,
        1.f, nullptr, 0, nullptr, 0, 0, 0.f, GFLAG_TFOUT, 0, 0);
    // 6. out_proj
    gemmCP<64, 128, false, false, 3><<<dim3(4, 32, EXP), 256, SMEMB(64, 128, false, false)>>>(
        p_sa4, p_opw, p_op4, DIM, DIM, DIM, DIM,
        LLND, 0, (long long)DIM * DIM, 0, LLND, 0, 1,
        1.f, opb, DIM, nullptr, 0, 0, 0.f, 0, 0, 0);
    ln_ra_k<<<EXP * NTOK, 128>>>(p_x4, p_op4, n1w, n1b, p_x14, p_x1r4);
    // 7. ff1 relu (rounded)
    gemmCP<64, 128, false, false, 3><<<dim3(16, 32, EXP), 256, SMEMB(64, 128, false, false)>>>(
        p_x1r4, p_w1, p_tmp4, DIM, DIM, DIM, FFD,
        LLND, 0, (long long)FFD * DIM, 0, (long long)NTOK * FFD, 0, 1,
        1.f, b1, FFD, nullptr, 0, 0, 0.f, GFLAG_RELU | GFLAG_TFOUT, 0, 0);
    // 8. ff2
    gemmCP<64, 128, false, false, 3><<<dim3(4, 32, EXP), 256, SMEMB(64, 128, false, false)>>>(
        p_tmp4, p_w2, p_sa4, FFD, FFD, FFD, DIM,
        (long long)NTOK * FFD, 0, (long long)DIM * FFD, 0, LLND, 0, 1,
        1.f, b2, DIM, nullptr, 0, 0, 0.f, 0, 0, 0);
    ln_ra_k<<<EXP * NTOK, 128>>>(p_x14, p_sa4, n2w, n2b, p_out, p_xor4);
    transpose_k<0><<<dim3(DIM / 32, NTOK / 32, EXP), dim3(32, 8)>>>(
        p_xor4, p_xorT, NTOK, DIM, DIM, LLND, LLND);
    // 9. memory logits [e][l][2048,4096]
    gemmCP<64, 128, false, false, 3><<<dim3(32, 32, EXP * NL), 256, SMEMB(64, 128, false, false)>>>(
        p_xor4, p_mem, p_big, DIM, DIM, DIM, MEMSZ,
        LLND, 0, 0, (long long)MEMSZ * DIM, (long long)NL * NTOK * MEMSZ, (long long)NTOK * MEMSZ, NL,
        inv_sqrt_d, nullptr, 0, nullptr, 0, 0, 10.f, 0, 0, 0);
    softmax_k<<<EXP * NL * NTOK, 256, MEMSZ * 4>>>(p_big, MEMSZ);
    // 10. retr (natural via memT)
    gemmCP<64, 128, false, false, 3><<<dim3(4, 32, EXP * NL), 256, SMEMB(64, 128, false, false)>>>(
        p_big, p_memT, p_retr4, MEMSZ, MEMSZ, MEMSZ, DIM,
        (long long)NL * NTOK * MEMSZ, (long long)NTOK * MEMSZ, 0, (long long)MEMSZ * DIM,
        (long long)NL * NTOK * DIM, (long long)NTOK * DIM, NL,
        1.f, nullptr, 0, nullptr, 0, 0, 0.f, 0, 0, 0);
    // 11. upd4[e][l] = clip(am^T @ xout, 1)  (ATR + natural B)
    gemmCP<64, 128, true, false, 3><<<dim3(4, 64, EXP * NL), 256, SMEMB(64, 128, true, false)>>>(
        p_big, p_xorT, p_upd4, NTOK, MEMSZ, NTOK, DIM,
        (long long)NL * NTOK * MEMSZ, (long long)NTOK * MEMSZ, LLND, 0,
        (long long)LMD_ELEMS, (long long)MEMSZ * DIM, NL,
        1.f, nullptr, 0, nullptr, 0, 0, 1.f, 0, 0, 0);
    permute_k<<<(EXP * NL * ND_ELEMS / 4 + 255) / 256, 256>>>((const float4*)p_retr4, (float4*)p_retrp4);
    // 12. outs += retrp @ aggw^T + aggb
    gemmCP<64, 128, false, false, 3><<<dim3(4, 32, EXP), 256, SMEMB(64, 128, false, false)>>>(
        p_retrp4, p_aggw, p_out, NL * DIM, NL * DIM, NL * DIM, DIM,
        (long long)NTOK * NL * DIM, 0, 0, 0, LLND, 0, 1,
        1.f, aggb, 0, p_out, LLND, DIM, 0.f, 0, 0, 0);

    dim3 ggrid(EXP, 16);
    gate_dot_k<<<ggrid, 256>>>(p_out, gg, p_glog);
    gate_softmax_k<<<1, 32>>>(p_glog, out_gw);
    fuse_k<<<(ND_ELEMS / 4 + 255) / 256, 256>>>((const float4*)p_out, out_gw, (float4*)out_fused);
    memupd_k<<<(LMD_ELEMS / 4 + 255) / 256, 256>>>((const float4*)memories, (const float4*)p_upd4, (float4*)out_mem);

    (void)in_sizes; (void)n_in; (void)out_size;
}

// round 14
// speedup vs baseline: 2.7629x; 1.7987x over previous
#include <cuda_runtime.h>
#include <cuda_fp16.h>
#include <math.h>
#include <stdint.h>

#define EXP 4
#define NTOK 2048
#define DIM 512
#define NH 8
#define DHEAD 64
#define FFD 2048
#define NL 4
#define MEMSZ 4096

#define ND_ELEMS (NTOK * DIM)
#define LMD_ELEMS (NL * MEMSZ * DIM)

#define GFLAG_RELU 1
#define GFLAG_KREMAP 2

// ---------------- scratch ----------------
__device__ __half gh_xln[EXP * NTOK * DIM];
__device__ __half gh_xlnT[EXP * NTOK * DIM];
__device__ __half gh_x4[EXP * NTOK * DIM];
__device__ __half gh_qkv[(size_t)EXP * NTOK * 3 * DIM];
__device__ __half gh_big[(size_t)EXP * NH * NTOK * NTOK];
__device__ __half gh_sa[EXP * NTOK * DIM];
__device__ __half gh_x1r[EXP * NTOK * DIM];
__device__ __half gh_xor[EXP * NTOK * DIM];
__device__ __half gh_xorT[EXP * NTOK * DIM];
__device__ __half gh_vT[(size_t)EXP * NTOK * DIM];
__device__ __half gh_tmp[(size_t)EXP * NTOK * FFD];
__device__ __half gh_retrp[(size_t)EXP * NTOK * NL * DIM];
__device__ __half gh_ipw[EXP * 3 * DIM * DIM];
__device__ __half gh_opw[EXP * DIM * DIM];
__device__ __half gh_w1[EXP * FFD * DIM];
__device__ __half gh_w2[EXP * DIM * FFD];
__device__ __half gh_aggw[DIM * NL * DIM];
__device__ __half gh_mem[LMD_ELEMS];
__device__ __half gh_memT[LMD_ELEMS];
__device__ float g_op4[EXP * NTOK * DIM];        // out_proj / ff2 out
__device__ float g_x14[EXP * NTOK * DIM];
__device__ float g_out[EXP * NTOK * DIM];
__device__ float g_retr4[(size_t)EXP * NL * NTOK * DIM];
__device__ float g_upd4[(size_t)EXP * NL * MEMSZ * DIM];
__device__ float g_glog[EXP];

// ---------------- helpers ----------------
__device__ __forceinline__ void mma16(float* c, const uint32_t* a, const uint32_t* b) {
    asm volatile(
        "mma.sync.aligned.m16n8k16.row.col.f32.f16.f16.f32 "
        "{%0,%1,%2,%3}, {%4,%5,%6,%7}, {%8,%9}, {%0,%1,%2,%3};"
        : "+f"(c[0]), "+f"(c[1]), "+f"(c[2]), "+f"(c[3])
        : "r"(a[0]), "r"(a[1]), "r"(a[2]), "r"(a[3]), "r"(b[0]), "r"(b[1]));
}
__device__ __forceinline__ void cpa16(uint32_t s, const void* g) {
    asm volatile("cp.async.cg.shared.global [%0], [%1], 16;" :: "r"(s), "l"(g));
}
__device__ __forceinline__ void ldsm4(uint32_t* r, uint32_t a) {
    asm volatile("ldmatrix.sync.aligned.m8n8.x4.shared.b16 {%0,%1,%2,%3}, [%4];"
        : "=r"(r[0]), "=r"(r[1]), "=r"(r[2]), "=r"(r[3]) : "r"(a));
}
__device__ __forceinline__ void ldsm4t(uint32_t* r, uint32_t a) {
    asm volatile("ldmatrix.sync.aligned.m8n8.x4.trans.shared.b16 {%0,%1,%2,%3}, [%4];"
        : "=r"(r[0]), "=r"(r[1]), "=r"(r[2]), "=r"(r[3]) : "r"(a));
}

// float4 -> 4 halves
__global__ void tohalf_k(const float4* __restrict__ s, __half2* __restrict__ d, long long n4) {
    long long i = (long long)blockIdx.x * 256 + threadIdx.x;
    if (i < n4) {
        float4 v = s[i];
        d[2 * i] = __floats2half2_rn(v.x, v.y);
        d[2 * i + 1] = __floats2half2_rn(v.z, v.w);
    }
}

// half -> half 32x32 tiled transpose
__global__ void transpose_h(const __half* __restrict__ in, __half* __restrict__ out,
                            int rows, int cols, int ldin, long long inB, long long outB) {
    __shared__ __half tile[32][38];
    int z = blockIdx.z;
    in += inB * z; out += outB * z;
    int c0 = blockIdx.x * 32, r0 = blockIdx.y * 32;
    int x = threadIdx.x, y = threadIdx.y;
#pragma unroll
    for (int j = 0; j < 32; j += 8)
        tile[y + j][x] = in[(long long)(r0 + y + j) * ldin + c0 + x];
    __syncthreads();
#pragma unroll
    for (int j = 0; j < 32; j += 8)
        out[(long long)(c0 + y + j) * rows + r0 + x] = tile[x][y + j];
}

// float -> half transpose (rounded)
__global__ void transpose_fh(const float* __restrict__ in, __half* __restrict__ out,
                             int rows, int cols, int ldin, long long inB, long long outB) {
    __shared__ float tile[32][33];
    int z = blockIdx.z;
    in += inB * z; out += outB * z;
    int c0 = blockIdx.x * 32, r0 = blockIdx.y * 32;
    int x = threadIdx.x, y = threadIdx.y;
#pragma unroll
    for (int j = 0; j < 32; j += 8)
        tile[y + j][x] = in[(long long)(r0 + y + j) * ldin + c0 + x];
    __syncthreads();
#pragma unroll
    for (int j = 0; j < 32; j += 8)
        out[(long long)(c0 + y + j) * rows + r0 + x] = __float2half_rn(tile[x][y + j]);
}

// ---------------- fp16 m16n8k16 cp.async GEMM ----------------
// C[M,Nc] = alpha*op(A)*op(B) (+bias)(relu)(clip)(+resid); z = zo*zInner+zi batching.
// ATR: A stored [K,M] (M contig). OUTH: C is __half. RESH: resid is __half.
// remap (rl>0): KREMAP remaps B k-cols; else B n-rows. rs<0 -> rs=zo*rl.
template <int MT, int NT, bool ATR, int OUTH, int RESH>
__global__ void __launch_bounds__(256, 3) gemmH(
    const __half* __restrict__ A, const __half* __restrict__ B, void* __restrict__ Cv,
    int K, int lda, int ldb, int ldc,
    long long aB, long long aBi, long long bB, long long bBi,
    long long cB, long long cBi, int zInner,
    float alpha, const float* __restrict__ bias, long long biasB,
    const void* __restrict__ residv, long long residB, int residLd,
    float clipVal, int flags, int rs, int rl)
{
    constexpr int KC = 32;
    constexpr int ASTh = 40;          // halves per A/B row (KC + 8 pad)
    constexpr int MSTh = MT + 8;      // ATR row stride
    constexpr int ASZ = ATR ? KC * MSTh : MT * ASTh;
    constexpr int BSZ = NT * ASTh;
    constexpr int STG = ASZ + BSZ;    // halves per stage
    constexpr int MI = MT / 32;
    constexpr int NB = NT / 32;

    extern __shared__ __half smh[];
    uint32_t smb = (uint32_t)__cvta_generic_to_shared(smh);

    const int t = threadIdx.x, l = t & 31, w = t >> 5;
    const int bz = blockIdx.z;
    const int zo = bz / zInner, zi = bz - zo * zInner;
    A += aB * zo + aBi * zi;
    B += bB * zo + bBi * zi;
    float* Cf = nullptr; __half* Ch = nullptr;
    if (OUTH) Ch = (__half*)Cv + cB * zo + cBi * zi;
    else      Cf = (float*)Cv + cB * zo + cBi * zi;
    if (bias) bias += biasB * zo;
    const float* residF = nullptr; const __half* residH = nullptr;
    if (residv) {
        if (RESH) residH = (const __half*)residv + residB * zo;
        else      residF = (const float*)residv + residB * zo;
    }
    if (rs < 0) rs = zo * rl;
    const int m0 = blockIdx.y * MT, n0 = blockIdx.x * NT;
    const int wm0 = (w >> 2) * (MT / 2), wn0 = (w & 3) * (NT / 4);
    const bool kRemap = (flags & GFLAG_KREMAP) != 0;

    // fragment base byte offsets
    const uint32_t aBase = (uint32_t)(((wm0 + ((l >> 3 & 1) << 3) + (l & 7)) * ASTh + ((l >> 4) << 3)) * 2);
    const uint32_t aBaseT = (uint32_t)(((((l >> 4) << 3) + (l & 7)) * MSTh + wm0 + ((l >> 3 & 1) << 3)) * 2);
    const uint32_t bBase = (uint32_t)(((wn0 + ((l >> 4) << 3) + (l & 7)) * ASTh + ((l >> 3 & 1) << 3)) * 2);

    float acc[MI][NB][4];
#pragma unroll
    for (int a = 0; a < MI; a++)
#pragma unroll
        for (int b = 0; b < NB; b++)
#pragma unroll
            for (int c = 0; c < 4; c++) acc[a][b][c] = 0.f;

    const int nK = K / KC;
    const int kmax = K - KC;

    auto issue = [&](int s, int k0) {
        uint32_t ab = smb + (uint32_t)(s * STG * 2);
        uint32_t bb = ab + (uint32_t)(ASZ * 2);
        if (!ATR) {
            constexpr int ACH = MT * 4;       // 4 x 16B chunks (8 halves) per row
#pragma unroll
            for (int c0 = 0; c0 < ACH; c0 += 256) {
                int c = c0 + t;
                int row = c >> 2, kq = (c & 3) * 8;
                cpa16(ab + (uint32_t)((row * ASTh + kq) * 2),
                      &A[(long long)(m0 + row) * lda + k0 + kq]);
            }
        } else {
            constexpr int ACH = KC * (MT / 8);  // 32 rows x 8 chunks
#pragma unroll
            for (int c0 = 0; c0 < ACH; c0 += 256) {
                int c = c0 + t;
                int kr = c >> 3, mq = (c & 7) * 8;
                cpa16(ab + (uint32_t)((kr * MSTh + mq) * 2),
                      &A[(long long)(k0 + kr) * lda + m0 + mq]);
            }
        }
        {
            constexpr int BCH = NT * 4;
#pragma unroll
            for (int c0 = 0; c0 < BCH; c0 += 256) {
                int c = c0 + t;
                int row = c >> 2, kq = (c & 3) * 8;
                int n = n0 + row;
                int g = k0 + kq;
                if (rl) {
                    if (kRemap) { if (g >= rs) g += rl; }
                    else { if (n >= rs) n += rl; }
                }
                cpa16(bb + (uint32_t)((row * ASTh + kq) * 2),
                      &B[(long long)n * ldb + g]);
            }
        }
        asm volatile("cp.async.commit_group;" ::: "memory");
    };

    issue(0, 0);
    if (KC <= kmax) issue(1, KC); else asm volatile("cp.async.commit_group;" ::: "memory");
    if (2 * KC <= kmax) issue(2, 2 * KC); else asm volatile("cp.async.commit_group;" ::: "memory");

    for (int i = 0; i < nK; i++) {
        asm volatile("cp.async.wait_group 2;" ::: "memory");
        __syncthreads();
        int pk = (i + 3) * KC;
        if (pk <= kmax) issue((i + 3) & 3, pk);
        else asm volatile("cp.async.commit_group;" ::: "memory");

        uint32_t abu = smb + (uint32_t)((i & 3) * STG * 2);
        uint32_t bbu = abu + (uint32_t)(ASZ * 2);
#pragma unroll
        for (int kk = 0; kk < 2; kk++) {
            uint32_t af[MI][4], bf[NB][2];
#pragma unroll
            for (int mi = 0; mi < MI; mi++) {
                if (!ATR)
                    ldsm4(af[mi], abu + aBase + (uint32_t)((mi * 16 * ASTh + kk * 16) * 2));
                else
                    ldsm4t(af[mi], abu + aBaseT + (uint32_t)((kk * 16 * MSTh + mi * 16) * 2));
            }
#pragma unroll
            for (int nj = 0; nj < NB / 2; nj++) {
                uint32_t r4[4];
                ldsm4(r4, bbu + bBase + (uint32_t)((nj * 16 * ASTh + kk * 16) * 2));
                bf[2 * nj][0] = r4[0]; bf[2 * nj][1] = r4[1];
                bf[2 * nj + 1][0] = r4[2]; bf[2 * nj + 1][1] = r4[3];
            }
#pragma unroll
            for (int mi = 0; mi < MI; mi++)
#pragma unroll
                for (int ni = 0; ni < NB; ni++) mma16(acc[mi][ni], af[mi], bf[ni]);
        }
    }

    // epilogue
#pragma unroll
    for (int mi = 0; mi < MI; mi++) {
        int row0 = m0 + wm0 + mi * 16 + (l >> 2);
#pragma unroll
        for (int ni = 0; ni < NB; ni++) {
            int col = n0 + wn0 + ni * 8 + (l & 3) * 2;
#pragma unroll
            for (int h = 0; h < 2; h++) {
                int row = row0 + h * 8;
                float vx = alpha * acc[mi][ni][h * 2];
                float vy = alpha * acc[mi][ni][h * 2 + 1];
                if (bias) { vx += bias[col]; vy += bias[col + 1]; }
                if (flags & GFLAG_RELU) { vx = fmaxf(vx, 0.f); vy = fmaxf(vy, 0.f); }
                if (clipVal > 0.f) {
                    vx = fminf(fmaxf(vx, -clipVal), clipVal);
                    vy = fminf(fmaxf(vy, -clipVal), clipVal);
                }
                if (residv) {
                    if (RESH) {
                        float2 rv = __half22float2(*(const __half2*)&residH[(long long)row * residLd + col]);
                        vx += rv.x; vy += rv.y;
                    } else {
                        float2 rv = *(const float2*)&residF[(long long)row * residLd + col];
                        vx += rv.x; vy += rv.y;
                    }
                }
                if (OUTH) {
                    *(__half2*)&Ch[(long long)row * ldc + col] = __floats2half2_rn(vx, vy);
                } else {
                    *(float2*)&Cf[(long long)row * ldc + col] = make_float2(vx, vy);
                }
            }
        }
    }
}

// ---------------- reductions ----------------
__device__ __forceinline__ float warpReduceSum(float v) {
#pragma unroll
    for (int o = 16; o; o >>= 1) v += __shfl_xor_sync(0xffffffffu, v, o);
    return v;
}
__device__ __forceinline__ float warpReduceMax(float v) {
#pragma unroll
    for (int o = 16; o; o >>= 1) v = fmaxf(v, __shfl_xor_sync(0xffffffffu, v, o));
    return v;
}

// ---------------- fp16 row softmax (fp32 math in smem) ----------------
__global__ void softmax_h(__half* __restrict__ p, int cols) {
    extern __shared__ float sbuf[];
    __half2* row = (__half2*)(p + (long long)blockIdx.x * cols);
    int nc2 = cols >> 1;
    __shared__ float sh[8];
    __shared__ float sb;
    int tid = threadIdx.x, lane = tid & 31, wid = tid >> 5;
    float m = -1e30f;
    for (int i = tid; i < nc2; i += 256) {
        float2 v = __half22float2(row[i]);
        sbuf[2 * i] = v.x; sbuf[2 * i + 1] = v.y;
        m = fmaxf(m, fmaxf(v.x, v.y));
    }
    m = warpReduceMax(m);
    if (lane == 0) sh[wid] = m;
    __syncthreads();
    if (tid == 0) { float x = sh[0]; for (int q = 1; q < 8; q++) x = fmaxf(x, sh[q]); sb = x; }
    __syncthreads();
    m = sb;
    float s = 0.f;
    for (int i = tid; i < nc2; i += 256) {
        float a = expf(sbuf[2 * i] - m), b = expf(sbuf[2 * i + 1] - m);
        sbuf[2 * i] = a; sbuf[2 * i + 1] = b;
        s += a + b;
    }
    s = warpReduceSum(s);
    if (lane == 0) sh[wid] = s;
    __syncthreads();
    if (tid == 0) { float x = 0; for (int q = 0; q < 8; q++) x += sh[q]; sb = 1.f / x; }
    __syncthreads();
    float inv = sb;
    for (int i = tid; i < nc2; i += 256)
        row[i] = __floats2half2_rn(sbuf[2 * i] * inv, sbuf[2 * i + 1] * inv);
}

// ---------------- LayerNorm: fp32 tokens -> fp16 ----------------
__global__ void ln_k(const float* __restrict__ src, __half* __restrict__ dst) {
    long long row = blockIdx.x;
    const float4* x = (const float4*)(src + row * DIM);
    __half2* y = (__half2*)(dst + row * DIM);
    int tid = threadIdx.x, lane = tid & 31, wid = tid >> 5;
    float4 v = x[tid];
    float s = v.x + v.y + v.z + v.w;
    float s2 = v.x * v.x + v.y * v.y + v.z * v.z + v.w * v.w;
    s = warpReduceSum(s); s2 = warpReduceSum(s2);
    __shared__ float sh[2][4]; __shared__ float mv[2];
    if (lane == 0) { sh[0][wid] = s; sh[1][wid] = s2; }
    __syncthreads();
    if (tid == 0) {
        float a = sh[0][0] + sh[0][1] + sh[0][2] + sh[0][3];
        float b = sh[1][0] + sh[1][1] + sh[1][2] + sh[1][3];
        float mean = a / DIM;
        mv[0] = mean; mv[1] = rsqrtf(b / DIM - mean * mean + 1e-5f);
    }
    __syncthreads();
    float mean = mv[0], rstd = mv[1];
    y[2 * tid] = __floats2half2_rn((v.x - mean) * rstd, (v.y - mean) * rstd);
    y[2 * tid + 1] = __floats2half2_rn((v.z - mean) * rstd, (v.w - mean) * rstd);
}

// LN(a+b)*w+bb; a fp16 (AH=1) or fp32; b fp32; y fp32; yr fp16. e = row>>11.
template <int AH>
__global__ void ln_ra_k(const void* __restrict__ av, const float* __restrict__ b,
                        const float* __restrict__ wAll, const float* __restrict__ bAll,
                        float* __restrict__ dst, __half* __restrict__ dstr) {
    long long row = blockIdx.x;
    int e = (int)(row >> 11);
    const float4* xb = (const float4*)(b + row * DIM);
    const float4* w = (const float4*)(wAll + (long long)e * DIM);
    const float4* bb = (const float4*)(bAll + (long long)e * DIM);
    float4* y = (float4*)(dst + row * DIM);
    __half2* yr = (__half2*)(dstr + row * DIM);
    int tid = threadIdx.x, lane = tid & 31, wid = tid >> 5;
    float4 va;
    if (AH) {
        const __half2* xa = (const __half2*)((const __half*)av + row * DIM);
        float2 p0 = __half22float2(xa[2 * tid]), p1 = __half22float2(xa[2 * tid + 1]);
        va = make_float4(p0.x, p0.y, p1.x, p1.y);
    } else {
        va = ((const float4*)((const float*)av + row * DIM))[tid];
    }
    float4 vb = xb[tid];
    float4 v = make_float4(va.x + vb.x, va.y + vb.y, va.z + vb.z, va.w + vb.w);
    float s = v.x + v.y + v.z + v.w;
    float s2 = v.x * v.x + v.y * v.y + v.z * v.z + v.w * v.w;
    s = warpReduceSum(s); s2 = warpReduceSum(s2);
    __shared__ float sh[2][4]; __shared__ float mv[2];
    if (lane == 0) { sh[0][wid] = s; sh[1][wid] = s2; }
    __syncthreads();
    if (tid == 0) {
        float p = sh[0][0] + sh[0][1] + sh[0][2] + sh[0][3];
        float q = sh[1][0] + sh[1][1] + sh[1][2] + sh[1][3];
        float mean = p / DIM;
        mv[0] = mean; mv[1] = rsqrtf(q / DIM - mean * mean + 1e-5f);
    }
    __syncthreads();
    float mean = mv[0], rstd = mv[1];
    float4 ww = w[tid], bbv = bb[tid];
    float4 o = make_float4((v.x - mean) * rstd * ww.x + bbv.x,
                           (v.y - mean) * rstd * ww.y + bbv.y,
                           (v.z - mean) * rstd * ww.z + bbv.z,
                           (v.w - mean) * rstd * ww.w + bbv.w);
    y[tid] = o;
    yr[2 * tid] = __floats2half2_rn(o.x, o.y);
    yr[2 * tid + 1] = __floats2half2_rn(o.z, o.w);
}

// retr4[e][l][n][d] fp32 -> retrp[e][n][l*D+d] fp16
__global__ void permute_k(const float4* __restrict__ retr, __half2* __restrict__ rp) {
    long long i = (long long)blockIdx.x * 256 + threadIdx.x;
    constexpr int D4 = DIM / 4;
    if (i < (long long)EXP * NL * NTOK * D4) {
        int d4 = (int)(i & (D4 - 1));
        long long r = i >> 7;
        int n = (int)(r & (NTOK - 1));
        long long r2 = r >> 11;
        int lay = (int)(r2 & (NL - 1));
        long long e = r2 >> 2;
        float4 v = retr[i];
        long long o = (((e * NTOK + n) * NL + lay) * D4 + d4) * 2;
        rp[o] = __floats2half2_rn(v.x, v.y);
        rp[o + 1] = __floats2half2_rn(v.z, v.w);
    }
}

__global__ void zero_k(float* __restrict__ p, long long n) {
    long long i = (long long)blockIdx.x * 256 + threadIdx.x;
    if (i < n) p[i] = 0.f;
}

__global__ void gate_dot_k(const float* __restrict__ outs, const float* __restrict__ gg,
                           float* __restrict__ glog) {
    int e = blockIdx.x;
    constexpr int D4 = DIM / 4;
    long long chunk4 = (long long)(ND_ELEMS / 4) / gridDim.y;
    const float4* base = (const float4*)(outs) + (long long)e * (ND_ELEMS / 4) + (long long)blockIdx.y * chunk4;
    const float4* gg4 = (const float4*)gg;
    float acc = 0.f;
    for (long long i = threadIdx.x; i < chunk4; i += blockDim.x) {
        float4 v = base[i];
        float4 g = gg4[i & (D4 - 1)];
        acc += v.x * g.x + v.y * g.y + v.z * g.z + v.w * g.w;
    }
    acc = warpReduceSum(acc);
    __shared__ float sh[8];
    int lane = threadIdx.x & 31, wid = threadIdx.x >> 5;
    if (lane == 0) sh[wid] = acc;
    __syncthreads();
    if (threadIdx.x == 0) {
        float x = 0;
        for (int q = 0; q < 8; q++) x += sh[q];
        atomicAdd(&glog[e], x);
    }
}

__global__ void gate_softmax_k(const float* __restrict__ glog, float* __restrict__ gw) {
    if (threadIdx.x == 0) {
        float l[EXP], m = -1e30f;
        for (int e = 0; e < EXP; e++) {
            l[e] = fminf(fmaxf(glog[e] / (float)NTOK, -10.f), 10.f);
            m = fmaxf(m, l[e]);
        }
        float s = 0.f;
        for (int e = 0; e < EXP; e++) { l[e] = expf(l[e] - m); s += l[e]; }
        for (int e = 0; e < EXP; e++) gw[e] = l[e] / s;
    }
}

__global__ void fuse_k(const float4* __restrict__ outs, const float* __restrict__ gw,
                       float4* __restrict__ fused) {
    long long i = (long long)blockIdx.x * 256 + threadIdx.x;
    constexpr long long N4 = ND_ELEMS / 4;
    if (i < N4) {
        float4 r = make_float4(0.f, 0.f, 0.f, 0.f);
#pragma unroll
        for (int e = 0; e < EXP; e++) {
            float4 v = outs[(long long)e * N4 + i];
            float gwe = gw[e];
            r.x += gwe * v.x; r.y += gwe * v.y; r.z += gwe * v.z; r.w += gwe * v.w;
        }
        fused[i] = r;
    }
}

__global__ void memupd_k(const float4* __restrict__ mem, const float4* __restrict__ upd4,
                         float4* __restrict__ o) {
    long long i = (long long)blockIdx.x * 256 + threadIdx.x;
    constexpr long long N4 = (long long)LMD_ELEMS / 4;
    if (i < N4) {
        float4 u = upd4[i];
#pragma unroll
        for (int e = 1; e < EXP; e++) {
            float4 v = upd4[(long long)e * N4 + i];
            u.x += v.x; u.y += v.y; u.z += v.z; u.w += v.w;
        }
        float4 mm = mem[i];
        float4 r;
        r.x = 0.9f * mm.x + fminf(fmaxf(0.1f * u.x, -0.1f), 0.1f);
        r.y = 0.9f * mm.y + fminf(fmaxf(0.1f * u.y, -0.1f), 0.1f);
        r.z = 0.9f * mm.z + fminf(fmaxf(0.1f * u.z, -0.1f), 0.1f);
        r.w = 0.9f * mm.w + fminf(fmaxf(0.1f * u.w, -0.1f), 0.1f);
        o[i] = r;
    }
}

// ---------------- host ----------------
static constexpr int stgH(int MT, int NT, bool ATR) {
    return (ATR ? 32 * (MT + 8) : MT * 40) + NT * 40;    // halves
}
#define SMEMH(MT, NT, ATR) (4 * stgH(MT, NT, ATR) * 2)

static void tohalf(const float* s, __half* d, long long n) {
    long long n4 = n / 4;
    tohalf_k<<<(int)((n4 + 255) / 256), 256>>>((const float4*)s, (__half2*)d, n4);
}

extern "C" void kernel_launch(void* const* d_in, const int* in_sizes, int n_in,
                              void* d_out, int out_size) {
    const float* tokens   = (const float*)d_in[0];
    const float* memories = (const float*)d_in[1];
    const float* ipw      = (const float*)d_in[2];
    const float* ipb      = (const float*)d_in[3];
    const float* opw      = (const float*)d_in[4];
    const float* opb      = (const float*)d_in[5];
    const float* w1       = (const float*)d_in[6];
    const float* b1       = (const float*)d_in[7];
    const float* w2       = (const float*)d_in[8];
    const float* b2       = (const float*)d_in[9];
    const float* n1w      = (const float*)d_in[10];
    const float* n1b      = (const float*)d_in[11];
    const float* n2w      = (const float*)d_in[12];
    const float* n2b      = (const float*)d_in[13];
    const float* aggw     = (const float*)d_in[14];
    const float* aggb     = (const float*)d_in[15];
    const float* gg       = (const float*)d_in[16];

    float* out = (float*)d_out;
    float* out_fused = out;
    float* out_gw = out + ND_ELEMS;
    float* out_mem = out + ND_ELEMS + EXP;

    static __half *h_xln = nullptr, *h_xlnT = nullptr, *h_x4 = nullptr, *h_qkv = nullptr,
                  *h_big = nullptr, *h_sa = nullptr, *h_x1r = nullptr, *h_xor = nullptr,
                  *h_xorT = nullptr, *h_vT = nullptr, *h_tmp = nullptr, *h_retrp = nullptr,
                  *h_ipw = nullptr, *h_opw = nullptr, *h_w1 = nullptr, *h_w2 = nullptr,
                  *h_aggw = nullptr, *h_mem = nullptr, *h_memT = nullptr;
    static float *p_op4 = nullptr, *p_x14 = nullptr, *p_out = nullptr,
                 *p_retr4 = nullptr, *p_upd4 = nullptr, *p_glog = nullptr;
    if (!h_xln) {
        cudaGetSymbolAddress((void**)&h_xln, gh_xln);
        cudaGetSymbolAddress((void**)&h_xlnT, gh_xlnT);
        cudaGetSymbolAddress((void**)&h_x4, gh_x4);
        cudaGetSymbolAddress((void**)&h_qkv, gh_qkv);
        cudaGetSymbolAddress((void**)&h_big, gh_big);
        cudaGetSymbolAddress((void**)&h_sa, gh_sa);
        cudaGetSymbolAddress((void**)&h_x1r, gh_x1r);
        cudaGetSymbolAddress((void**)&h_xor, gh_xor);
        cudaGetSymbolAddress((void**)&h_xorT, gh_xorT);
        cudaGetSymbolAddress((void**)&h_vT, gh_vT);
        cudaGetSymbolAddress((void**)&h_tmp, gh_tmp);
        cudaGetSymbolAddress((void**)&h_retrp, gh_retrp);
        cudaGetSymbolAddress((void**)&h_ipw, gh_ipw);
        cudaGetSymbolAddress((void**)&h_opw, gh_opw);
        cudaGetSymbolAddress((void**)&h_w1, gh_w1);
        cudaGetSymbolAddress((void**)&h_w2, gh_w2);
        cudaGetSymbolAddress((void**)&h_aggw, gh_aggw);
        cudaGetSymbolAddress((void**)&h_mem, gh_mem);
        cudaGetSymbolAddress((void**)&h_memT, gh_memT);
        cudaGetSymbolAddress((void**)&p_op4, g_op4);
        cudaGetSymbolAddress((void**)&p_x14, g_x14);
        cudaGetSymbolAddress((void**)&p_out, g_out);
        cudaGetSymbolAddress((void**)&p_retr4, g_retr4);
        cudaGetSymbolAddress((void**)&p_upd4, g_upd4);
        cudaGetSymbolAddress((void**)&p_glog, g_glog);
        cudaFuncSetAttribute(gemmH<64, 128, false, 1, 0>, cudaFuncAttributeMaxDynamicSharedMemorySize, SMEMH(64, 128, false));
        cudaFuncSetAttribute(gemmH<64, 128, false, 1, 1>, cudaFuncAttributeMaxDynamicSharedMemorySize, SMEMH(64, 128, false));
        cudaFuncSetAttribute(gemmH<64, 128, false, 0, 0>, cudaFuncAttributeMaxDynamicSharedMemorySize, SMEMH(64, 128, false));
        cudaFuncSetAttribute(gemmH<64, 64, false, 1, 0>,  cudaFuncAttributeMaxDynamicSharedMemorySize, SMEMH(64, 64, false));
        cudaFuncSetAttribute(gemmH<64, 128, true, 0, 0>,  cudaFuncAttributeMaxDynamicSharedMemorySize, SMEMH(64, 128, true));
    }

    const float inv_sqrt_d = 1.0f / sqrtf((float)DIM);
    const float inv_sqrt_dh = 1.0f / sqrtf((float)DHEAD);

    const long long LLND = ND_ELEMS;
    const long long BIGE = (long long)NH * NTOK * NTOK;
    const long long QKVE = (long long)NTOK * 3 * DIM;

    // launches 1-5 (6th = cross GEMM for ncu)
    zero_k<<<1, 256>>>(p_glog, EXP);
    ln_k<<<EXP * NTOK, 128>>>(tokens, h_xln);
    transpose_h<<<dim3(DIM / 32, EXP * NTOK / 32, 1), dim3(32, 8)>>>(
        h_xln, h_xlnT, EXP * NTOK, DIM, DIM, 0, 0);
    tohalf(ipw, h_ipw, (long long)EXP * 3 * DIM * DIM);
    tohalf(opw, h_opw, (long long)EXP * DIM * DIM);

    // 1. cross logits [e][2048, 6144] fp16 out  <- 6th launch
    gemmH<64, 128, false, 1, 0><<<dim3(48, 32, EXP), 256, SMEMH(64, 128, false)>>>(
        h_xln, h_xln, h_big, DIM, DIM, DIM, 3 * NTOK,
        LLND, 0, 0, 0, (long long)NTOK * 3 * NTOK, 0, 1,
        inv_sqrt_d, nullptr, 0, nullptr, 0, 0, 10.f, 0, -1, NTOK);

    tohalf(w1, h_w1, (long long)EXP * FFD * DIM);
    tohalf(w2, h_w2, (long long)EXP * DIM * FFD);
    tohalf(aggw, h_aggw, (long long)DIM * NL * DIM);
    tohalf(memories, h_mem, (long long)LMD_ELEMS);
    transpose_fh<<<dim3(DIM / 32, MEMSZ / 32, NL), dim3(32, 8)>>>(
        memories, h_memT, MEMSZ, DIM, DIM, (long long)MEMSZ * DIM, (long long)MEMSZ * DIM);

    softmax_h<<<EXP * NTOK, 256, 3 * NTOK * 4>>>(h_big, 3 * NTOK);
    // 2. x = probs @ ctx + xln  (B = xlnT, k-remap; fp16 out, fp16 resid)
    gemmH<64, 128, false, 1, 1><<<dim3(4, 32, EXP), 256, SMEMH(64, 128, false)>>>(
        h_big, h_xlnT, h_x4, 3 * NTOK, 3 * NTOK, EXP * NTOK, DIM,
        (long long)NTOK * 3 * NTOK, 0, 0, 0, LLND, 0, 1,
        1.f, nullptr, 0, h_xln, LLND, DIM, 0.f, GFLAG_KREMAP, -1, NTOK);
    // 3. qkv fp16
    gemmH<64, 128, false, 1, 0><<<dim3(12, 32, EXP), 256, SMEMH(64, 128, false)>>>(
        h_x4, h_ipw, h_qkv, DIM, DIM, DIM, 3 * DIM,
        LLND, 0, (long long)3 * DIM * DIM, 0, QKVE, 0, 1,
        1.f, ipb, 3 * DIM, nullptr, 0, 0, 0.f, 0, 0, 0);
    transpose_h<<<dim3(DIM / 32, NTOK / 32, EXP), dim3(32, 8)>>>(
        h_qkv + 2 * DIM, h_vT, NTOK, DIM, 3 * DIM, QKVE, LLND);
    // 4. scores [e][h][2048,2048] fp16 (K=64)
    gemmH<64, 128, false, 1, 0><<<dim3(16, 32, EXP * NH), 256, SMEMH(64, 128, false)>>>(
        h_qkv, h_qkv + DIM, h_big, DHEAD, 3 * DIM, 3 * DIM, NTOK,
        QKVE, DHEAD, QKVE, DHEAD, BIGE, (long long)NTOK * NTOK, NH,
        inv_sqrt_dh, nullptr, 0, nullptr, 0, 0, 0.f, 0, 0, 0);
    softmax_h<<<EXP * NH * NTOK, 256, NTOK * 4>>>(h_big, NTOK);
    // 5. sa = probs @ v (B = vT natural) fp16
    gemmH<64, 64, false, 1, 0><<<dim3(1, 32, EXP * NH), 256, SMEMH(64, 64, false)>>>(
        h_big, h_vT, h_sa, NTOK, NTOK, NTOK, DIM,
        BIGE, (long long)NTOK * NTOK, LLND, (long long)DHEAD * NTOK, LLND, DHEAD, NH,
        1.f, nullptr, 0, nullptr, 0, 0, 0.f, 0, 0, 0);
    // 6. out_proj fp32 out
    gemmH<64, 128, false, 0, 0><<<dim3(4, 32, EXP), 256, SMEMH(64, 128, false)>>>(
        h_sa, h_opw, p_op4, DIM, DIM, DIM, DIM,
        LLND, 0, (long long)DIM * DIM, 0, LLND, 0, 1,
        1.f, opb, DIM, nullptr, 0, 0, 0.f, 0, 0, 0);
    ln_ra_k<1><<<EXP * NTOK, 128>>>(h_x4, p_op4, n1w, n1b, p_x14, h_x1r);
    // 7. ff1 relu fp16
    gemmH<64, 128, false, 1, 0><<<dim3(16, 32, EXP), 256, SMEMH(64, 128, false)>>>(
        h_x1r, h_w1, h_tmp, DIM, DIM, DIM, FFD,
        LLND, 0, (long long)FFD * DIM, 0, (long long)NTOK * FFD, 0, 1,
        1.f, b1, FFD, nullptr, 0, 0, 0.f, GFLAG_RELU, 0, 0);
    // 8. ff2 fp32 out (reuse op4)
    gemmH<64, 128, false, 0, 0><<<dim3(4, 32, EXP), 256, SMEMH(64, 128, false)>>>(
        h_tmp, h_w2, p_op4, FFD, FFD, FFD, DIM,
        (long long)NTOK * FFD, 0, (long long)DIM * FFD, 0, LLND, 0, 1,
        1.f, b2, DIM, nullptr, 0, 0, 0.f, 0, 0, 0);
    ln_ra_k<0><<<EXP * NTOK, 128>>>(p_x14, p_op4, n2w, n2b, p_out, h_xor);
    transpose_h<<<dim3(DIM / 32, NTOK / 32, EXP), dim3(32, 8)>>>(
        h_xor, h_xorT, NTOK, DIM, DIM, LLND, LLND);
    // 9. memory logits fp16
    gemmH<64, 128, false, 1, 0><<<dim3(32, 32, EXP * NL), 256, SMEMH(64, 128, false)>>>(
        h_xor, h_mem, h_big, DIM, DIM, DIM, MEMSZ,
        LLND, 0, 0, (long long)MEMSZ * DIM, (long long)NL * NTOK * MEMSZ, (long long)NTOK * MEMSZ, NL,
        inv_sqrt_d, nullptr, 0, nullptr, 0, 0, 10.f, 0, 0, 0);
    softmax_h<<<EXP * NL * NTOK, 256, MEMSZ * 4>>>(h_big, MEMSZ);
    // 10. retr fp32 out (B = memT natural)
    gemmH<64, 128, false, 0, 0><<<dim3(4, 32, EXP * NL), 256, SMEMH(64, 128, false)>>>(
        h_big, h_memT, p_retr4, MEMSZ, MEMSZ, MEMSZ, DIM,
        (long long)NL * NTOK * MEMSZ, (long long)NTOK * MEMSZ, 0, (long long)MEMSZ * DIM,
        (long long)NL * NTOK * DIM, (long long)NTOK * DIM, NL,
        1.f, nullptr, 0, nullptr, 0, 0, 0.f, 0, 0, 0);
    // 11. upd = clip(am^T @ xout, 1) fp32 out (ATR A, B = xorT natural)
    gemmH<64, 128, true, 0, 0><<<dim3(4, 64, EXP * NL), 256, SMEMH(64, 128, true)>>>(
        h_big, h_xorT, p_upd4, NTOK, MEMSZ, NTOK, DIM,
        (long long)NL * NTOK * MEMSZ, (long long)NTOK * MEMSZ, LLND, 0,
        (long long)LMD_ELEMS, (long long)MEMSZ * DIM, NL,
        1.f, nullptr, 0, nullptr, 0, 0, 1.f, 0, 0, 0);
    permute_k<<<(EXP * NL * ND_ELEMS / 4 + 255) / 256, 256>>>((const float4*)p_retr4, (__half2*)h_retrp);
    // 12. outs += retrp @ aggw^T + aggb (fp32 out, fp32 resid)
    gemmH<64, 128, false, 0, 0><<<dim3(4, 32, EXP), 256, SMEMH(64, 128, false)>>>(
        h_retrp, h_aggw, p_out, NL * DIM, NL * DIM, NL * DIM, DIM,
        (long long)NTOK * NL * DIM, 0, 0, 0, LLND, 0, 1,
        1.f, aggb, 0, p_out, LLND, DIM, 0.f, 0, 0, 0);

    dim3 ggrid(EXP, 16);
    gate_dot_k<<<ggrid, 256>>>(p_out, gg, p_glog);
    gate_softmax_k<<<1, 32>>>(p_glog, out_gw);
    fuse_k<<<(ND_ELEMS / 4 + 255) / 256, 256>>>((const float4*)p_out, out_gw, (float4*)out_fused);
    memupd_k<<<(LMD_ELEMS / 4 + 255) / 256, 256>>>((const float4*)memories, (const float4*)p_upd4, (float4*)out_mem);

    (void)in_sizes; (void)n_in; (void)out_size;
}

// round 15
// speedup vs baseline: 3.0184x; 1.0925x over previous
#include <cuda_runtime.h>
#include <cuda_fp16.h>
#include <math.h>
#include <stdint.h>

#define EXP 4
#define NTOK 2048
#define DIM 512
#define NH 8
#define DHEAD 64
#define FFD 2048
#define NL 4
#define MEMSZ 4096

#define ND_ELEMS (NTOK * DIM)
#define LMD_ELEMS (NL * MEMSZ * DIM)

#define GFLAG_RELU 1
#define GFLAG_KREMAP 2

// ---------------- scratch ----------------
__device__ __half gh_xln[EXP * NTOK * DIM];
__device__ __half gh_xlnT[EXP * NTOK * DIM];
__device__ __half gh_x4[EXP * NTOK * DIM];
__device__ __half gh_qkv[(size_t)EXP * NTOK * 3 * DIM];
__device__ __half gh_big[(size_t)EXP * NH * NTOK * NTOK];
__device__ __half gh_sa[EXP * NTOK * DIM];
__device__ __half gh_x1r[EXP * NTOK * DIM];
__device__ __half gh_xor[EXP * NTOK * DIM];
__device__ __half gh_xorT[EXP * NTOK * DIM];
__device__ __half gh_vT[(size_t)EXP * NTOK * DIM];
__device__ __half gh_tmp[(size_t)EXP * NTOK * FFD];
__device__ __half gh_retrp[(size_t)EXP * NTOK * NL * DIM];
__device__ __half gh_ipw[EXP * 3 * DIM * DIM];
__device__ __half gh_opw[EXP * DIM * DIM];
__device__ __half gh_w1[EXP * FFD * DIM];
__device__ __half gh_w2[EXP * DIM * FFD];
__device__ __half gh_aggw[DIM * NL * DIM];
__device__ __half gh_mem[LMD_ELEMS];
__device__ __half gh_memT[LMD_ELEMS];
__device__ float g_op4[EXP * NTOK * DIM];
__device__ float g_x14[EXP * NTOK * DIM];
__device__ float g_out[EXP * NTOK * DIM];
__device__ float g_retr4[(size_t)EXP * NL * NTOK * DIM];
__device__ float g_upd4[(size_t)EXP * NL * MEMSZ * DIM];
__device__ float g_glog[EXP];

// ---------------- helpers ----------------
__device__ __forceinline__ void mma16(float* c, const uint32_t* a, const uint32_t* b) {
    asm volatile(
        "mma.sync.aligned.m16n8k16.row.col.f32.f16.f16.f32 "
        "{%0,%1,%2,%3}, {%4,%5,%6,%7}, {%8,%9}, {%0,%1,%2,%3};"
        : "+f"(c[0]), "+f"(c[1]), "+f"(c[2]), "+f"(c[3])
        : "r"(a[0]), "r"(a[1]), "r"(a[2]), "r"(a[3]), "r"(b[0]), "r"(b[1]));
}
__device__ __forceinline__ void cpa16(uint32_t s, const void* g) {
    asm volatile("cp.async.cg.shared.global [%0], [%1], 16;" :: "r"(s), "l"(g));
}
__device__ __forceinline__ void ldsm4(uint32_t* r, uint32_t a) {
    asm volatile("ldmatrix.sync.aligned.m8n8.x4.shared.b16 {%0,%1,%2,%3}, [%4];"
        : "=r"(r[0]), "=r"(r[1]), "=r"(r[2]), "=r"(r[3]) : "r"(a));
}
__device__ __forceinline__ void ldsm4t(uint32_t* r, uint32_t a) {
    asm volatile("ldmatrix.sync.aligned.m8n8.x4.trans.shared.b16 {%0,%1,%2,%3}, [%4];"
        : "=r"(r[0]), "=r"(r[1]), "=r"(r[2]), "=r"(r[3]) : "r"(a));
}

__global__ void tohalf_k(const float4* __restrict__ s, __half2* __restrict__ d, long long n4) {
    long long i = (long long)blockIdx.x * 256 + threadIdx.x;
    if (i < n4) {
        float4 v = s[i];
        d[2 * i] = __floats2half2_rn(v.x, v.y);
        d[2 * i + 1] = __floats2half2_rn(v.z, v.w);
    }
}

__global__ void transpose_h(const __half* __restrict__ in, __half* __restrict__ out,
                            int rows, int cols, int ldin, long long inB, long long outB) {
    __shared__ __half tile[32][38];
    int z = blockIdx.z;
    in += inB * z; out += outB * z;
    int c0 = blockIdx.x * 32, r0 = blockIdx.y * 32;
    int x = threadIdx.x, y = threadIdx.y;
#pragma unroll
    for (int j = 0; j < 32; j += 8)
        tile[y + j][x] = in[(long long)(r0 + y + j) * ldin + c0 + x];
    __syncthreads();
#pragma unroll
    for (int j = 0; j < 32; j += 8)
        out[(long long)(c0 + y + j) * rows + r0 + x] = tile[x][y + j];
}

__global__ void transpose_fh(const float* __restrict__ in, __half* __restrict__ out,
                             int rows, int cols, int ldin, long long inB, long long outB) {
    __shared__ float tile[32][33];
    int z = blockIdx.z;
    in += inB * z; out += outB * z;
    int c0 = blockIdx.x * 32, r0 = blockIdx.y * 32;
    int x = threadIdx.x, y = threadIdx.y;
#pragma unroll
    for (int j = 0; j < 32; j += 8)
        tile[y + j][x] = in[(long long)(r0 + y + j) * ldin + c0 + x];
    __syncthreads();
#pragma unroll
    for (int j = 0; j < 32; j += 8)
        out[(long long)(c0 + y + j) * rows + r0 + x] = __float2half_rn(tile[x][y + j]);
}

// ---------------- fp16 m16n8k16 cp.async GEMM ----------------
template <int MT, int NT, bool ATR, int OUTH, int RESH>
__global__ void __launch_bounds__(256, 3) gemmH(
    const __half* __restrict__ A, const __half* __restrict__ B, void* __restrict__ Cv,
    int K, int lda, int ldb, int ldc,
    long long aB, long long aBi, long long bB, long long bBi,
    long long cB, long long cBi, int zInner,
    float alpha, const float* __restrict__ bias, long long biasB,
    const void* __restrict__ residv, long long residB, int residLd,
    float clipVal, int flags, int rs, int rl)
{
    constexpr int KC = 32;
    constexpr int ASTh = 40;
    constexpr int MSTh = MT + 8;
    constexpr int ASZ = ATR ? KC * MSTh : MT * ASTh;
    constexpr int BSZ = NT * ASTh;
    constexpr int STG = ASZ + BSZ;
    constexpr int MI = MT / 32;
    constexpr int NB = NT / 32;

    extern __shared__ __half smh[];
    uint32_t smb = (uint32_t)__cvta_generic_to_shared(smh);

    const int t = threadIdx.x, l = t & 31, w = t >> 5;
    const int bz = blockIdx.z;
    const int zo = bz / zInner, zi = bz - zo * zInner;
    A += aB * zo + aBi * zi;
    B += bB * zo + bBi * zi;
    float* Cf = nullptr; __half* Ch = nullptr;
    if (OUTH) Ch = (__half*)Cv + cB * zo + cBi * zi;
    else      Cf = (float*)Cv + cB * zo + cBi * zi;
    if (bias) bias += biasB * zo;
    const float* residF = nullptr; const __half* residH = nullptr;
    if (residv) {
        if (RESH) residH = (const __half*)residv + residB * zo;
        else      residF = (const float*)residv + residB * zo;
    }
    if (rs < 0) rs = zo * rl;
    const int m0 = blockIdx.y * MT, n0 = blockIdx.x * NT;
    const int wm0 = (w >> 2) * (MT / 2), wn0 = (w & 3) * (NT / 4);
    const bool kRemap = (flags & GFLAG_KREMAP) != 0;

    const uint32_t aBase = (uint32_t)(((wm0 + ((l >> 3 & 1) << 3) + (l & 7)) * ASTh + ((l >> 4) << 3)) * 2);
    const uint32_t aBaseT = (uint32_t)(((((l >> 4) << 3) + (l & 7)) * MSTh + wm0 + ((l >> 3 & 1) << 3)) * 2);
    const uint32_t bBase = (uint32_t)(((wn0 + ((l >> 4) << 3) + (l & 7)) * ASTh + ((l >> 3 & 1) << 3)) * 2);

    float acc[MI][NB][4];
#pragma unroll
    for (int a = 0; a < MI; a++)
#pragma unroll
        for (int b = 0; b < NB; b++)
#pragma unroll
            for (int c = 0; c < 4; c++) acc[a][b][c] = 0.f;

    const int nK = K / KC;
    const int kmax = K - KC;

    auto issue = [&](int s, int k0) {
        uint32_t ab = smb + (uint32_t)(s * STG * 2);
        uint32_t bb = ab + (uint32_t)(ASZ * 2);
        if (!ATR) {
            constexpr int ACH = MT * 4;
#pragma unroll
            for (int c0 = 0; c0 < ACH; c0 += 256) {
                int c = c0 + t;
                int row = c >> 2, kq = (c & 3) * 8;
                cpa16(ab + (uint32_t)((row * ASTh + kq) * 2),
                      &A[(long long)(m0 + row) * lda + k0 + kq]);
            }
        } else {
            constexpr int ACH = KC * (MT / 8);
#pragma unroll
            for (int c0 = 0; c0 < ACH; c0 += 256) {
                int c = c0 + t;
                int kr = c >> 3, mq = (c & 7) * 8;
                cpa16(ab + (uint32_t)((kr * MSTh + mq) * 2),
                      &A[(long long)(k0 + kr) * lda + m0 + mq]);
            }
        }
        {
            constexpr int BCH = NT * 4;
#pragma unroll
            for (int c0 = 0; c0 < BCH; c0 += 256) {
                int c = c0 + t;
                int row = c >> 2, kq = (c & 3) * 8;
                int n = n0 + row;
                int g = k0 + kq;
                if (rl) {
                    if (kRemap) { if (g >= rs) g += rl; }
                    else { if (n >= rs) n += rl; }
                }
                cpa16(bb + (uint32_t)((row * ASTh + kq) * 2),
                      &B[(long long)n * ldb + g]);
            }
        }
        asm volatile("cp.async.commit_group;" ::: "memory");
    };

    issue(0, 0);
    if (KC <= kmax) issue(1, KC); else asm volatile("cp.async.commit_group;" ::: "memory");
    if (2 * KC <= kmax) issue(2, 2 * KC); else asm volatile("cp.async.commit_group;" ::: "memory");

    for (int i = 0; i < nK; i++) {
        asm volatile("cp.async.wait_group 2;" ::: "memory");
        __syncthreads();
        int pk = (i + 3) * KC;
        if (pk <= kmax) issue((i + 3) & 3, pk);
        else asm volatile("cp.async.commit_group;" ::: "memory");

        uint32_t abu = smb + (uint32_t)((i & 3) * STG * 2);
        uint32_t bbu = abu + (uint32_t)(ASZ * 2);
#pragma unroll
        for (int kk = 0; kk < 2; kk++) {
            uint32_t af[MI][4], bf[NB][2];
#pragma unroll
            for (int mi = 0; mi < MI; mi++) {
                if (!ATR)
                    ldsm4(af[mi], abu + aBase + (uint32_t)((mi * 16 * ASTh + kk * 16) * 2));
                else
                    ldsm4t(af[mi], abu + aBaseT + (uint32_t)((kk * 16 * MSTh + mi * 16) * 2));
            }
#pragma unroll
            for (int nj = 0; nj < NB / 2; nj++) {
                uint32_t r4[4];
                ldsm4(r4, bbu + bBase + (uint32_t)((nj * 16 * ASTh + kk * 16) * 2));
                bf[2 * nj][0] = r4[0]; bf[2 * nj][1] = r4[1];
                bf[2 * nj + 1][0] = r4[2]; bf[2 * nj + 1][1] = r4[3];
            }
#pragma unroll
            for (int mi = 0; mi < MI; mi++)
#pragma unroll
                for (int ni = 0; ni < NB; ni++) mma16(acc[mi][ni], af[mi], bf[ni]);
        }
    }

#pragma unroll
    for (int mi = 0; mi < MI; mi++) {
        int row0 = m0 + wm0 + mi * 16 + (l >> 2);
#pragma unroll
        for (int ni = 0; ni < NB; ni++) {
            int col = n0 + wn0 + ni * 8 + (l & 3) * 2;
#pragma unroll
            for (int h = 0; h < 2; h++) {
                int row = row0 + h * 8;
                float vx = alpha * acc[mi][ni][h * 2];
                float vy = alpha * acc[mi][ni][h * 2 + 1];
                if (bias) { vx += bias[col]; vy += bias[col + 1]; }
                if (flags & GFLAG_RELU) { vx = fmaxf(vx, 0.f); vy = fmaxf(vy, 0.f); }
                if (clipVal > 0.f) {
                    vx = fminf(fmaxf(vx, -clipVal), clipVal);
                    vy = fminf(fmaxf(vy, -clipVal), clipVal);
                }
                if (residv) {
                    if (RESH) {
                        float2 rv = __half22float2(*(const __half2*)&residH[(long long)row * residLd + col]);
                        vx += rv.x; vy += rv.y;
                    } else {
                        float2 rv = *(const float2*)&residF[(long long)row * residLd + col];
                        vx += rv.x; vy += rv.y;
                    }
                }
                if (OUTH) {
                    *(__half2*)&Ch[(long long)row * ldc + col] = __floats2half2_rn(vx, vy);
                } else {
                    *(float2*)&Cf[(long long)row * ldc + col] = make_float2(vx, vy);
                }
            }
        }
    }
}

// ---------------- flash attention (scores+softmax+PV fused) ----------------
// grid (NTOK/64, EXP*NH), 128 threads / 4 warps, each warp owns 16 q rows.
#define FST 72
__global__ void __launch_bounds__(128) flash_k(
    const __half* __restrict__ qkv, const __half* __restrict__ vT,
    __half* __restrict__ saOut)
{
    __shared__ __half sQ[64 * FST];
    __shared__ __half sK[2][64 * FST];
    __shared__ __half sV[2][64 * FST];

    const int t = threadIdx.x, l = t & 31, w = t >> 5;
    const int q0 = blockIdx.x * 64;
    const int z = blockIdx.y;
    const int e = z >> 3, h = z & 7;

    const __half* Qg = qkv + (long long)e * (NTOK * 3 * DIM) + h * DHEAD;
    const __half* Kg = Qg + DIM;
    const __half* Vg = vT + (long long)e * ND_ELEMS + (long long)(h * DHEAD) * NTOK;

    uint32_t sQb = (uint32_t)__cvta_generic_to_shared(sQ);
    uint32_t sKb = (uint32_t)__cvta_generic_to_shared(sK);
    uint32_t sVb = (uint32_t)__cvta_generic_to_shared(sV);

    auto issueKV = [&](int buf, int kv0) {
#pragma unroll
        for (int c0 = 0; c0 < 512; c0 += 128) {
            int c = c0 + t;
            int row = c >> 3, ch = (c & 7) * 8;
            cpa16(sKb + (uint32_t)((buf * 64 * FST + row * FST + ch) * 2),
                  Kg + (long long)(kv0 + row) * (3 * DIM) + ch);
        }
#pragma unroll
        for (int c0 = 0; c0 < 512; c0 += 128) {
            int c = c0 + t;
            int row = c >> 3, ch = (c & 7) * 8;
            cpa16(sVb + (uint32_t)((buf * 64 * FST + row * FST + ch) * 2),
                  Vg + (long long)row * NTOK + kv0 + ch);
        }
    };

    // Q + tile0, then tile1
    {
#pragma unroll
        for (int c0 = 0; c0 < 512; c0 += 128) {
            int c = c0 + t;
            int row = c >> 3, ch = (c & 7) * 8;
            cpa16(sQb + (uint32_t)((row * FST + ch) * 2),
                  Qg + (long long)(q0 + row) * (3 * DIM) + ch);
        }
        issueKV(0, 0);
        asm volatile("cp.async.commit_group;" ::: "memory");
        issueKV(1, 64);
        asm volatile("cp.async.commit_group;" ::: "memory");
        asm volatile("cp.async.wait_group 1;" ::: "memory");
        __syncthreads();
    }

    const uint32_t aOff = (uint32_t)(((w * 16 + ((l >> 3 & 1) << 3) + (l & 7)) * FST + ((l >> 4) << 3)) * 2);
    const uint32_t bOff = (uint32_t)(((((l >> 4) << 3) + (l & 7)) * FST + ((l >> 3 & 1) << 3)) * 2);

    uint32_t qa[4][4];
#pragma unroll
    for (int kk = 0; kk < 4; kk++) ldsm4(qa[kk], sQb + aOff + kk * 32);

    float oacc[8][4];
#pragma unroll
    for (int b = 0; b < 8; b++)
#pragma unroll
        for (int c = 0; c < 4; c++) oacc[b][c] = 0.f;
    float m0 = -1e30f, m1 = -1e30f, l0 = 0.f, l1 = 0.f;
    const float scale = 0.125f;   // 1/sqrt(64)

    for (int j = 0; j < NTOK / 64; j++) {
        uint32_t kb = sKb + (uint32_t)((j & 1) * 64 * FST * 2);
        uint32_t vb = sVb + (uint32_t)((j & 1) * 64 * FST * 2);

        float sacc[8][4];
#pragma unroll
        for (int b = 0; b < 8; b++)
#pragma unroll
            for (int c = 0; c < 4; c++) sacc[b][c] = 0.f;
#pragma unroll
        for (int kk = 0; kk < 4; kk++) {
#pragma unroll
            for (int nj = 0; nj < 4; nj++) {
                uint32_t r4[4];
                ldsm4(r4, kb + bOff + (uint32_t)((nj * 16 * FST + kk * 16) * 2));
                mma16(sacc[2 * nj], qa[kk], r4);
                mma16(sacc[2 * nj + 1], qa[kk], r4 + 2);
            }
        }
        float rm0 = -1e30f, rm1 = -1e30f;
#pragma unroll
        for (int b = 0; b < 8; b++) {
            rm0 = fmaxf(rm0, fmaxf(sacc[b][0], sacc[b][1]));
            rm1 = fmaxf(rm1, fmaxf(sacc[b][2], sacc[b][3]));
        }
        rm0 = fmaxf(rm0, __shfl_xor_sync(0xffffffffu, rm0, 1));
        rm0 = fmaxf(rm0, __shfl_xor_sync(0xffffffffu, rm0, 2));
        rm1 = fmaxf(rm1, __shfl_xor_sync(0xffffffffu, rm1, 1));
        rm1 = fmaxf(rm1, __shfl_xor_sync(0xffffffffu, rm1, 2));
        float mn0 = fmaxf(m0, rm0 * scale);
        float mn1 = fmaxf(m1, rm1 * scale);
        float cr0 = expf(m0 - mn0), cr1 = expf(m1 - mn1);
        float ps0 = 0.f, ps1 = 0.f;
        uint32_t ph[8][2];
#pragma unroll
        for (int b = 0; b < 8; b++) {
            float p00 = expf(sacc[b][0] * scale - mn0);
            float p01 = expf(sacc[b][1] * scale - mn0);
            float p10 = expf(sacc[b][2] * scale - mn1);
            float p11 = expf(sacc[b][3] * scale - mn1);
            ps0 += p00 + p01; ps1 += p10 + p11;
            __half2 h0 = __floats2half2_rn(p00, p01);
            __half2 h1 = __floats2half2_rn(p10, p11);
            ph[b][0] = *(uint32_t*)&h0;
            ph[b][1] = *(uint32_t*)&h1;
        }
        ps0 += __shfl_xor_sync(0xffffffffu, ps0, 1);
        ps0 += __shfl_xor_sync(0xffffffffu, ps0, 2);
        ps1 += __shfl_xor_sync(0xffffffffu, ps1, 1);
        ps1 += __shfl_xor_sync(0xffffffffu, ps1, 2);
        l0 = l0 * cr0 + ps0; l1 = l1 * cr1 + ps1;
        m0 = mn0; m1 = mn1;
#pragma unroll
        for (int b = 0; b < 8; b++) {
            oacc[b][0] *= cr0; oacc[b][1] *= cr0;
            oacc[b][2] *= cr1; oacc[b][3] *= cr1;
        }
#pragma unroll
        for (int kk2 = 0; kk2 < 4; kk2++) {
            uint32_t pa[4] = { ph[2 * kk2][0], ph[2 * kk2][1], ph[2 * kk2 + 1][0], ph[2 * kk2 + 1][1] };
#pragma unroll
            for (int nj = 0; nj < 4; nj++) {
                uint32_t r4[4];
                ldsm4(r4, vb + bOff + (uint32_t)((nj * 16 * FST + kk2 * 16) * 2));
                mma16(oacc[2 * nj], pa, r4);
                mma16(oacc[2 * nj + 1], pa, r4 + 2);
            }
        }
        __syncthreads();
        int jn = j + 2;
        if (jn < NTOK / 64) issueKV(jn & 1, jn * 64);
        asm volatile("cp.async.commit_group;" ::: "memory");
        asm volatile("cp.async.wait_group 1;" ::: "memory");
        __syncthreads();
    }

    float inv0 = 1.f / l0, inv1 = 1.f / l1;
    int row0 = q0 + w * 16 + (l >> 2);
    __half* outp = saOut + (long long)e * ND_ELEMS + h * DHEAD;
#pragma unroll
    for (int b = 0; b < 8; b++) {
        int col = b * 8 + (l & 3) * 2;
        *(__half2*)&outp[(long long)row0 * DIM + col] =
            __floats2half2_rn(oacc[b][0] * inv0, oacc[b][1] * inv0);
        *(__half2*)&outp[(long long)(row0 + 8) * DIM + col] =
            __floats2half2_rn(oacc[b][2] * inv1, oacc[b][3] * inv1);
    }
}

// ---------------- reductions ----------------
__device__ __forceinline__ float warpReduceSum(float v) {
#pragma unroll
    for (int o = 16; o; o >>= 1) v += __shfl_xor_sync(0xffffffffu, v, o);
    return v;
}
__device__ __forceinline__ float warpReduceMax(float v) {
#pragma unroll
    for (int o = 16; o; o >>= 1) v = fmaxf(v, __shfl_xor_sync(0xffffffffu, v, o));
    return v;
}

// ---------------- fp16 row softmax ----------------
__global__ void softmax_h(__half* __restrict__ p, int cols) {
    extern __shared__ float sbuf[];
    __half2* row = (__half2*)(p + (long long)blockIdx.x * cols);
    int nc2 = cols >> 1;
    __shared__ float sh[8];
    __shared__ float sb;
    int tid = threadIdx.x, lane = tid & 31, wid = tid >> 5;
    float m = -1e30f;
    for (int i = tid; i < nc2; i += 256) {
        float2 v = __half22float2(row[i]);
        sbuf[2 * i] = v.x; sbuf[2 * i + 1] = v.y;
        m = fmaxf(m, fmaxf(v.x, v.y));
    }
    m = warpReduceMax(m);
    if (lane == 0) sh[wid] = m;
    __syncthreads();
    if (tid == 0) { float x = sh[0]; for (int q = 1; q < 8; q++) x = fmaxf(x, sh[q]); sb = x; }
    __syncthreads();
    m = sb;
    float s = 0.f;
    for (int i = tid; i < nc2; i += 256) {
        float a = expf(sbuf[2 * i] - m), b = expf(sbuf[2 * i + 1] - m);
        sbuf[2 * i] = a; sbuf[2 * i + 1] = b;
        s += a + b;
    }
    s = warpReduceSum(s);
    if (lane == 0) sh[wid] = s;
    __syncthreads();
    if (tid == 0) { float x = 0; for (int q = 0; q < 8; q++) x += sh[q]; sb = 1.f / x; }
    __syncthreads();
    float inv = sb;
    for (int i = tid; i < nc2; i += 256)
        row[i] = __floats2half2_rn(sbuf[2 * i] * inv, sbuf[2 * i + 1] * inv);
}

// ---------------- LayerNorm ----------------
__global__ void ln_k(const float* __restrict__ src, __half* __restrict__ dst) {
    long long row = blockIdx.x;
    const float4* x = (const float4*)(src + row * DIM);
    __half2* y = (__half2*)(dst + row * DIM);
    int tid = threadIdx.x, lane = tid & 31, wid = tid >> 5;
    float4 v = x[tid];
    float s = v.x + v.y + v.z + v.w;
    float s2 = v.x * v.x + v.y * v.y + v.z * v.z + v.w * v.w;
    s = warpReduceSum(s); s2 = warpReduceSum(s2);
    __shared__ float sh[2][4]; __shared__ float mv[2];
    if (lane == 0) { sh[0][wid] = s; sh[1][wid] = s2; }
    __syncthreads();
    if (tid == 0) {
        float a = sh[0][0] + sh[0][1] + sh[0][2] + sh[0][3];
        float b = sh[1][0] + sh[1][1] + sh[1][2] + sh[1][3];
        float mean = a / DIM;
        mv[0] = mean; mv[1] = rsqrtf(b / DIM - mean * mean + 1e-5f);
    }
    __syncthreads();
    float mean = mv[0], rstd = mv[1];
    y[2 * tid] = __floats2half2_rn((v.x - mean) * rstd, (v.y - mean) * rstd);
    y[2 * tid + 1] = __floats2half2_rn((v.z - mean) * rstd, (v.w - mean) * rstd);
}

template <int AH>
__global__ void ln_ra_k(const void* __restrict__ av, const float* __restrict__ b,
                        const float* __restrict__ wAll, const float* __restrict__ bAll,
                        float* __restrict__ dst, __half* __restrict__ dstr) {
    long long row = blockIdx.x;
    int e = (int)(row >> 11);
    const float4* xb = (const float4*)(b + row * DIM);
    const float4* w = (const float4*)(wAll + (long long)e * DIM);
    const float4* bb = (const float4*)(bAll + (long long)e * DIM);
    float4* y = (float4*)(dst + row * DIM);
    __half2* yr = (__half2*)(dstr + row * DIM);
    int tid = threadIdx.x, lane = tid & 31, wid = tid >> 5;
    float4 va;
    if (AH) {
        const __half2* xa = (const __half2*)((const __half*)av + row * DIM);
        float2 p0 = __half22float2(xa[2 * tid]), p1 = __half22float2(xa[2 * tid + 1]);
        va = make_float4(p0.x, p0.y, p1.x, p1.y);
    } else {
        va = ((const float4*)((const float*)av + row * DIM))[tid];
    }
    float4 vb = xb[tid];
    float4 v = make_float4(va.x + vb.x, va.y + vb.y, va.z + vb.z, va.w + vb.w);
    float s = v.x + v.y + v.z + v.w;
    float s2 = v.x * v.x + v.y * v.y + v.z * v.z + v.w * v.w;
    s = warpReduceSum(s); s2 = warpReduceSum(s2);
    __shared__ float sh[2][4]; __shared__ float mv[2];
    if (lane == 0) { sh[0][wid] = s; sh[1][wid] = s2; }
    __syncthreads();
    if (tid == 0) {
        float p = sh[0][0] + sh[0][1] + sh[0][2] + sh[0][3];
        float q = sh[1][0] + sh[1][1] + sh[1][2] + sh[1][3];
        float mean = p / DIM;
        mv[0] = mean; mv[1] = rsqrtf(q / DIM - mean * mean + 1e-5f);
    }
    __syncthreads();
    float mean = mv[0], rstd = mv[1];
    float4 ww = w[tid], bbv = bb[tid];
    float4 o = make_float4((v.x - mean) * rstd * ww.x + bbv.x,
                           (v.y - mean) * rstd * ww.y + bbv.y,
                           (v.z - mean) * rstd * ww.z + bbv.z,
                           (v.w - mean) * rstd * ww.w + bbv.w);
    y[tid] = o;
    yr[2 * tid] = __floats2half2_rn(o.x, o.y);
    yr[2 * tid + 1] = __floats2half2_rn(o.z, o.w);
}

__global__ void permute_k(const float4* __restrict__ retr, __half2* __restrict__ rp) {
    long long i = (long long)blockIdx.x * 256 + threadIdx.x;
    constexpr int D4 = DIM / 4;
    if (i < (long long)EXP * NL * NTOK * D4) {
        int d4 = (int)(i & (D4 - 1));
        long long r = i >> 7;
        int n = (int)(r & (NTOK - 1));
        long long r2 = r >> 11;
        int lay = (int)(r2 & (NL - 1));
        long long e = r2 >> 2;
        float4 v = retr[i];
        long long o = (((e * NTOK + n) * NL + lay) * D4 + d4) * 2;
        rp[o] = __floats2half2_rn(v.x, v.y);
        rp[o + 1] = __floats2half2_rn(v.z, v.w);
    }
}

__global__ void zero_k(float* __restrict__ p, long long n) {
    long long i = (long long)blockIdx.x * 256 + threadIdx.x;
    if (i < n) p[i] = 0.f;
}

__global__ void gate_dot_k(const float* __restrict__ outs, const float* __restrict__ gg,
                           float* __restrict__ glog) {
    int e = blockIdx.x;
    constexpr int D4 = DIM / 4;
    long long chunk4 = (long long)(ND_ELEMS / 4) / gridDim.y;
    const float4* base = (const float4*)(outs) + (long long)e * (ND_ELEMS / 4) + (long long)blockIdx.y * chunk4;
    const float4* gg4 = (const float4*)gg;
    float acc = 0.f;
    for (long long i = threadIdx.x; i < chunk4; i += blockDim.x) {
        float4 v = base[i];
        float4 g = gg4[i & (D4 - 1)];
        acc += v.x * g.x + v.y * g.y + v.z * g.z + v.w * g.w;
    }
    acc = warpReduceSum(acc);
    __shared__ float sh[8];
    int lane = threadIdx.x & 31, wid = threadIdx.x >> 5;
    if (lane == 0) sh[wid] = acc;
    __syncthreads();
    if (threadIdx.x == 0) {
        float x = 0;
        for (int q = 0; q < 8; q++) x += sh[q];
        atomicAdd(&glog[e], x);
    }
}

__global__ void gate_softmax_k(const float* __restrict__ glog, float* __restrict__ gw) {
    if (threadIdx.x == 0) {
        float l[EXP], m = -1e30f;
        for (int e = 0; e < EXP; e++) {
            l[e] = fminf(fmaxf(glog[e] / (float)NTOK, -10.f), 10.f);
            m = fmaxf(m, l[e]);
        }
        float s = 0.f;
        for (int e = 0; e < EXP; e++) { l[e] = expf(l[e] - m); s += l[e]; }
        for (int e = 0; e < EXP; e++) gw[e] = l[e] / s;
    }
}

__global__ void fuse_k(const float4* __restrict__ outs, const float* __restrict__ gw,
                       float4* __restrict__ fused) {
    long long i = (long long)blockIdx.x * 256 + threadIdx.x;
    constexpr long long N4 = ND_ELEMS / 4;
    if (i < N4) {
        float4 r = make_float4(0.f, 0.f, 0.f, 0.f);
#pragma unroll
        for (int e = 0; e < EXP; e++) {
            float4 v = outs[(long long)e * N4 + i];
            float gwe = gw[e];
            r.x += gwe * v.x; r.y += gwe * v.y; r.z += gwe * v.z; r.w += gwe * v.w;
        }
        fused[i] = r;
    }
}

__global__ void memupd_k(const float4* __restrict__ mem, const float4* __restrict__ upd4,
                         float4* __restrict__ o) {
    long long i = (long long)blockIdx.x * 256 + threadIdx.x;
    constexpr long long N4 = (long long)LMD_ELEMS / 4;
    if (i < N4) {
        float4 u = upd4[i];
#pragma unroll
        for (int e = 1; e < EXP; e++) {
            float4 v = upd4[(long long)e * N4 + i];
            u.x += v.x; u.y += v.y; u.z += v.z; u.w += v.w;
        }
        float4 mm = mem[i];
        float4 r;
        r.x = 0.9f * mm.x + fminf(fmaxf(0.1f * u.x, -0.1f), 0.1f);
        r.y = 0.9f * mm.y + fminf(fmaxf(0.1f * u.y, -0.1f), 0.1f);
        r.z = 0.9f * mm.z + fminf(fmaxf(0.1f * u.z, -0.1f), 0.1f);
        r.w = 0.9f * mm.w + fminf(fmaxf(0.1f * u.w, -0.1f), 0.1f);
        o[i] = r;
    }
}

// ---------------- host ----------------
static constexpr int stgH(int MT, int NT, bool ATR) {
    return (ATR ? 32 * (MT + 8) : MT * 40) + NT * 40;
}
#define SMEMH(MT, NT, ATR) (4 * stgH(MT, NT, ATR) * 2)

static void tohalf(const float* s, __half* d, long long n) {
    long long n4 = n / 4;
    tohalf_k<<<(int)((n4 + 255) / 256), 256>>>((const float4*)s, (__half2*)d, n4);
}

extern "C" void kernel_launch(void* const* d_in, const int* in_sizes, int n_in,
                              void* d_out, int out_size) {
    const float* tokens   = (const float*)d_in[0];
    const float* memories = (const float*)d_in[1];
    const float* ipw      = (const float*)d_in[2];
    const float* ipb      = (const float*)d_in[3];
    const float* opw      = (const float*)d_in[4];
    const float* opb      = (const float*)d_in[5];
    const float* w1       = (const float*)d_in[6];
    const float* b1       = (const float*)d_in[7];
    const float* w2       = (const float*)d_in[8];
    const float* b2       = (const float*)d_in[9];
    const float* n1w      = (const float*)d_in[10];
    const float* n1b      = (const float*)d_in[11];
    const float* n2w      = (const float*)d_in[12];
    const float* n2b      = (const float*)d_in[13];
    const float* aggw     = (const float*)d_in[14];
    const float* aggb     = (const float*)d_in[15];
    const float* gg       = (const float*)d_in[16];

    float* out = (float*)d_out;
    float* out_fused = out;
    float* out_gw = out + ND_ELEMS;
    float* out_mem = out + ND_ELEMS + EXP;

    static __half *h_xln = nullptr, *h_xlnT = nullptr, *h_x4 = nullptr, *h_qkv = nullptr,
                  *h_big = nullptr, *h_sa = nullptr, *h_x1r = nullptr, *h_xor = nullptr,
                  *h_xorT = nullptr, *h_vT = nullptr, *h_tmp = nullptr, *h_retrp = nullptr,
                  *h_ipw = nullptr, *h_opw = nullptr, *h_w1 = nullptr, *h_w2 = nullptr,
                  *h_aggw = nullptr, *h_mem = nullptr, *h_memT = nullptr;
    static float *p_op4 = nullptr, *p_x14 = nullptr, *p_out = nullptr,
                 *p_retr4 = nullptr, *p_upd4 = nullptr, *p_glog = nullptr;
    if (!h_xln) {
        cudaGetSymbolAddress((void**)&h_xln, gh_xln);
        cudaGetSymbolAddress((void**)&h_xlnT, gh_xlnT);
        cudaGetSymbolAddress((void**)&h_x4, gh_x4);
        cudaGetSymbolAddress((void**)&h_qkv, gh_qkv);
        cudaGetSymbolAddress((void**)&h_big, gh_big);
        cudaGetSymbolAddress((void**)&h_sa, gh_sa);
        cudaGetSymbolAddress((void**)&h_x1r, gh_x1r);
        cudaGetSymbolAddress((void**)&h_xor, gh_xor);
        cudaGetSymbolAddress((void**)&h_xorT, gh_xorT);
        cudaGetSymbolAddress((void**)&h_vT, gh_vT);
        cudaGetSymbolAddress((void**)&h_tmp, gh_tmp);
        cudaGetSymbolAddress((void**)&h_retrp, gh_retrp);
        cudaGetSymbolAddress((void**)&h_ipw, gh_ipw);
        cudaGetSymbolAddress((void**)&h_opw, gh_opw);
        cudaGetSymbolAddress((void**)&h_w1, gh_w1);
        cudaGetSymbolAddress((void**)&h_w2, gh_w2);
        cudaGetSymbolAddress((void**)&h_aggw, gh_aggw);
        cudaGetSymbolAddress((void**)&h_mem, gh_mem);
        cudaGetSymbolAddress((void**)&h_memT, gh_memT);
        cudaGetSymbolAddress((void**)&p_op4, g_op4);
        cudaGetSymbolAddress((void**)&p_x14, g_x14);
        cudaGetSymbolAddress((void**)&p_out, g_out);
        cudaGetSymbolAddress((void**)&p_retr4, g_retr4);
        cudaGetSymbolAddress((void**)&p_upd4, g_upd4);
        cudaGetSymbolAddress((void**)&p_glog, g_glog);
        cudaFuncSetAttribute(gemmH<64, 128, false, 1, 0>, cudaFuncAttributeMaxDynamicSharedMemorySize, SMEMH(64, 128, false));
        cudaFuncSetAttribute(gemmH<64, 128, false, 1, 1>, cudaFuncAttributeMaxDynamicSharedMemorySize, SMEMH(64, 128, false));
        cudaFuncSetAttribute(gemmH<64, 128, false, 0, 0>, cudaFuncAttributeMaxDynamicSharedMemorySize, SMEMH(64, 128, false));
        cudaFuncSetAttribute(gemmH<64, 128, true, 0, 0>,  cudaFuncAttributeMaxDynamicSharedMemorySize, SMEMH(64, 128, true));
    }

    const float inv_sqrt_d = 1.0f / sqrtf((float)DIM);

    const long long LLND = ND_ELEMS;
    const long long QKVE = (long long)NTOK * 3 * DIM;

    // launches 1-5 (6th = cross GEMM for ncu)
    zero_k<<<1, 256>>>(p_glog, EXP);
    ln_k<<<EXP * NTOK, 128>>>(tokens, h_xln);
    transpose_h<<<dim3(DIM / 32, EXP * NTOK / 32, 1), dim3(32, 8)>>>(
        h_xln, h_xlnT, EXP * NTOK, DIM, DIM, 0, 0);
    tohalf(ipw, h_ipw, (long long)EXP * 3 * DIM * DIM);
    tohalf(opw, h_opw, (long long)EXP * DIM * DIM);

    // 1. cross logits [e][2048, 6144] fp16 out  <- 6th launch
    gemmH<64, 128, false, 1, 0><<<dim3(48, 32, EXP), 256, SMEMH(64, 128, false)>>>(
        h_xln, h_xln, h_big, DIM, DIM, DIM, 3 * NTOK,
        LLND, 0, 0, 0, (long long)NTOK * 3 * NTOK, 0, 1,
        inv_sqrt_d, nullptr, 0, nullptr, 0, 0, 10.f, 0, -1, NTOK);

    tohalf(w1, h_w1, (long long)EXP * FFD * DIM);
    tohalf(w2, h_w2, (long long)EXP * DIM * FFD);
    tohalf(aggw, h_aggw, (long long)DIM * NL * DIM);
    tohalf(memories, h_mem, (long long)LMD_ELEMS);
    transpose_fh<<<dim3(DIM / 32, MEMSZ / 32, NL), dim3(32, 8)>>>(
        memories, h_memT, MEMSZ, DIM, DIM, (long long)MEMSZ * DIM, (long long)MEMSZ * DIM);

    softmax_h<<<EXP * NTOK, 256, 3 * NTOK * 4>>>(h_big, 3 * NTOK);
    // 2. x = probs @ ctx + xln
    gemmH<64, 128, false, 1, 1><<<dim3(4, 32, EXP), 256, SMEMH(64, 128, false)>>>(
        h_big, h_xlnT, h_x4, 3 * NTOK, 3 * NTOK, EXP * NTOK, DIM,
        (long long)NTOK * 3 * NTOK, 0, 0, 0, LLND, 0, 1,
        1.f, nullptr, 0, h_xln, LLND, DIM, 0.f, GFLAG_KREMAP, -1, NTOK);
    // 3. qkv fp16
    gemmH<64, 128, false, 1, 0><<<dim3(12, 32, EXP), 256, SMEMH(64, 128, false)>>>(
        h_x4, h_ipw, h_qkv, DIM, DIM, DIM, 3 * DIM,
        LLND, 0, (long long)3 * DIM * DIM, 0, QKVE, 0, 1,
        1.f, ipb, 3 * DIM, nullptr, 0, 0, 0.f, 0, 0, 0);
    transpose_h<<<dim3(DIM / 32, NTOK / 32, EXP), dim3(32, 8)>>>(
        h_qkv + 2 * DIM, h_vT, NTOK, DIM, 3 * DIM, QKVE, LLND);
    // 4+5. flash attention (scores+softmax+PV fused)
    flash_k<<<dim3(NTOK / 64, EXP * NH), 128>>>(h_qkv, h_vT, h_sa);
    // 6. out_proj fp32 out
    gemmH<64, 128, false, 0, 0><<<dim3(4, 32, EXP), 256, SMEMH(64, 128, false)>>>(
        h_sa, h_opw, p_op4, DIM, DIM, DIM, DIM,
        LLND, 0, (long long)DIM * DIM, 0, LLND, 0, 1,
        1.f, opb, DIM, nullptr, 0, 0, 0.f, 0, 0, 0);
    ln_ra_k<1><<<EXP * NTOK, 128>>>(h_x4, p_op4, n1w, n1b, p_x14, h_x1r);
    // 7. ff1 relu fp16
    gemmH<64, 128, false, 1, 0><<<dim3(16, 32, EXP), 256, SMEMH(64, 128, false)>>>(
        h_x1r, h_w1, h_tmp, DIM, DIM, DIM, FFD,
        LLND, 0, (long long)FFD * DIM, 0, (long long)NTOK * FFD, 0, 1,
        1.f, b1, FFD, nullptr, 0, 0, 0.f, GFLAG_RELU, 0, 0);
    // 8. ff2 fp32 out
    gemmH<64, 128, false, 0, 0><<<dim3(4, 32, EXP), 256, SMEMH(64, 128, false)>>>(
        h_tmp, h_w2, p_op4, FFD, FFD, FFD, DIM,
        (long long)NTOK * FFD, 0, (long long)DIM * FFD, 0, LLND, 0, 1,
        1.f, b2, DIM, nullptr, 0, 0, 0.f, 0, 0, 0);
    ln_ra_k<0><<<EXP * NTOK, 128>>>(p_x14, p_op4, n2w, n2b, p_out, h_xor);
    transpose_h<<<dim3(DIM / 32, NTOK / 32, EXP), dim3(32, 8)>>>(
        h_xor, h_xorT, NTOK, DIM, DIM, LLND, LLND);
    // 9. memory logits fp16
    gemmH<64, 128, false, 1, 0><<<dim3(32, 32, EXP * NL), 256, SMEMH(64, 128, false)>>>(
        h_xor, h_mem, h_big, DIM, DIM, DIM, MEMSZ,
        LLND, 0, 0, (long long)MEMSZ * DIM, (long long)NL * NTOK * MEMSZ, (long long)NTOK * MEMSZ, NL,
        inv_sqrt_d, nullptr, 0, nullptr, 0, 0, 10.f, 0, 0, 0);
    softmax_h<<<EXP * NL * NTOK, 256, MEMSZ * 4>>>(h_big, MEMSZ);
    // 10. retr fp32 out
    gemmH<64, 128, false, 0, 0><<<dim3(4, 32, EXP * NL), 256, SMEMH(64, 128, false)>>>(
        h_big, h_memT, p_retr4, MEMSZ, MEMSZ, MEMSZ, DIM,
        (long long)NL * NTOK * MEMSZ, (long long)NTOK * MEMSZ, 0, (long long)MEMSZ * DIM,
        (long long)NL * NTOK * DIM, (long long)NTOK * DIM, NL,
        1.f, nullptr, 0, nullptr, 0, 0, 0.f, 0, 0, 0);
    // 11. upd = clip(am^T @ xout, 1)
    gemmH<64, 128, true, 0, 0><<<dim3(4, 64, EXP * NL), 256, SMEMH(64, 128, true)>>>(
        h_big, h_xorT, p_upd4, NTOK, MEMSZ, NTOK, DIM,
        (long long)NL * NTOK * MEMSZ, (long long)NTOK * MEMSZ, LLND, 0,
        (long long)LMD_ELEMS, (long long)MEMSZ * DIM, NL,
        1.f, nullptr, 0, nullptr, 0, 0, 1.f, 0, 0, 0);
    permute_k<<<(EXP * NL * ND_ELEMS / 4 + 255) / 256, 256>>>((const float4*)p_retr4, (__half2*)h_retrp);
    // 12. outs += retrp @ aggw^T + aggb
    gemmH<64, 128, false, 0, 0><<<dim3(4, 32, EXP), 256, SMEMH(64, 128, false)>>>(
        h_retrp, h_aggw, p_out, NL * DIM, NL * DIM, NL * DIM, DIM,
        (long long)NTOK * NL * DIM, 0, 0, 0, LLND, 0, 1,
        1.f, aggb, 0, p_out, LLND, DIM, 0.f, 0, 0, 0);

    dim3 ggrid(EXP, 16);
    gate_dot_k<<<ggrid, 256>>>(p_out, gg, p_glog);
    gate_softmax_k<<<1, 32>>>(p_glog, out_gw);
    fuse_k<<<(ND_ELEMS / 4 + 255) / 256, 256>>>((const float4*)p_out, out_gw, (float4*)out_fused);
    memupd_k<<<(LMD_ELEMS / 4 + 255) / 256, 256>>>((const float4*)memories, (const float4*)p_upd4, (float4*)out_mem);

    (void)in_sizes; (void)n_in; (void)out_size;
}

// round 16
// speedup vs baseline: 3.0929x; 1.0247x over previous
#include <cuda_runtime.h>
#include <cuda_fp16.h>
#include <math.h>
#include <stdint.h>

#define EXP 4
#define NTOK 2048
#define DIM 512
#define NH 8
#define DHEAD 64
#define FFD 2048
#define NL 4
#define MEMSZ 4096

#define ND_ELEMS (NTOK * DIM)
#define LMD_ELEMS (NL * MEMSZ * DIM)

#define GFLAG_RELU 1
#define GFLAG_KREMAP 2
#define GFLAG_EXPOUT 4
#define GFLAG_RSCALE 8

// ---------------- scratch ----------------
__device__ __half gh_xln[EXP * NTOK * DIM];
__device__ __half gh_xlnT[EXP * NTOK * DIM];
__device__ __half gh_x4[EXP * NTOK * DIM];
__device__ __half gh_qkv[(size_t)EXP * NTOK * 3 * DIM];
__device__ __half gh_big[(size_t)EXP * NH * NTOK * NTOK];
__device__ __half gh_sa[EXP * NTOK * DIM];
__device__ __half gh_x1r[EXP * NTOK * DIM];
__device__ __half gh_xor[EXP * NTOK * DIM];
__device__ __half gh_xorT[EXP * NTOK * DIM];
__device__ __half gh_xorS[(size_t)EXP * NL * NTOK * DIM];
__device__ __half gh_vT[(size_t)EXP * NTOK * DIM];
__device__ __half gh_tmp[(size_t)EXP * NTOK * FFD];
__device__ __half gh_retrp[(size_t)EXP * NTOK * NL * DIM];
__device__ __half gh_ipw[EXP * 3 * DIM * DIM];
__device__ __half gh_opw[EXP * DIM * DIM];
__device__ __half gh_w1[EXP * FFD * DIM];
__device__ __half gh_w2[EXP * DIM * FFD];
__device__ __half gh_aggw[DIM * NL * DIM];
__device__ __half gh_mem[LMD_ELEMS];
__device__ __half gh_memT[LMD_ELEMS];
__device__ float g_op4[EXP * NTOK * DIM];
__device__ float g_x14[EXP * NTOK * DIM];
__device__ float g_out[EXP * NTOK * DIM];
__device__ float g_retr4[(size_t)EXP * NL * NTOK * DIM];
__device__ float g_upd4[(size_t)EXP * NL * MEMSZ * DIM];
__device__ float g_glog[EXP];
__device__ float g_rsum[(EXP + EXP * NL) * NTOK];   // cross rows | memory rows

// ---------------- helpers ----------------
__device__ __forceinline__ void mma16(float* c, const uint32_t* a, const uint32_t* b) {
    asm volatile(
        "mma.sync.aligned.m16n8k16.row.col.f32.f16.f16.f32 "
        "{%0,%1,%2,%3}, {%4,%5,%6,%7}, {%8,%9}, {%0,%1,%2,%3};"
        : "+f"(c[0]), "+f"(c[1]), "+f"(c[2]), "+f"(c[3])
        : "r"(a[0]), "r"(a[1]), "r"(a[2]), "r"(a[3]), "r"(b[0]), "r"(b[1]));
}
__device__ __forceinline__ void cpa16(uint32_t s, const void* g) {
    asm volatile("cp.async.cg.shared.global [%0], [%1], 16;" :: "r"(s), "l"(g));
}
__device__ __forceinline__ void ldsm4(uint32_t* r, uint32_t a) {
    asm volatile("ldmatrix.sync.aligned.m8n8.x4.shared.b16 {%0,%1,%2,%3}, [%4];"
        : "=r"(r[0]), "=r"(r[1]), "=r"(r[2]), "=r"(r[3]) : "r"(a));
}
__device__ __forceinline__ void ldsm4t(uint32_t* r, uint32_t a) {
    asm volatile("ldmatrix.sync.aligned.m8n8.x4.trans.shared.b16 {%0,%1,%2,%3}, [%4];"
        : "=r"(r[0]), "=r"(r[1]), "=r"(r[2]), "=r"(r[3]) : "r"(a));
}

__global__ void tohalf_k(const float4* __restrict__ s, __half2* __restrict__ d, long long n4) {
    long long i = (long long)blockIdx.x * 256 + threadIdx.x;
    if (i < n4) {
        float4 v = s[i];
        d[2 * i] = __floats2half2_rn(v.x, v.y);
        d[2 * i + 1] = __floats2half2_rn(v.z, v.w);
    }
}

__global__ void transpose_h(const __half* __restrict__ in, __half* __restrict__ out,
                            int rows, int cols, int ldin, long long inB, long long outB) {
    __shared__ __half tile[32][38];
    int z = blockIdx.z;
    in += inB * z; out += outB * z;
    int c0 = blockIdx.x * 32, r0 = blockIdx.y * 32;
    int x = threadIdx.x, y = threadIdx.y;
#pragma unroll
    for (int j = 0; j < 32; j += 8)
        tile[y + j][x] = in[(long long)(r0 + y + j) * ldin + c0 + x];
    __syncthreads();
#pragma unroll
    for (int j = 0; j < 32; j += 8)
        out[(long long)(c0 + y + j) * rows + r0 + x] = tile[x][y + j];
}

__global__ void transpose_fh(const float* __restrict__ in, __half* __restrict__ out,
                             int rows, int cols, int ldin, long long inB, long long outB) {
    __shared__ float tile[32][33];
    int z = blockIdx.z;
    in += inB * z; out += outB * z;
    int c0 = blockIdx.x * 32, r0 = blockIdx.y * 32;
    int x = threadIdx.x, y = threadIdx.y;
#pragma unroll
    for (int j = 0; j < 32; j += 8)
        tile[y + j][x] = in[(long long)(r0 + y + j) * ldin + c0 + x];
    __syncthreads();
#pragma unroll
    for (int j = 0; j < 32; j += 8)
        out[(long long)(c0 + y + j) * rows + r0 + x] = __float2half_rn(tile[x][y + j]);
}

// xorS[e][l][d][n] = xorT[e][d][n] * 4096/rsumMem[(e*NL+l)*NTOK + n]
__global__ void scalexor_k(const __half2* __restrict__ xorT, const float* __restrict__ rsum,
                           __half2* __restrict__ xorS) {
    long long i = (long long)blockIdx.x * 256 + threadIdx.x;
    constexpr int N2 = NTOK / 2;
    if (i < (long long)EXP * NL * DIM * N2) {
        int n2 = (int)(i % N2);
        long long r = i / N2;
        int d = (int)(r % DIM);
        long long r2 = r / DIM;
        int l = (int)(r2 % NL);
        int e = (int)(r2 / NL);
        float2 f = __half22float2(xorT[((long long)e * DIM + d) * N2 + n2]);
        const float* rs = rsum + ((long long)e * NL + l) * NTOK + 2 * n2;
        xorS[i] = __floats2half2_rn(f.x * (4096.f / rs[0]), f.y * (4096.f / rs[1]));
    }
}

// ---------------- fp16 m16n8k16 cp.async GEMM ----------------
template <int MT, int NT, bool ATR, int OUTH, int RESH>
__global__ void __launch_bounds__(256, 3) gemmH(
    const __half* __restrict__ A, const __half* __restrict__ B, void* __restrict__ Cv,
    int K, int lda, int ldb, int ldc,
    long long aB, long long aBi, long long bB, long long bBi,
    long long cB, long long cBi, int zInner,
    float alpha, const float* __restrict__ bias, long long biasB,
    const void* __restrict__ residv, long long residB, int residLd,
    float clipVal, int flags, int rs, int rl,
    float* __restrict__ rowSum, long long rsStride)
{
    constexpr int KC = 32;
    constexpr int ASTh = 40;
    constexpr int MSTh = MT + 8;
    constexpr int ASZ = ATR ? KC * MSTh : MT * ASTh;
    constexpr int BSZ = NT * ASTh;
    constexpr int STG = ASZ + BSZ;
    constexpr int MI = MT / 32;
    constexpr int NB = NT / 32;

    extern __shared__ __half smh[];
    uint32_t smb = (uint32_t)__cvta_generic_to_shared(smh);

    const int t = threadIdx.x, l = t & 31, w = t >> 5;
    const int bz = blockIdx.z;
    const int zo = bz / zInner, zi = bz - zo * zInner;
    A += aB * zo + aBi * zi;
    B += bB * zo + bBi * zi;
    float* Cf = nullptr; __half* Ch = nullptr;
    if (OUTH) Ch = (__half*)Cv + cB * zo + cBi * zi;
    else      Cf = (float*)Cv + cB * zo + cBi * zi;
    if (bias) bias += biasB * zo;
    const float* residF = nullptr; const __half* residH = nullptr;
    if (residv) {
        if (RESH) residH = (const __half*)residv + residB * zo;
        else      residF = (const float*)residv + residB * zo;
    }
    if (rowSum) rowSum += rsStride * bz;
    if (rs < 0) rs = zo * rl;
    const int m0 = blockIdx.y * MT, n0 = blockIdx.x * NT;
    const int wm0 = (w >> 2) * (MT / 2), wn0 = (w & 3) * (NT / 4);
    const bool kRemap = (flags & GFLAG_KREMAP) != 0;

    const uint32_t aBase = (uint32_t)(((wm0 + ((l >> 3 & 1) << 3) + (l & 7)) * ASTh + ((l >> 4) << 3)) * 2);
    const uint32_t aBaseT = (uint32_t)(((((l >> 4) << 3) + (l & 7)) * MSTh + wm0 + ((l >> 3 & 1) << 3)) * 2);
    const uint32_t bBase = (uint32_t)(((wn0 + ((l >> 4) << 3) + (l & 7)) * ASTh + ((l >> 3 & 1) << 3)) * 2);

    float acc[MI][NB][4];
#pragma unroll
    for (int a = 0; a < MI; a++)
#pragma unroll
        for (int b = 0; b < NB; b++)
#pragma unroll
            for (int c = 0; c < 4; c++) acc[a][b][c] = 0.f;

    const int nK = K / KC;
    const int kmax = K - KC;

    auto issue = [&](int s, int k0) {
        uint32_t ab = smb + (uint32_t)(s * STG * 2);
        uint32_t bb = ab + (uint32_t)(ASZ * 2);
        if (!ATR) {
            constexpr int ACH = MT * 4;
#pragma unroll
            for (int c0 = 0; c0 < ACH; c0 += 256) {
                int c = c0 + t;
                int row = c >> 2, kq = (c & 3) * 8;
                cpa16(ab + (uint32_t)((row * ASTh + kq) * 2),
                      &A[(long long)(m0 + row) * lda + k0 + kq]);
            }
        } else {
            constexpr int ACH = KC * (MT / 8);
#pragma unroll
            for (int c0 = 0; c0 < ACH; c0 += 256) {
                int c = c0 + t;
                int kr = c >> 3, mq = (c & 7) * 8;
                cpa16(ab + (uint32_t)((kr * MSTh + mq) * 2),
                      &A[(long long)(k0 + kr) * lda + m0 + mq]);
            }
        }
        {
            constexpr int BCH = NT * 4;
#pragma unroll
            for (int c0 = 0; c0 < BCH; c0 += 256) {
                int c = c0 + t;
                int row = c >> 2, kq = (c & 3) * 8;
                int n = n0 + row;
                int g = k0 + kq;
                if (rl) {
                    if (kRemap) { if (g >= rs) g += rl; }
                    else { if (n >= rs) n += rl; }
                }
                cpa16(bb + (uint32_t)((row * ASTh + kq) * 2),
                      &B[(long long)n * ldb + g]);
            }
        }
        asm volatile("cp.async.commit_group;" ::: "memory");
    };

    issue(0, 0);
    if (KC <= kmax) issue(1, KC); else asm volatile("cp.async.commit_group;" ::: "memory");
    if (2 * KC <= kmax) issue(2, 2 * KC); else asm volatile("cp.async.commit_group;" ::: "memory");

    for (int i = 0; i < nK; i++) {
        asm volatile("cp.async.wait_group 2;" ::: "memory");
        __syncthreads();
        int pk = (i + 3) * KC;
        if (pk <= kmax) issue((i + 3) & 3, pk);
        else asm volatile("cp.async.commit_group;" ::: "memory");

        uint32_t abu = smb + (uint32_t)((i & 3) * STG * 2);
        uint32_t bbu = abu + (uint32_t)(ASZ * 2);
#pragma unroll
        for (int kk = 0; kk < 2; kk++) {
            uint32_t af[MI][4], bf[NB][2];
#pragma unroll
            for (int mi = 0; mi < MI; mi++) {
                if (!ATR)
                    ldsm4(af[mi], abu + aBase + (uint32_t)((mi * 16 * ASTh + kk * 16) * 2));
                else
                    ldsm4t(af[mi], abu + aBaseT + (uint32_t)((kk * 16 * MSTh + mi * 16) * 2));
            }
#pragma unroll
            for (int nj = 0; nj < NB / 2; nj++) {
                uint32_t r4[4];
                ldsm4(r4, bbu + bBase + (uint32_t)((nj * 16 * ASTh + kk * 16) * 2));
                bf[2 * nj][0] = r4[0]; bf[2 * nj][1] = r4[1];
                bf[2 * nj + 1][0] = r4[2]; bf[2 * nj + 1][1] = r4[3];
            }
#pragma unroll
            for (int mi = 0; mi < MI; mi++)
#pragma unroll
                for (int ni = 0; ni < NB; ni++) mma16(acc[mi][ni], af[mi], bf[ni]);
        }
    }

    // epilogue
    float rsAcc[MI][2];
#pragma unroll
    for (int a = 0; a < MI; a++) { rsAcc[a][0] = 0.f; rsAcc[a][1] = 0.f; }

#pragma unroll
    for (int mi = 0; mi < MI; mi++) {
        int row0 = m0 + wm0 + mi * 16 + (l >> 2);
        float sc0 = 1.f, sc1 = 1.f;
        if (flags & GFLAG_RSCALE) {
            sc0 = 1.f / rowSum[row0];
            sc1 = 1.f / rowSum[row0 + 8];
        }
#pragma unroll
        for (int ni = 0; ni < NB; ni++) {
            int col = n0 + wn0 + ni * 8 + (l & 3) * 2;
#pragma unroll
            for (int h = 0; h < 2; h++) {
                int row = row0 + h * 8;
                float vx = alpha * acc[mi][ni][h * 2];
                float vy = alpha * acc[mi][ni][h * 2 + 1];
                if (bias) { vx += bias[col]; vy += bias[col + 1]; }
                if (flags & GFLAG_RELU) { vx = fmaxf(vx, 0.f); vy = fmaxf(vy, 0.f); }
                if (clipVal > 0.f) {
                    vx = fminf(fmaxf(vx, -clipVal), clipVal);
                    vy = fminf(fmaxf(vy, -clipVal), clipVal);
                }
                if (flags & GFLAG_EXPOUT) {
                    vx = expf(vx); vy = expf(vy);
                    rsAcc[mi][h] += vx + vy;
                }
                if (flags & GFLAG_RSCALE) {
                    float sc = h ? sc1 : sc0;
                    vx *= sc; vy *= sc;
                }
                if (residv) {
                    if (RESH) {
                        float2 rv = __half22float2(*(const __half2*)&residH[(long long)row * residLd + col]);
                        vx += rv.x; vy += rv.y;
                    } else {
                        float2 rv = *(const float2*)&residF[(long long)row * residLd + col];
                        vx += rv.x; vy += rv.y;
                    }
                }
                if (OUTH) {
                    *(__half2*)&Ch[(long long)row * ldc + col] = __floats2half2_rn(vx, vy);
                } else {
                    *(float2*)&Cf[(long long)row * ldc + col] = make_float2(vx, vy);
                }
            }
        }
    }
    if (flags & GFLAG_EXPOUT) {
#pragma unroll
        for (int mi = 0; mi < MI; mi++)
#pragma unroll
            for (int h = 0; h < 2; h++) {
                float v = rsAcc[mi][h];
                v += __shfl_xor_sync(0xffffffffu, v, 1);
                v += __shfl_xor_sync(0xffffffffu, v, 2);
                if ((l & 3) == 0) {
                    int row = m0 + wm0 + mi * 16 + (l >> 2) + h * 8;
                    atomicAdd(&rowSum[row], v);
                }
            }
    }
}

// ---------------- flash attention ----------------
#define FST 72
__global__ void __launch_bounds__(128) flash_k(
    const __half* __restrict__ qkv, const __half* __restrict__ vT,
    __half* __restrict__ saOut)
{
    __shared__ __half sQ[64 * FST];
    __shared__ __half sK[2][64 * FST];
    __shared__ __half sV[2][64 * FST];

    const int t = threadIdx.x, l = t & 31, w = t >> 5;
    const int q0 = blockIdx.x * 64;
    const int z = blockIdx.y;
    const int e = z >> 3, h = z & 7;

    const __half* Qg = qkv + (long long)e * (NTOK * 3 * DIM) + h * DHEAD;
    const __half* Kg = Qg + DIM;
    const __half* Vg = vT + (long long)e * ND_ELEMS + (long long)(h * DHEAD) * NTOK;

    uint32_t sQb = (uint32_t)__cvta_generic_to_shared(sQ);
    uint32_t sKb = (uint32_t)__cvta_generic_to_shared(sK);
    uint32_t sVb = (uint32_t)__cvta_generic_to_shared(sV);

    auto issueKV = [&](int buf, int kv0) {
#pragma unroll
        for (int c0 = 0; c0 < 512; c0 += 128) {
            int c = c0 + t;
            int row = c >> 3, ch = (c & 7) * 8;
            cpa16(sKb + (uint32_t)((buf * 64 * FST + row * FST + ch) * 2),
                  Kg + (long long)(kv0 + row) * (3 * DIM) + ch);
        }
#pragma unroll
        for (int c0 = 0; c0 < 512; c0 += 128) {
            int c = c0 + t;
            int row = c >> 3, ch = (c & 7) * 8;
            cpa16(sVb + (uint32_t)((buf * 64 * FST + row * FST + ch) * 2),
                  Vg + (long long)row * NTOK + kv0 + ch);
        }
    };

    {
#pragma unroll
        for (int c0 = 0; c0 < 512; c0 += 128) {
            int c = c0 + t;
            int row = c >> 3, ch = (c & 7) * 8;
            cpa16(sQb + (uint32_t)((row * FST + ch) * 2),
                  Qg + (long long)(q0 + row) * (3 * DIM) + ch);
        }
        issueKV(0, 0);
        asm volatile("cp.async.commit_group;" ::: "memory");
        issueKV(1, 64);
        asm volatile("cp.async.commit_group;" ::: "memory");
        asm volatile("cp.async.wait_group 1;" ::: "memory");
        __syncthreads();
    }

    const uint32_t aOff = (uint32_t)(((w * 16 + ((l >> 3 & 1) << 3) + (l & 7)) * FST + ((l >> 4) << 3)) * 2);
    const uint32_t bOff = (uint32_t)(((((l >> 4) << 3) + (l & 7)) * FST + ((l >> 3 & 1) << 3)) * 2);

    uint32_t qa[4][4];
#pragma unroll
    for (int kk = 0; kk < 4; kk++) ldsm4(qa[kk], sQb + aOff + kk * 32);

    float oacc[8][4];
#pragma unroll
    for (int b = 0; b < 8; b++)
#pragma unroll
        for (int c = 0; c < 4; c++) oacc[b][c] = 0.f;
    float m0 = -1e30f, m1 = -1e30f, l0 = 0.f, l1 = 0.f;
    const float scale = 0.125f;

    for (int j = 0; j < NTOK / 64; j++) {
        uint32_t kb = sKb + (uint32_t)((j & 1) * 64 * FST * 2);
        uint32_t vb = sVb + (uint32_t)((j & 1) * 64 * FST * 2);

        float sacc[8][4];
#pragma unroll
        for (int b = 0; b < 8; b++)
#pragma unroll
            for (int c = 0; c < 4; c++) sacc[b][c] = 0.f;
#pragma unroll
        for (int kk = 0; kk < 4; kk++) {
#pragma unroll
            for (int nj = 0; nj < 4; nj++) {
                uint32_t r4[4];
                ldsm4(r4, kb + bOff + (uint32_t)((nj * 16 * FST + kk * 16) * 2));
                mma16(sacc[2 * nj], qa[kk], r4);
                mma16(sacc[2 * nj + 1], qa[kk], r4 + 2);
            }
        }
        float rm0 = -1e30f, rm1 = -1e30f;
#pragma unroll
        for (int b = 0; b < 8; b++) {
            rm0 = fmaxf(rm0, fmaxf(sacc[b][0], sacc[b][1]));
            rm1 = fmaxf(rm1, fmaxf(sacc[b][2], sacc[b][3]));
        }
        rm0 = fmaxf(rm0, __shfl_xor_sync(0xffffffffu, rm0, 1));
        rm0 = fmaxf(rm0, __shfl_xor_sync(0xffffffffu, rm0, 2));
        rm1 = fmaxf(rm1, __shfl_xor_sync(0xffffffffu, rm1, 1));
        rm1 = fmaxf(rm1, __shfl_xor_sync(0xffffffffu, rm1, 2));
        float mn0 = fmaxf(m0, rm0 * scale);
        float mn1 = fmaxf(m1, rm1 * scale);
        float cr0 = expf(m0 - mn0), cr1 = expf(m1 - mn1);
        float ps0 = 0.f, ps1 = 0.f;
        uint32_t ph[8][2];
#pragma unroll
        for (int b = 0; b < 8; b++) {
            float p00 = expf(sacc[b][0] * scale - mn0);
            float p01 = expf(sacc[b][1] * scale - mn0);
            float p10 = expf(sacc[b][2] * scale - mn1);
            float p11 = expf(sacc[b][3] * scale - mn1);
            ps0 += p00 + p01; ps1 += p10 + p11;
            __half2 h0 = __floats2half2_rn(p00, p01);
            __half2 h1 = __floats2half2_rn(p10, p11);
            ph[b][0] = *(uint32_t*)&h0;
            ph[b][1] = *(uint32_t*)&h1;
        }
        ps0 += __shfl_xor_sync(0xffffffffu, ps0, 1);
        ps0 += __shfl_xor_sync(0xffffffffu, ps0, 2);
        ps1 += __shfl_xor_sync(0xffffffffu, ps1, 1);
        ps1 += __shfl_xor_sync(0xffffffffu, ps1, 2);
        l0 = l0 * cr0 + ps0; l1 = l1 * cr1 + ps1;
        m0 = mn0; m1 = mn1;
#pragma unroll
        for (int b = 0; b < 8; b++) {
            oacc[b][0] *= cr0; oacc[b][1] *= cr0;
            oacc[b][2] *= cr1; oacc[b][3] *= cr1;
        }
#pragma unroll
        for (int kk2 = 0; kk2 < 4; kk2++) {
            uint32_t pa[4] = { ph[2 * kk2][0], ph[2 * kk2][1], ph[2 * kk2 + 1][0], ph[2 * kk2 + 1][1] };
#pragma unroll
            for (int nj = 0; nj < 4; nj++) {
                uint32_t r4[4];
                ldsm4(r4, vb + bOff + (uint32_t)((nj * 16 * FST + kk2 * 16) * 2));
                mma16(oacc[2 * nj], pa, r4);
                mma16(oacc[2 * nj + 1], pa, r4 + 2);
            }
        }
        __syncthreads();
        int jn = j + 2;
        if (jn < NTOK / 64) issueKV(jn & 1, jn * 64);
        asm volatile("cp.async.commit_group;" ::: "memory");
        asm volatile("cp.async.wait_group 1;" ::: "memory");
        __syncthreads();
    }

    float inv0 = 1.f / l0, inv1 = 1.f / l1;
    int row0 = q0 + w * 16 + (l >> 2);
    __half* outp = saOut + (long long)e * ND_ELEMS + h * DHEAD;
#pragma unroll
    for (int b = 0; b < 8; b++) {
        int col = b * 8 + (l & 3) * 2;
        *(__half2*)&outp[(long long)row0 * DIM + col] =
            __floats2half2_rn(oacc[b][0] * inv0, oacc[b][1] * inv0);
        *(__half2*)&outp[(long long)(row0 + 8) * DIM + col] =
            __floats2half2_rn(oacc[b][2] * inv1, oacc[b][3] * inv1);
    }
}

// ---------------- reductions ----------------
__device__ __forceinline__ float warpReduceSum(float v) {
#pragma unroll
    for (int o = 16; o; o >>= 1) v += __shfl_xor_sync(0xffffffffu, v, o);
    return v;
}

// ---------------- LayerNorm ----------------
__global__ void ln_k(const float* __restrict__ src, __half* __restrict__ dst) {
    long long row = blockIdx.x;
    const float4* x = (const float4*)(src + row * DIM);
    __half2* y = (__half2*)(dst + row * DIM);
    int tid = threadIdx.x, lane = tid & 31, wid = tid >> 5;
    float4 v = x[tid];
    float s = v.x + v.y + v.z + v.w;
    float s2 = v.x * v.x + v.y * v.y + v.z * v.z + v.w * v.w;
    s = warpReduceSum(s); s2 = warpReduceSum(s2);
    __shared__ float sh[2][4]; __shared__ float mv[2];
    if (lane == 0) { sh[0][wid] = s; sh[1][wid] = s2; }
    __syncthreads();
    if (tid == 0) {
        float a = sh[0][0] + sh[0][1] + sh[0][2] + sh[0][3];
        float b = sh[1][0] + sh[1][1] + sh[1][2] + sh[1][3];
        float mean = a / DIM;
        mv[0] = mean; mv[1] = rsqrtf(b / DIM - mean * mean + 1e-5f);
    }
    __syncthreads();
    float mean = mv[0], rstd = mv[1];
    y[2 * tid] = __floats2half2_rn((v.x - mean) * rstd, (v.y - mean) * rstd);
    y[2 * tid + 1] = __floats2half2_rn((v.z - mean) * rstd, (v.w - mean) * rstd);
}

template <int AH>
__global__ void ln_ra_k(const void* __restrict__ av, const float* __restrict__ b,
                        const float* __restrict__ wAll, const float* __restrict__ bAll,
                        float* __restrict__ dst, __half* __restrict__ dstr) {
    long long row = blockIdx.x;
    int e = (int)(row >> 11);
    const float4* xb = (const float4*)(b + row * DIM);
    const float4* w = (const float4*)(wAll + (long long)e * DIM);
    const float4* bb = (const float4*)(bAll + (long long)e * DIM);
    float4* y = (float4*)(dst + row * DIM);
    __half2* yr = (__half2*)(dstr + row * DIM);
    int tid = threadIdx.x, lane = tid & 31, wid = tid >> 5;
    float4 va;
    if (AH) {
        const __half2* xa = (const __half2*)((const __half*)av + row * DIM);
        float2 p0 = __half22float2(xa[2 * tid]), p1 = __half22float2(xa[2 * tid + 1]);
        va = make_float4(p0.x, p0.y, p1.x, p1.y);
    } else {
        va = ((const float4*)((const float*)av + row * DIM))[tid];
    }
    float4 vb = xb[tid];
    float4 v = make_float4(va.x + vb.x, va.y + vb.y, va.z + vb.z, va.w + vb.w);
    float s = v.x + v.y + v.z + v.w;
    float s2 = v.x * v.x + v.y * v.y + v.z * v.z + v.w * v.w;
    s = warpReduceSum(s); s2 = warpReduceSum(s2);
    __shared__ float sh[2][4]; __shared__ float mv[2];
    if (lane == 0) { sh[0][wid] = s; sh[1][wid] = s2; }
    __syncthreads();
    if (tid == 0) {
        float p = sh[0][0] + sh[0][1] + sh[0][2] + sh[0][3];
        float q = sh[1][0] + sh[1][1] + sh[1][2] + sh[1][3];
        float mean = p / DIM;
        mv[0] = mean; mv[1] = rsqrtf(q / DIM - mean * mean + 1e-5f);
    }
    __syncthreads();
    float mean = mv[0], rstd = mv[1];
    float4 ww = w[tid], bbv = bb[tid];
    float4 o = make_float4((v.x - mean) * rstd * ww.x + bbv.x,
                           (v.y - mean) * rstd * ww.y + bbv.y,
                           (v.z - mean) * rstd * ww.z + bbv.z,
                           (v.w - mean) * rstd * ww.w + bbv.w);
    y[tid] = o;
    yr[2 * tid] = __floats2half2_rn(o.x, o.y);
    yr[2 * tid + 1] = __floats2half2_rn(o.z, o.w);
}

__global__ void permute_k(const float4* __restrict__ retr, __half2* __restrict__ rp) {
    long long i = (long long)blockIdx.x * 256 + threadIdx.x;
    constexpr int D4 = DIM / 4;
    if (i < (long long)EXP * NL * NTOK * D4) {
        int d4 = (int)(i & (D4 - 1));
        long long r = i >> 7;
        int n = (int)(r & (NTOK - 1));
        long long r2 = r >> 11;
        int lay = (int)(r2 & (NL - 1));
        long long e = r2 >> 2;
        float4 v = retr[i];
        long long o = (((e * NTOK + n) * NL + lay) * D4 + d4) * 2;
        rp[o] = __floats2half2_rn(v.x, v.y);
        rp[o + 1] = __floats2half2_rn(v.z, v.w);
    }
}

__global__ void zero_k(float* __restrict__ p, long long n) {
    long long i = (long long)blockIdx.x * 256 + threadIdx.x;
    if (i < n) p[i] = 0.f;
}

__global__ void gate_dot_k(const float* __restrict__ outs, const float* __restrict__ gg,
                           float* __restrict__ glog) {
    int e = blockIdx.x;
    constexpr int D4 = DIM / 4;
    long long chunk4 = (long long)(ND_ELEMS / 4) / gridDim.y;
    const float4* base = (const float4*)(outs) + (long long)e * (ND_ELEMS / 4) + (long long)blockIdx.y * chunk4;
    const float4* gg4 = (const float4*)gg;
    float acc = 0.f;
    for (long long i = threadIdx.x; i < chunk4; i += blockDim.x) {
        float4 v = base[i];
        float4 g = gg4[i & (D4 - 1)];
        acc += v.x * g.x + v.y * g.y + v.z * g.z + v.w * g.w;
    }
    acc = warpReduceSum(acc);
    __shared__ float sh[8];
    int lane = threadIdx.x & 31, wid = threadIdx.x >> 5;
    if (lane == 0) sh[wid] = acc;
    __syncthreads();
    if (threadIdx.x == 0) {
        float x = 0;
        for (int q = 0; q < 8; q++) x += sh[q];
        atomicAdd(&glog[e], x);
    }
}

__global__ void gate_softmax_k(const float* __restrict__ glog, float* __restrict__ gw) {
    if (threadIdx.x == 0) {
        float l[EXP], m = -1e30f;
        for (int e = 0; e < EXP; e++) {
            l[e] = fminf(fmaxf(glog[e] / (float)NTOK, -10.f), 10.f);
            m = fmaxf(m, l[e]);
        }
        float s = 0.f;
        for (int e = 0; e < EXP; e++) { l[e] = expf(l[e] - m); s += l[e]; }
        for (int e = 0; e < EXP; e++) gw[e] = l[e] / s;
    }
}

__global__ void fuse_k(const float4* __restrict__ outs, const float* __restrict__ gw,
                       float4* __restrict__ fused) {
    long long i = (long long)blockIdx.x * 256 + threadIdx.x;
    constexpr long long N4 = ND_ELEMS / 4;
    if (i < N4) {
        float4 r = make_float4(0.f, 0.f, 0.f, 0.f);
#pragma unroll
        for (int e = 0; e < EXP; e++) {
            float4 v = outs[(long long)e * N4 + i];
            float gwe = gw[e];
            r.x += gwe * v.x; r.y += gwe * v.y; r.z += gwe * v.z; r.w += gwe * v.w;
        }
        fused[i] = r;
    }
}

__global__ void memupd_k(const float4* __restrict__ mem, const float4* __restrict__ upd4,
                         float4* __restrict__ o) {
    long long i = (long long)blockIdx.x * 256 + threadIdx.x;
    constexpr long long N4 = (long long)LMD_ELEMS / 4;
    if (i < N4) {
        float4 u = upd4[i];
#pragma unroll
        for (int e = 1; e < EXP; e++) {
            float4 v = upd4[(long long)e * N4 + i];
            u.x += v.x; u.y += v.y; u.z += v.z; u.w += v.w;
        }
        float4 mm = mem[i];
        float4 r;
        r.x = 0.9f * mm.x + fminf(fmaxf(0.1f * u.x, -0.1f), 0.1f);
        r.y = 0.9f * mm.y + fminf(fmaxf(0.1f * u.y, -0.1f), 0.1f);
        r.z = 0.9f * mm.z + fminf(fmaxf(0.1f * u.z, -0.1f), 0.1f);
        r.w = 0.9f * mm.w + fminf(fmaxf(0.1f * u.w, -0.1f), 0.1f);
        o[i] = r;
    }
}

// ---------------- host ----------------
static constexpr int stgH(int MT, int NT, bool ATR) {
    return (ATR ? 32 * (MT + 8) : MT * 40) + NT * 40;
}
#define SMEMH(MT, NT, ATR) (4 * stgH(MT, NT, ATR) * 2)

static void tohalf(const float* s, __half* d, long long n) {
    long long n4 = n / 4;
    tohalf_k<<<(int)((n4 + 255) / 256), 256>>>((const float4*)s, (__half2*)d, n4);
}

extern "C" void kernel_launch(void* const* d_in, const int* in_sizes, int n_in,
                              void* d_out, int out_size) {
    const float* tokens   = (const float*)d_in[0];
    const float* memories = (const float*)d_in[1];
    const float* ipw      = (const float*)d_in[2];
    const float* ipb      = (const float*)d_in[3];
    const float* opw      = (const float*)d_in[4];
    const float* opb      = (const float*)d_in[5];
    const float* w1       = (const float*)d_in[6];
    const float* b1       = (const float*)d_in[7];
    const float* w2       = (const float*)d_in[8];
    const float* b2       = (const float*)d_in[9];
    const float* n1w      = (const float*)d_in[10];
    const float* n1b      = (const float*)d_in[11];
    const float* n2w      = (const float*)d_in[12];
    const float* n2b      = (const float*)d_in[13];
    const float* aggw     = (const float*)d_in[14];
    const float* aggb     = (const float*)d_in[15];
    const float* gg       = (const float*)d_in[16];

    float* out = (float*)d_out;
    float* out_fused = out;
    float* out_gw = out + ND_ELEMS;
    float* out_mem = out + ND_ELEMS + EXP;

    static __half *h_xln = nullptr, *h_xlnT = nullptr, *h_x4 = nullptr, *h_qkv = nullptr,
                  *h_big = nullptr, *h_sa = nullptr, *h_x1r = nullptr, *h_xor = nullptr,
                  *h_xorT = nullptr, *h_xorS = nullptr, *h_vT = nullptr, *h_tmp = nullptr,
                  *h_retrp = nullptr, *h_ipw = nullptr, *h_opw = nullptr, *h_w1 = nullptr,
                  *h_w2 = nullptr, *h_aggw = nullptr, *h_mem = nullptr, *h_memT = nullptr;
    static float *p_op4 = nullptr, *p_x14 = nullptr, *p_out = nullptr,
                 *p_retr4 = nullptr, *p_upd4 = nullptr, *p_glog = nullptr, *p_rsum = nullptr;
    if (!h_xln) {
        cudaGetSymbolAddress((void**)&h_xln, gh_xln);
        cudaGetSymbolAddress((void**)&h_xlnT, gh_xlnT);
        cudaGetSymbolAddress((void**)&h_x4, gh_x4);
        cudaGetSymbolAddress((void**)&h_qkv, gh_qkv);
        cudaGetSymbolAddress((void**)&h_big, gh_big);
        cudaGetSymbolAddress((void**)&h_sa, gh_sa);
        cudaGetSymbolAddress((void**)&h_x1r, gh_x1r);
        cudaGetSymbolAddress((void**)&h_xor, gh_xor);
        cudaGetSymbolAddress((void**)&h_xorT, gh_xorT);
        cudaGetSymbolAddress((void**)&h_xorS, gh_xorS);
        cudaGetSymbolAddress((void**)&h_vT, gh_vT);
        cudaGetSymbolAddress((void**)&h_tmp, gh_tmp);
        cudaGetSymbolAddress((void**)&h_retrp, gh_retrp);
        cudaGetSymbolAddress((void**)&h_ipw, gh_ipw);
        cudaGetSymbolAddress((void**)&h_opw, gh_opw);
        cudaGetSymbolAddress((void**)&h_w1, gh_w1);
        cudaGetSymbolAddress((void**)&h_w2, gh_w2);
        cudaGetSymbolAddress((void**)&h_aggw, gh_aggw);
        cudaGetSymbolAddress((void**)&h_mem, gh_mem);
        cudaGetSymbolAddress((void**)&h_memT, gh_memT);
        cudaGetSymbolAddress((void**)&p_op4, g_op4);
        cudaGetSymbolAddress((void**)&p_x14, g_x14);
        cudaGetSymbolAddress((void**)&p_out, g_out);
        cudaGetSymbolAddress((void**)&p_retr4, g_retr4);
        cudaGetSymbolAddress((void**)&p_upd4, g_upd4);
        cudaGetSymbolAddress((void**)&p_glog, g_glog);
        cudaGetSymbolAddress((void**)&p_rsum, g_rsum);
        cudaFuncSetAttribute(gemmH<64, 128, false, 1, 0>, cudaFuncAttributeMaxDynamicSharedMemorySize, SMEMH(64, 128, false));
        cudaFuncSetAttribute(gemmH<64, 128, false, 1, 1>, cudaFuncAttributeMaxDynamicSharedMemorySize, SMEMH(64, 128, false));
        cudaFuncSetAttribute(gemmH<64, 128, false, 0, 0>, cudaFuncAttributeMaxDynamicSharedMemorySize, SMEMH(64, 128, false));
        cudaFuncSetAttribute(gemmH<64, 128, true, 0, 0>,  cudaFuncAttributeMaxDynamicSharedMemorySize, SMEMH(64, 128, true));
    }

    const float inv_sqrt_d = 1.0f / sqrtf((float)DIM);

    const long long LLND = ND_ELEMS;
    const long long QKVE = (long long)NTOK * 3 * DIM;
    float* rsumC = p_rsum;                      // [EXP][NTOK]
    float* rsumM = p_rsum + EXP * NTOK;         // [EXP*NL][NTOK]

    // launches 1-5 (6th = cross GEMM for ncu)
    zero_k<<<1, 256>>>(p_glog, EXP);
    zero_k<<<((EXP + EXP * NL) * NTOK + 255) / 256, 256>>>(p_rsum, (EXP + EXP * NL) * NTOK);
    ln_k<<<EXP * NTOK, 128>>>(tokens, h_xln);
    transpose_h<<<dim3(DIM / 32, EXP * NTOK / 32, 1), dim3(32, 8)>>>(
        h_xln, h_xlnT, EXP * NTOK, DIM, DIM, 0, 0);
    tohalf(ipw, h_ipw, (long long)EXP * 3 * DIM * DIM);

    // 1. cross logits -> exp(clip(.)) fp16 + rowsum   <- 6th launch
    gemmH<64, 128, false, 1, 0><<<dim3(48, 32, EXP), 256, SMEMH(64, 128, false)>>>(
        h_xln, h_xln, h_big, DIM, DIM, DIM, 3 * NTOK,
        LLND, 0, 0, 0, (long long)NTOK * 3 * NTOK, 0, 1,
        inv_sqrt_d, nullptr, 0, nullptr, 0, 0, 10.f, GFLAG_EXPOUT, -1, NTOK,
        rsumC, NTOK);

    tohalf(opw, h_opw, (long long)EXP * DIM * DIM);
    tohalf(w1, h_w1, (long long)EXP * FFD * DIM);
    tohalf(w2, h_w2, (long long)EXP * DIM * FFD);
    tohalf(aggw, h_aggw, (long long)DIM * NL * DIM);
    tohalf(memories, h_mem, (long long)LMD_ELEMS);
    transpose_fh<<<dim3(DIM / 32, MEMSZ / 32, NL), dim3(32, 8)>>>(
        memories, h_memT, MEMSZ, DIM, DIM, (long long)MEMSZ * DIM, (long long)MEMSZ * DIM);

    // 2. x = (expbig @ ctx)/rowsum + xln
    gemmH<64, 128, false, 1, 1><<<dim3(4, 32, EXP), 256, SMEMH(64, 128, false)>>>(
        h_big, h_xlnT, h_x4, 3 * NTOK, 3 * NTOK, EXP * NTOK, DIM,
        (long long)NTOK * 3 * NTOK, 0, 0, 0, LLND, 0, 1,
        1.f, nullptr, 0, h_xln, LLND, DIM, 0.f, GFLAG_KREMAP | GFLAG_RSCALE, -1, NTOK,
        rsumC, NTOK);
    // 3. qkv fp16
    gemmH<64, 128, false, 1, 0><<<dim3(12, 32, EXP), 256, SMEMH(64, 128, false)>>>(
        h_x4, h_ipw, h_qkv, DIM, DIM, DIM, 3 * DIM,
        LLND, 0, (long long)3 * DIM * DIM, 0, QKVE, 0, 1,
        1.f, ipb, 3 * DIM, nullptr, 0, 0, 0.f, 0, 0, 0, nullptr, 0);
    transpose_h<<<dim3(DIM / 32, NTOK / 32, EXP), dim3(32, 8)>>>(
        h_qkv + 2 * DIM, h_vT, NTOK, DIM, 3 * DIM, QKVE, LLND);
    // 4+5. flash attention
    flash_k<<<dim3(NTOK / 64, EXP * NH), 128>>>(h_qkv, h_vT, h_sa);
    // 6. out_proj fp32 out
    gemmH<64, 128, false, 0, 0><<<dim3(4, 32, EXP), 256, SMEMH(64, 128, false)>>>(
        h_sa, h_opw, p_op4, DIM, DIM, DIM, DIM,
        LLND, 0, (long long)DIM * DIM, 0, LLND, 0, 1,
        1.f, opb, DIM, nullptr, 0, 0, 0.f, 0, 0, 0, nullptr, 0);
    ln_ra_k<1><<<EXP * NTOK, 128>>>(h_x4, p_op4, n1w, n1b, p_x14, h_x1r);
    // 7. ff1 relu fp16
    gemmH<64, 128, false, 1, 0><<<dim3(16, 32, EXP), 256, SMEMH(64, 128, false)>>>(
        h_x1r, h_w1, h_tmp, DIM, DIM, DIM, FFD,
        LLND, 0, (long long)FFD * DIM, 0, (long long)NTOK * FFD, 0, 1,
        1.f, b1, FFD, nullptr, 0, 0, 0.f, GFLAG_RELU, 0, 0, nullptr, 0);
    // 8. ff2 fp32 out
    gemmH<64, 128, false, 0, 0><<<dim3(4, 32, EXP), 256, SMEMH(64, 128, false)>>>(
        h_tmp, h_w2, p_op4, FFD, FFD, FFD, DIM,
        (long long)NTOK * FFD, 0, (long long)DIM * FFD, 0, LLND, 0, 1,
        1.f, b2, DIM, nullptr, 0, 0, 0.f, 0, 0, 0, nullptr, 0);
    ln_ra_k<0><<<EXP * NTOK, 128>>>(p_x14, p_op4, n2w, n2b, p_out, h_xor);
    transpose_h<<<dim3(DIM / 32, NTOK / 32, EXP), dim3(32, 8)>>>(
        h_xor, h_xorT, NTOK, DIM, DIM, LLND, LLND);
    // 9. memory logits -> exp(clip(.)) fp16 + rowsum
    gemmH<64, 128, false, 1, 0><<<dim3(32, 32, EXP * NL), 256, SMEMH(64, 128, false)>>>(
        h_xor, h_mem, h_big, DIM, DIM, DIM, MEMSZ,
        LLND, 0, 0, (long long)MEMSZ * DIM, (long long)NL * NTOK * MEMSZ, (long long)NTOK * MEMSZ, NL,
        inv_sqrt_d, nullptr, 0, nullptr, 0, 0, 10.f, GFLAG_EXPOUT, 0, 0,
        rsumM, NTOK);
    // 9b. xorS = xorT * 4096/rowsum (per layer)
    scalexor_k<<<(int)(((long long)EXP * NL * DIM * (NTOK / 2) + 255) / 256), 256>>>(
        (const __half2*)h_xorT, rsumM, (__half2*)h_xorS);
    // 10. retr = (expbig @ memT)/rowsum, fp32 out
    gemmH<64, 128, false, 0, 0><<<dim3(4, 32, EXP * NL), 256, SMEMH(64, 128, false)>>>(
        h_big, h_memT, p_retr4, MEMSZ, MEMSZ, MEMSZ, DIM,
        (long long)NL * NTOK * MEMSZ, (long long)NTOK * MEMSZ, 0, (long long)MEMSZ * DIM,
        (long long)NL * NTOK * DIM, (long long)NTOK * DIM, NL,
        1.f, nullptr, 0, nullptr, 0, 0, 0.f, GFLAG_RSCALE, 0, 0,
        rsumM, NTOK);
    // 11. upd = clip((expbig^T @ xorS)/4096, 1), fp32 out
    gemmH<64, 128, true, 0, 0><<<dim3(4, 64, EXP * NL), 256, SMEMH(64, 128, true)>>>(
        h_big, h_xorS, p_upd4, NTOK, MEMSZ, NTOK, DIM,
        (long long)NL * NTOK * MEMSZ, (long long)NTOK * MEMSZ,
        (long long)NL * LLND, LLND,
        (long long)LMD_ELEMS, (long long)MEMSZ * DIM, NL,
        1.f / 4096.f, nullptr, 0, nullptr, 0, 0, 1.f, 0, 0, 0, nullptr, 0);
    permute_k<<<(EXP * NL * ND_ELEMS / 4 + 255) / 256, 256>>>((const float4*)p_retr4, (__half2*)h_retrp);
    // 12. outs += retrp @ aggw^T + aggb
    gemmH<64, 128, false, 0, 0><<<dim3(4, 32, EXP), 256, SMEMH(64, 128, false)>>>(
        h_retrp, h_aggw, p_out, NL * DIM, NL * DIM, NL * DIM, DIM,
        (long long)NTOK * NL * DIM, 0, 0, 0, LLND, 0, 1,
        1.f, aggb, 0, p_out, LLND, DIM, 0.f, 0, 0, 0, nullptr, 0);

    dim3 ggrid(EXP, 16);
    gate_dot_k<<<ggrid, 256>>>(p_out, gg, p_glog);
    gate_softmax_k<<<1, 32>>>(p_glog, out_gw);
    fuse_k<<<(ND_ELEMS / 4 + 255) / 256, 256>>>((const float4*)p_out, out_gw, (float4*)out_fused);
    memupd_k<<<(LMD_ELEMS / 4 + 255) / 256, 256>>>((const float4*)memories, (const float4*)p_upd4, (float4*)out_mem);

    (void)in_sizes; (void)n_in; (void)out_size;
}

// round 17
// speedup vs baseline: 3.4182x; 1.1052x over previous
#include <cuda_runtime.h>
#include <cuda_fp16.h>
#include <math.h>
#include <stdint.h>

#define EXP 4
#define NTOK 2048
#define DIM 512
#define NH 8
#define DHEAD 64
#define FFD 2048
#define NL 4
#define MEMSZ 4096

#define ND_ELEMS (NTOK * DIM)
#define LMD_ELEMS (NL * MEMSZ * DIM)

#define GFLAG_RELU 1
#define GFLAG_KREMAP 2
#define GFLAG_EXPOUT 4
#define GFLAG_RSCALE 8

// ---------------- scratch ----------------
__device__ __half gh_xln[EXP * NTOK * DIM];
__device__ __half gh_xlnT[EXP * NTOK * DIM];
__device__ __half gh_x4[EXP * NTOK * DIM];
__device__ __half gh_qkv[(size_t)EXP * NTOK * 3 * DIM];
__device__ __half gh_big[(size_t)EXP * NH * NTOK * NTOK];
__device__ __half gh_sa[EXP * NTOK * DIM];
__device__ __half gh_x1r[EXP * NTOK * DIM];
__device__ __half gh_xor[EXP * NTOK * DIM];
__device__ __half gh_xorT[EXP * NTOK * DIM];
__device__ __half gh_xorS[(size_t)EXP * NL * NTOK * DIM];
__device__ __half gh_vT[(size_t)EXP * NTOK * DIM];
__device__ __half gh_tmp[(size_t)EXP * NTOK * FFD];
__device__ __half gh_retrp[(size_t)EXP * NTOK * NL * DIM];
__device__ __half gh_ipw[EXP * 3 * DIM * DIM];
__device__ __half gh_opw[EXP * DIM * DIM];
__device__ __half gh_w1[EXP * FFD * DIM];
__device__ __half gh_w2[EXP * DIM * FFD];
__device__ __half gh_aggw[DIM * NL * DIM];
__device__ __half gh_mem[LMD_ELEMS];
__device__ __half gh_memT[LMD_ELEMS];
__device__ float g_op4[EXP * NTOK * DIM];
__device__ float g_x14[EXP * NTOK * DIM];
__device__ float g_out[EXP * NTOK * DIM];
__device__ float g_retr4[(size_t)EXP * NL * NTOK * DIM];
__device__ float g_upd4[(size_t)EXP * NL * MEMSZ * DIM];
__device__ float g_glog[EXP];
__device__ float g_rsum[(EXP + EXP * NL) * NTOK];

// ---------------- helpers ----------------
__device__ __forceinline__ void mma16(float* c, const uint32_t* a, const uint32_t* b) {
    asm volatile(
        "mma.sync.aligned.m16n8k16.row.col.f32.f16.f16.f32 "
        "{%0,%1,%2,%3}, {%4,%5,%6,%7}, {%8,%9}, {%0,%1,%2,%3};"
        : "+f"(c[0]), "+f"(c[1]), "+f"(c[2]), "+f"(c[3])
        : "r"(a[0]), "r"(a[1]), "r"(a[2]), "r"(a[3]), "r"(b[0]), "r"(b[1]));
}
__device__ __forceinline__ void cpa16(uint32_t s, const void* g) {
    asm volatile("cp.async.cg.shared.global [%0], [%1], 16;" :: "r"(s), "l"(g));
}
__device__ __forceinline__ void ldsm4(uint32_t* r, uint32_t a) {
    asm volatile("ldmatrix.sync.aligned.m8n8.x4.shared.b16 {%0,%1,%2,%3}, [%4];"
        : "=r"(r[0]), "=r"(r[1]), "=r"(r[2]), "=r"(r[3]) : "r"(a));
}
__device__ __forceinline__ void ldsm4t(uint32_t* r, uint32_t a) {
    asm volatile("ldmatrix.sync.aligned.m8n8.x4.trans.shared.b16 {%0,%1,%2,%3}, [%4];"
        : "=r"(r[0]), "=r"(r[1]), "=r"(r[2]), "=r"(r[3]) : "r"(a));
}

__global__ void tohalf_k(const float4* __restrict__ s, __half2* __restrict__ d, long long n4) {
    long long i = (long long)blockIdx.x * 256 + threadIdx.x;
    if (i < n4) {
        float4 v = s[i];
        d[2 * i] = __floats2half2_rn(v.x, v.y);
        d[2 * i + 1] = __floats2half2_rn(v.z, v.w);
    }
}

__global__ void transpose_h(const __half* __restrict__ in, __half* __restrict__ out,
                            int rows, int cols, int ldin, long long inB, long long outB) {
    __shared__ __half tile[32][38];
    int z = blockIdx.z;
    in += inB * z; out += outB * z;
    int c0 = blockIdx.x * 32, r0 = blockIdx.y * 32;
    int x = threadIdx.x, y = threadIdx.y;
#pragma unroll
    for (int j = 0; j < 32; j += 8)
        tile[y + j][x] = in[(long long)(r0 + y + j) * ldin + c0 + x];
    __syncthreads();
#pragma unroll
    for (int j = 0; j < 32; j += 8)
        out[(long long)(c0 + y + j) * rows + r0 + x] = tile[x][y + j];
}

__global__ void transpose_fh(const float* __restrict__ in, __half* __restrict__ out,
                             int rows, int cols, int ldin, long long inB, long long outB) {
    __shared__ float tile[32][33];
    int z = blockIdx.z;
    in += inB * z; out += outB * z;
    int c0 = blockIdx.x * 32, r0 = blockIdx.y * 32;
    int x = threadIdx.x, y = threadIdx.y;
#pragma unroll
    for (int j = 0; j < 32; j += 8)
        tile[y + j][x] = in[(long long)(r0 + y + j) * ldin + c0 + x];
    __syncthreads();
#pragma unroll
    for (int j = 0; j < 32; j += 8)
        out[(long long)(c0 + y + j) * rows + r0 + x] = __float2half_rn(tile[x][y + j]);
}

// xorS[e][l][d][n] = xorT[e][d][n] * 4096/rsumMem[(e*NL+l)*NTOK + n]
__global__ void scalexor_k(const __half2* __restrict__ xorT, const float* __restrict__ rsum,
                           __half2* __restrict__ xorS) {
    long long i = (long long)blockIdx.x * 256 + threadIdx.x;
    constexpr int N2 = NTOK / 2;
    if (i < (long long)EXP * NL * DIM * N2) {
        int n2 = (int)(i % N2);
        long long r = i / N2;
        int d = (int)(r % DIM);
        long long r2 = r / DIM;
        int l = (int)(r2 % NL);
        int e = (int)(r2 / NL);
        float2 f = __half22float2(xorT[((long long)e * DIM + d) * N2 + n2]);
        const float* rs = rsum + ((long long)e * NL + l) * NTOK + 2 * n2;
        xorS[i] = __floats2half2_rn(f.x * (4096.f / rs[0]), f.y * (4096.f / rs[1]));
    }
}

// ---------------- fp16 m16n8k16 cp.async GEMM ----------------
template <int MT, int NT, bool ATR, int OUTH, int RESH, int OCC>
__global__ void __launch_bounds__(256, OCC) gemmH(
    const __half* __restrict__ A, const __half* __restrict__ B, void* __restrict__ Cv,
    int K, int lda, int ldb, int ldc,
    long long aB, long long aBi, long long bB, long long bBi,
    long long cB, long long cBi, int zInner,
    float alpha, const float* __restrict__ bias, long long biasB,
    const void* __restrict__ residv, long long residB, int residLd,
    float clipVal, int flags, int rs, int rl,
    float* __restrict__ rowSum, long long rsStride)
{
    constexpr int KC = 32;
    constexpr int ASTh = 40;
    constexpr int MSTh = MT + 8;
    constexpr int ASZ = ATR ? KC * MSTh : MT * ASTh;
    constexpr int BSZ = NT * ASTh;
    constexpr int STG = ASZ + BSZ;
    constexpr int MI = MT / 32;
    constexpr int NB = NT / 32;

    extern __shared__ __half smh[];
    uint32_t smb = (uint32_t)__cvta_generic_to_shared(smh);

    const int t = threadIdx.x, l = t & 31, w = t >> 5;
    const int bz = blockIdx.z;
    const int zo = bz / zInner, zi = bz - zo * zInner;
    A += aB * zo + aBi * zi;
    B += bB * zo + bBi * zi;
    float* Cf = nullptr; __half* Ch = nullptr;
    if (OUTH) Ch = (__half*)Cv + cB * zo + cBi * zi;
    else      Cf = (float*)Cv + cB * zo + cBi * zi;
    if (bias) bias += biasB * zo;
    const float* residF = nullptr; const __half* residH = nullptr;
    if (residv) {
        if (RESH) residH = (const __half*)residv + residB * zo;
        else      residF = (const float*)residv + residB * zo;
    }
    if (rowSum) rowSum += rsStride * bz;
    if (rs < 0) rs = zo * rl;
    const int m0 = blockIdx.y * MT, n0 = blockIdx.x * NT;
    const int wm0 = (w >> 2) * (MT / 2), wn0 = (w & 3) * (NT / 4);
    const bool kRemap = (flags & GFLAG_KREMAP) != 0;

    const uint32_t aBase = (uint32_t)(((wm0 + ((l >> 3 & 1) << 3) + (l & 7)) * ASTh + ((l >> 4) << 3)) * 2);
    const uint32_t aBaseT = (uint32_t)(((((l >> 4) << 3) + (l & 7)) * MSTh + wm0 + ((l >> 3 & 1) << 3)) * 2);
    const uint32_t bBase = (uint32_t)(((wn0 + ((l >> 4) << 3) + (l & 7)) * ASTh + ((l >> 3 & 1) << 3)) * 2);

    float acc[MI][NB][4];
#pragma unroll
    for (int a = 0; a < MI; a++)
#pragma unroll
        for (int b = 0; b < NB; b++)
#pragma unroll
            for (int c = 0; c < 4; c++) acc[a][b][c] = 0.f;

    const int nK = K / KC;
    const int kmax = K - KC;

    auto issue = [&](int s, int k0) {
        uint32_t ab = smb + (uint32_t)(s * STG * 2);
        uint32_t bb = ab + (uint32_t)(ASZ * 2);
        if (!ATR) {
            constexpr int ACH = MT * 4;
#pragma unroll
            for (int c0 = 0; c0 < ACH; c0 += 256) {
                int c = c0 + t;
                int row = c >> 2, kq = (c & 3) * 8;
                cpa16(ab + (uint32_t)((row * ASTh + kq) * 2),
                      &A[(long long)(m0 + row) * lda + k0 + kq]);
            }
        } else {
            constexpr int ACH = KC * (MT / 8);
#pragma unroll
            for (int c0 = 0; c0 < ACH; c0 += 256) {
                int c = c0 + t;
                int kr = c / (MT / 8), mq = (c % (MT / 8)) * 8;
                cpa16(ab + (uint32_t)((kr * MSTh + mq) * 2),
                      &A[(long long)(k0 + kr) * lda + m0 + mq]);
            }
        }
        {
            constexpr int BCH = NT * 4;
#pragma unroll
            for (int c0 = 0; c0 < BCH; c0 += 256) {
                int c = c0 + t;
                int row = c >> 2, kq = (c & 3) * 8;
                int n = n0 + row;
                int g = k0 + kq;
                if (rl) {
                    if (kRemap) { if (g >= rs) g += rl; }
                    else { if (n >= rs) n += rl; }
                }
                cpa16(bb + (uint32_t)((row * ASTh + kq) * 2),
                      &B[(long long)n * ldb + g]);
            }
        }
        asm volatile("cp.async.commit_group;" ::: "memory");
    };

    issue(0, 0);
    if (KC <= kmax) issue(1, KC); else asm volatile("cp.async.commit_group;" ::: "memory");
    if (2 * KC <= kmax) issue(2, 2 * KC); else asm volatile("cp.async.commit_group;" ::: "memory");

    for (int i = 0; i < nK; i++) {
        asm volatile("cp.async.wait_group 2;" ::: "memory");
        __syncthreads();
        int pk = (i + 3) * KC;
        if (pk <= kmax) issue((i + 3) & 3, pk);
        else asm volatile("cp.async.commit_group;" ::: "memory");

        uint32_t abu = smb + (uint32_t)((i & 3) * STG * 2);
        uint32_t bbu = abu + (uint32_t)(ASZ * 2);
#pragma unroll
        for (int kk = 0; kk < 2; kk++) {
            uint32_t af[MI][4], bf[NB][2];
#pragma unroll
            for (int mi = 0; mi < MI; mi++) {
                if (!ATR)
                    ldsm4(af[mi], abu + aBase + (uint32_t)((mi * 16 * ASTh + kk * 16) * 2));
                else
                    ldsm4t(af[mi], abu + aBaseT + (uint32_t)((kk * 16 * MSTh + mi * 16) * 2));
            }
#pragma unroll
            for (int nj = 0; nj < NB / 2; nj++) {
                uint32_t r4[4];
                ldsm4(r4, bbu + bBase + (uint32_t)((nj * 16 * ASTh + kk * 16) * 2));
                bf[2 * nj][0] = r4[0]; bf[2 * nj][1] = r4[1];
                bf[2 * nj + 1][0] = r4[2]; bf[2 * nj + 1][1] = r4[3];
            }
#pragma unroll
            for (int mi = 0; mi < MI; mi++)
#pragma unroll
                for (int ni = 0; ni < NB; ni++) mma16(acc[mi][ni], af[mi], bf[ni]);
        }
    }

    // epilogue
    float rsAcc[MI][2];
#pragma unroll
    for (int a = 0; a < MI; a++) { rsAcc[a][0] = 0.f; rsAcc[a][1] = 0.f; }

#pragma unroll
    for (int mi = 0; mi < MI; mi++) {
        int row0 = m0 + wm0 + mi * 16 + (l >> 2);
        float sc0 = 1.f, sc1 = 1.f;
        if (flags & GFLAG_RSCALE) {
            sc0 = 1.f / rowSum[row0];
            sc1 = 1.f / rowSum[row0 + 8];
        }
#pragma unroll
        for (int ni = 0; ni < NB; ni++) {
            int col = n0 + wn0 + ni * 8 + (l & 3) * 2;
#pragma unroll
            for (int h = 0; h < 2; h++) {
                int row = row0 + h * 8;
                float vx = alpha * acc[mi][ni][h * 2];
                float vy = alpha * acc[mi][ni][h * 2 + 1];
                if (bias) { vx += bias[col]; vy += bias[col + 1]; }
                if (flags & GFLAG_RELU) { vx = fmaxf(vx, 0.f); vy = fmaxf(vy, 0.f); }
                if (clipVal > 0.f) {
                    vx = fminf(fmaxf(vx, -clipVal), clipVal);
                    vy = fminf(fmaxf(vy, -clipVal), clipVal);
                }
                if (flags & GFLAG_EXPOUT) {
                    vx = expf(vx); vy = expf(vy);
                    rsAcc[mi][h] += vx + vy;
                }
                if (flags & GFLAG_RSCALE) {
                    float sc = h ? sc1 : sc0;
                    vx *= sc; vy *= sc;
                }
                if (residv) {
                    if (RESH) {
                        float2 rv = __half22float2(*(const __half2*)&residH[(long long)row * residLd + col]);
                        vx += rv.x; vy += rv.y;
                    } else {
                        float2 rv = *(const float2*)&residF[(long long)row * residLd + col];
                        vx += rv.x; vy += rv.y;
                    }
                }
                if (OUTH) {
                    *(__half2*)&Ch[(long long)row * ldc + col] = __floats2half2_rn(vx, vy);
                } else {
                    *(float2*)&Cf[(long long)row * ldc + col] = make_float2(vx, vy);
                }
            }
        }
    }
    if (flags & GFLAG_EXPOUT) {
#pragma unroll
        for (int mi = 0; mi < MI; mi++)
#pragma unroll
            for (int h = 0; h < 2; h++) {
                float v = rsAcc[mi][h];
                v += __shfl_xor_sync(0xffffffffu, v, 1);
                v += __shfl_xor_sync(0xffffffffu, v, 2);
                if ((l & 3) == 0) {
                    int row = m0 + wm0 + mi * 16 + (l >> 2) + h * 8;
                    atomicAdd(&rowSum[row], v);
                }
            }
    }
}

// ---------------- flash attention ----------------
#define FST 72
__global__ void __launch_bounds__(128) flash_k(
    const __half* __restrict__ qkv, const __half* __restrict__ vT,
    __half* __restrict__ saOut)
{
    __shared__ __half sQ[64 * FST];
    __shared__ __half sK[2][64 * FST];
    __shared__ __half sV[2][64 * FST];

    const int t = threadIdx.x, l = t & 31, w = t >> 5;
    const int q0 = blockIdx.x * 64;
    const int z = blockIdx.y;
    const int e = z >> 3, h = z & 7;

    const __half* Qg = qkv + (long long)e * (NTOK * 3 * DIM) + h * DHEAD;
    const __half* Kg = Qg + DIM;
    const __half* Vg = vT + (long long)e * ND_ELEMS + (long long)(h * DHEAD) * NTOK;

    uint32_t sQb = (uint32_t)__cvta_generic_to_shared(sQ);
    uint32_t sKb = (uint32_t)__cvta_generic_to_shared(sK);
    uint32_t sVb = (uint32_t)__cvta_generic_to_shared(sV);

    auto issueKV = [&](int buf, int kv0) {
#pragma unroll
        for (int c0 = 0; c0 < 512; c0 += 128) {
            int c = c0 + t;
            int row = c >> 3, ch = (c & 7) * 8;
            cpa16(sKb + (uint32_t)((buf * 64 * FST + row * FST + ch) * 2),
                  Kg + (long long)(kv0 + row) * (3 * DIM) + ch);
        }
#pragma unroll
        for (int c0 = 0; c0 < 512; c0 += 128) {
            int c = c0 + t;
            int row = c >> 3, ch = (c & 7) * 8;
            cpa16(sVb + (uint32_t)((buf * 64 * FST + row * FST + ch) * 2),
                  Vg + (long long)row * NTOK + kv0 + ch);
        }
    };

    {
#pragma unroll
        for (int c0 = 0; c0 < 512; c0 += 128) {
            int c = c0 + t;
            int row = c >> 3, ch = (c & 7) * 8;
            cpa16(sQb + (uint32_t)((row * FST + ch) * 2),
                  Qg + (long long)(q0 + row) * (3 * DIM) + ch);
        }
        issueKV(0, 0);
        asm volatile("cp.async.commit_group;" ::: "memory");
        issueKV(1, 64);
        asm volatile("cp.async.commit_group;" ::: "memory");
        asm volatile("cp.async.wait_group 1;" ::: "memory");
        __syncthreads();
    }

    const uint32_t aOff = (uint32_t)(((w * 16 + ((l >> 3 & 1) << 3) + (l & 7)) * FST + ((l >> 4) << 3)) * 2);
    const uint32_t bOff = (uint32_t)(((((l >> 4) << 3) + (l & 7)) * FST + ((l >> 3 & 1) << 3)) * 2);

    uint32_t qa[4][4];
#pragma unroll
    for (int kk = 0; kk < 4; kk++) ldsm4(qa[kk], sQb + aOff + kk * 32);

    float oacc[8][4];
#pragma unroll
    for (int b = 0; b < 8; b++)
#pragma unroll
        for (int c = 0; c < 4; c++) oacc[b][c] = 0.f;
    float m0 = -1e30f, m1 = -1e30f, l0 = 0.f, l1 = 0.f;
    const float scale = 0.125f;

    for (int j = 0; j < NTOK / 64; j++) {
        uint32_t kb = sKb + (uint32_t)((j & 1) * 64 * FST * 2);
        uint32_t vb = sVb + (uint32_t)((j & 1) * 64 * FST * 2);

        float sacc[8][4];
#pragma unroll
        for (int b = 0; b < 8; b++)
#pragma unroll
            for (int c = 0; c < 4; c++) sacc[b][c] = 0.f;
#pragma unroll
        for (int kk = 0; kk < 4; kk++) {
#pragma unroll
            for (int nj = 0; nj < 4; nj++) {
                uint32_t r4[4];
                ldsm4(r4, kb + bOff + (uint32_t)((nj * 16 * FST + kk * 16) * 2));
                mma16(sacc[2 * nj], qa[kk], r4);
                mma16(sacc[2 * nj + 1], qa[kk], r4 + 2);
            }
        }
        float rm0 = -1e30f, rm1 = -1e30f;
#pragma unroll
        for (int b = 0; b < 8; b++) {
            rm0 = fmaxf(rm0, fmaxf(sacc[b][0], sacc[b][1]));
            rm1 = fmaxf(rm1, fmaxf(sacc[b][2], sacc[b][3]));
        }
        rm0 = fmaxf(rm0, __shfl_xor_sync(0xffffffffu, rm0, 1));
        rm0 = fmaxf(rm0, __shfl_xor_sync(0xffffffffu, rm0, 2));
        rm1 = fmaxf(rm1, __shfl_xor_sync(0xffffffffu, rm1, 1));
        rm1 = fmaxf(rm1, __shfl_xor_sync(0xffffffffu, rm1, 2));
        float mn0 = fmaxf(m0, rm0 * scale);
        float mn1 = fmaxf(m1, rm1 * scale);
        float cr0 = expf(m0 - mn0), cr1 = expf(m1 - mn1);
        float ps0 = 0.f, ps1 = 0.f;
        uint32_t ph[8][2];
#pragma unroll
        for (int b = 0; b < 8; b++) {
            float p00 = expf(sacc[b][0] * scale - mn0);
            float p01 = expf(sacc[b][1] * scale - mn0);
            float p10 = expf(sacc[b][2] * scale - mn1);
            float p11 = expf(sacc[b][3] * scale - mn1);
            ps0 += p00 + p01; ps1 += p10 + p11;
            __half2 h0 = __floats2half2_rn(p00, p01);
            __half2 h1 = __floats2half2_rn(p10, p11);
            ph[b][0] = *(uint32_t*)&h0;
            ph[b][1] = *(uint32_t*)&h1;
        }
        ps0 += __shfl_xor_sync(0xffffffffu, ps0, 1);
        ps0 += __shfl_xor_sync(0xffffffffu, ps0, 2);
        ps1 += __shfl_xor_sync(0xffffffffu, ps1, 1);
        ps1 += __shfl_xor_sync(0xffffffffu, ps1, 2);
        l0 = l0 * cr0 + ps0; l1 = l1 * cr1 + ps1;
        m0 = mn0; m1 = mn1;
#pragma unroll
        for (int b = 0; b < 8; b++) {
            oacc[b][0] *= cr0; oacc[b][1] *= cr0;
            oacc[b][2] *= cr1; oacc[b][3] *= cr1;
        }
#pragma unroll
        for (int kk2 = 0; kk2 < 4; kk2++) {
            uint32_t pa[4] = { ph[2 * kk2][0], ph[2 * kk2][1], ph[2 * kk2 + 1][0], ph[2 * kk2 + 1][1] };
#pragma unroll
            for (int nj = 0; nj < 4; nj++) {
                uint32_t r4[4];
                ldsm4(r4, vb + bOff + (uint32_t)((nj * 16 * FST + kk2 * 16) * 2));
                mma16(oacc[2 * nj], pa, r4);
                mma16(oacc[2 * nj + 1], pa, r4 + 2);
            }
        }
        __syncthreads();
        int jn = j + 2;
        if (jn < NTOK / 64) issueKV(jn & 1, jn * 64);
        asm volatile("cp.async.commit_group;" ::: "memory");
        asm volatile("cp.async.wait_group 1;" ::: "memory");
        __syncthreads();
    }

    float inv0 = 1.f / l0, inv1 = 1.f / l1;
    int row0 = q0 + w * 16 + (l >> 2);
    __half* outp = saOut + (long long)e * ND_ELEMS + h * DHEAD;
#pragma unroll
    for (int b = 0; b < 8; b++) {
        int col = b * 8 + (l & 3) * 2;
        *(__half2*)&outp[(long long)row0 * DIM + col] =
            __floats2half2_rn(oacc[b][0] * inv0, oacc[b][1] * inv0);
        *(__half2*)&outp[(long long)(row0 + 8) * DIM + col] =
            __floats2half2_rn(oacc[b][2] * inv1, oacc[b][3] * inv1);
    }
}

// ---------------- reductions ----------------
__device__ __forceinline__ float warpReduceSum(float v) {
#pragma unroll
    for (int o = 16; o; o >>= 1) v += __shfl_xor_sync(0xffffffffu, v, o);
    return v;
}

// ---------------- LayerNorm ----------------
__global__ void ln_k(const float* __restrict__ src, __half* __restrict__ dst) {
    long long row = blockIdx.x;
    const float4* x = (const float4*)(src + row * DIM);
    __half2* y = (__half2*)(dst + row * DIM);
    int tid = threadIdx.x, lane = tid & 31, wid = tid >> 5;
    float4 v = x[tid];
    float s = v.x + v.y + v.z + v.w;
    float s2 = v.x * v.x + v.y * v.y + v.z * v.z + v.w * v.w;
    s = warpReduceSum(s); s2 = warpReduceSum(s2);
    __shared__ float sh[2][4]; __shared__ float mv[2];
    if (lane == 0) { sh[0][wid] = s; sh[1][wid] = s2; }
    __syncthreads();
    if (tid == 0) {
        float a = sh[0][0] + sh[0][1] + sh[0][2] + sh[0][3];
        float b = sh[1][0] + sh[1][1] + sh[1][2] + sh[1][3];
        float mean = a / DIM;
        mv[0] = mean; mv[1] = rsqrtf(b / DIM - mean * mean + 1e-5f);
    }
    __syncthreads();
    float mean = mv[0], rstd = mv[1];
    y[2 * tid] = __floats2half2_rn((v.x - mean) * rstd, (v.y - mean) * rstd);
    y[2 * tid + 1] = __floats2half2_rn((v.z - mean) * rstd, (v.w - mean) * rstd);
}

template <int AH>
__global__ void ln_ra_k(const void* __restrict__ av, const float* __restrict__ b,
                        const float* __restrict__ wAll, const float* __restrict__ bAll,
                        float* __restrict__ dst, __half* __restrict__ dstr) {
    long long row = blockIdx.x;
    int e = (int)(row >> 11);
    const float4* xb = (const float4*)(b + row * DIM);
    const float4* w = (const float4*)(wAll + (long long)e * DIM);
    const float4* bb = (const float4*)(bAll + (long long)e * DIM);
    float4* y = (float4*)(dst + row * DIM);
    __half2* yr = (__half2*)(dstr + row * DIM);
    int tid = threadIdx.x, lane = tid & 31, wid = tid >> 5;
    float4 va;
    if (AH) {
        const __half2* xa = (const __half2*)((const __half*)av + row * DIM);
        float2 p0 = __half22float2(xa[2 * tid]), p1 = __half22float2(xa[2 * tid + 1]);
        va = make_float4(p0.x, p0.y, p1.x, p1.y);
    } else {
        va = ((const float4*)((const float*)av + row * DIM))[tid];
    }
    float4 vb = xb[tid];
    float4 v = make_float4(va.x + vb.x, va.y + vb.y, va.z + vb.z, va.w + vb.w);
    float s = v.x + v.y + v.z + v.w;
    float s2 = v.x * v.x + v.y * v.y + v.z * v.z + v.w * v.w;
    s = warpReduceSum(s); s2 = warpReduceSum(s2);
    __shared__ float sh[2][4]; __shared__ float mv[2];
    if (lane == 0) { sh[0][wid] = s; sh[1][wid] = s2; }
    __syncthreads();
    if (tid == 0) {
        float p = sh[0][0] + sh[0][1] + sh[0][2] + sh[0][3];
        float q = sh[1][0] + sh[1][1] + sh[1][2] + sh[1][3];
        float mean = p / DIM;
        mv[0] = mean; mv[1] = rsqrtf(q / DIM - mean * mean + 1e-5f);
    }
    __syncthreads();
    float mean = mv[0], rstd = mv[1];
    float4 ww = w[tid], bbv = bb[tid];
    float4 o = make_float4((v.x - mean) * rstd * ww.x + bbv.x,
                           (v.y - mean) * rstd * ww.y + bbv.y,
                           (v.z - mean) * rstd * ww.z + bbv.z,
                           (v.w - mean) * rstd * ww.w + bbv.w);
    y[tid] = o;
    yr[2 * tid] = __floats2half2_rn(o.x, o.y);
    yr[2 * tid + 1] = __floats2half2_rn(o.z, o.w);
}

__global__ void permute_k(const float4* __restrict__ retr, __half2* __restrict__ rp) {
    long long i = (long long)blockIdx.x * 256 + threadIdx.x;
    constexpr int D4 = DIM / 4;
    if (i < (long long)EXP * NL * NTOK * D4) {
        int d4 = (int)(i & (D4 - 1));
        long long r = i >> 7;
        int n = (int)(r & (NTOK - 1));
        long long r2 = r >> 11;
        int lay = (int)(r2 & (NL - 1));
        long long e = r2 >> 2;
        float4 v = retr[i];
        long long o = (((e * NTOK + n) * NL + lay) * D4 + d4) * 2;
        rp[o] = __floats2half2_rn(v.x, v.y);
        rp[o + 1] = __floats2half2_rn(v.z, v.w);
    }
}

__global__ void zero_k(float* __restrict__ p, long long n) {
    long long i = (long long)blockIdx.x * 256 + threadIdx.x;
    if (i < n) p[i] = 0.f;
}

__global__ void gate_dot_k(const float* __restrict__ outs, const float* __restrict__ gg,
                           float* __restrict__ glog) {
    int e = blockIdx.x;
    constexpr int D4 = DIM / 4;
    long long chunk4 = (long long)(ND_ELEMS / 4) / gridDim.y;
    const float4* base = (const float4*)(outs) + (long long)e * (ND_ELEMS / 4) + (long long)blockIdx.y * chunk4;
    const float4* gg4 = (const float4*)gg;
    float acc = 0.f;
    for (long long i = threadIdx.x; i < chunk4; i += blockDim.x) {
        float4 v = base[i];
        float4 g = gg4[i & (D4 - 1)];
        acc += v.x * g.x + v.y * g.y + v.z * g.z + v.w * g.w;
    }
    acc = warpReduceSum(acc);
    __shared__ float sh[8];
    int lane = threadIdx.x & 31, wid = threadIdx.x >> 5;
    if (lane == 0) sh[wid] = acc;
    __syncthreads();
    if (threadIdx.x == 0) {
        float x = 0;
        for (int q = 0; q < 8; q++) x += sh[q];
        atomicAdd(&glog[e], x);
    }
}

__global__ void gate_softmax_k(const float* __restrict__ glog, float* __restrict__ gw) {
    if (threadIdx.x == 0) {
        float l[EXP], m = -1e30f;
        for (int e = 0; e < EXP; e++) {
            l[e] = fminf(fmaxf(glog[e] / (float)NTOK, -10.f), 10.f);
            m = fmaxf(m, l[e]);
        }
        float s = 0.f;
        for (int e = 0; e < EXP; e++) { l[e] = expf(l[e] - m); s += l[e]; }
        for (int e = 0; e < EXP; e++) gw[e] = l[e] / s;
    }
}

__global__ void fuse_k(const float4* __restrict__ outs, const float* __restrict__ gw,
                       float4* __restrict__ fused) {
    long long i = (long long)blockIdx.x * 256 + threadIdx.x;
    constexpr long long N4 = ND_ELEMS / 4;
    if (i < N4) {
        float4 r = make_float4(0.f, 0.f, 0.f, 0.f);
#pragma unroll
        for (int e = 0; e < EXP; e++) {
            float4 v = outs[(long long)e * N4 + i];
            float gwe = gw[e];
            r.x += gwe * v.x; r.y += gwe * v.y; r.z += gwe * v.z; r.w += gwe * v.w;
        }
        fused[i] = r;
    }
}

__global__ void memupd_k(const float4* __restrict__ mem, const float4* __restrict__ upd4,
                         float4* __restrict__ o) {
    long long i = (long long)blockIdx.x * 256 + threadIdx.x;
    constexpr long long N4 = (long long)LMD_ELEMS / 4;
    if (i < N4) {
        float4 u = upd4[i];
#pragma unroll
        for (int e = 1; e < EXP; e++) {
            float4 v = upd4[(long long)e * N4 + i];
            u.x += v.x; u.y += v.y; u.z += v.z; u.w += v.w;
        }
        float4 mm = mem[i];
        float4 r;
        r.x = 0.9f * mm.x + fminf(fmaxf(0.1f * u.x, -0.1f), 0.1f);
        r.y = 0.9f * mm.y + fminf(fmaxf(0.1f * u.y, -0.1f), 0.1f);
        r.z = 0.9f * mm.z + fminf(fmaxf(0.1f * u.z, -0.1f), 0.1f);
        r.w = 0.9f * mm.w + fminf(fmaxf(0.1f * u.w, -0.1f), 0.1f);
        o[i] = r;
    }
}

// ---------------- host ----------------
static constexpr int stgH(int MT, int NT, bool ATR) {
    return (ATR ? 32 * (MT + 8) : MT * 40) + NT * 40;
}
#define SMEMH(MT, NT, ATR) (4 * stgH(MT, NT, ATR) * 2)

static void tohalf(const float* s, __half* d, long long n) {
    long long n4 = n / 4;
    tohalf_k<<<(int)((n4 + 255) / 256), 256>>>((const float4*)s, (__half2*)d, n4);
}

extern "C" void kernel_launch(void* const* d_in, const int* in_sizes, int n_in,
                              void* d_out, int out_size) {
    const float* tokens   = (const float*)d_in[0];
    const float* memories = (const float*)d_in[1];
    const float* ipw      = (const float*)d_in[2];
    const float* ipb      = (const float*)d_in[3];
    const float* opw      = (const float*)d_in[4];
    const float* opb      = (const float*)d_in[5];
    const float* w1       = (const float*)d_in[6];
    const float* b1       = (const float*)d_in[7];
    const float* w2       = (const float*)d_in[8];
    const float* b2       = (const float*)d_in[9];
    const float* n1w      = (const float*)d_in[10];
    const float* n1b      = (const float*)d_in[11];
    const float* n2w      = (const float*)d_in[12];
    const float* n2b      = (const float*)d_in[13];
    const float* aggw     = (const float*)d_in[14];
    const float* aggb     = (const float*)d_in[15];
    const float* gg       = (const float*)d_in[16];

    float* out = (float*)d_out;
    float* out_fused = out;
    float* out_gw = out + ND_ELEMS;
    float* out_mem = out + ND_ELEMS + EXP;

    static __half *h_xln = nullptr, *h_xlnT = nullptr, *h_x4 = nullptr, *h_qkv = nullptr,
                  *h_big = nullptr, *h_sa = nullptr, *h_x1r = nullptr, *h_xor = nullptr,
                  *h_xorT = nullptr, *h_xorS = nullptr, *h_vT = nullptr, *h_tmp = nullptr,
                  *h_retrp = nullptr, *h_ipw = nullptr, *h_opw = nullptr, *h_w1 = nullptr,
                  *h_w2 = nullptr, *h_aggw = nullptr, *h_mem = nullptr, *h_memT = nullptr;
    static float *p_op4 = nullptr, *p_x14 = nullptr, *p_out = nullptr,
                 *p_retr4 = nullptr, *p_upd4 = nullptr, *p_glog = nullptr, *p_rsum = nullptr;
    if (!h_xln) {
        cudaGetSymbolAddress((void**)&h_xln, gh_xln);
        cudaGetSymbolAddress((void**)&h_xlnT, gh_xlnT);
        cudaGetSymbolAddress((void**)&h_x4, gh_x4);
        cudaGetSymbolAddress((void**)&h_qkv, gh_qkv);
        cudaGetSymbolAddress((void**)&h_big, gh_big);
        cudaGetSymbolAddress((void**)&h_sa, gh_sa);
        cudaGetSymbolAddress((void**)&h_x1r, gh_x1r);
        cudaGetSymbolAddress((void**)&h_xor, gh_xor);
        cudaGetSymbolAddress((void**)&h_xorT, gh_xorT);
        cudaGetSymbolAddress((void**)&h_xorS, gh_xorS);
        cudaGetSymbolAddress((void**)&h_vT, gh_vT);
        cudaGetSymbolAddress((void**)&h_tmp, gh_tmp);
        cudaGetSymbolAddress((void**)&h_retrp, gh_retrp);
        cudaGetSymbolAddress((void**)&h_ipw, gh_ipw);
        cudaGetSymbolAddress((void**)&h_opw, gh_opw);
        cudaGetSymbolAddress((void**)&h_w1, gh_w1);
        cudaGetSymbolAddress((void**)&h_w2, gh_w2);
        cudaGetSymbolAddress((void**)&h_aggw, gh_aggw);
        cudaGetSymbolAddress((void**)&h_mem, gh_mem);
        cudaGetSymbolAddress((void**)&h_memT, gh_memT);
        cudaGetSymbolAddress((void**)&p_op4, g_op4);
        cudaGetSymbolAddress((void**)&p_x14, g_x14);
        cudaGetSymbolAddress((void**)&p_out, g_out);
        cudaGetSymbolAddress((void**)&p_retr4, g_retr4);
        cudaGetSymbolAddress((void**)&p_upd4, g_upd4);
        cudaGetSymbolAddress((void**)&p_glog, g_glog);
        cudaGetSymbolAddress((void**)&p_rsum, g_rsum);
        cudaFuncSetAttribute(gemmH<128, 128, false, 1, 0, 2>, cudaFuncAttributeMaxDynamicSharedMemorySize, SMEMH(128, 128, false));
        cudaFuncSetAttribute(gemmH<128, 128, false, 1, 1, 2>, cudaFuncAttributeMaxDynamicSharedMemorySize, SMEMH(128, 128, false));
        cudaFuncSetAttribute(gemmH<128, 128, false, 0, 0, 2>, cudaFuncAttributeMaxDynamicSharedMemorySize, SMEMH(128, 128, false));
        cudaFuncSetAttribute(gemmH<128, 128, true, 0, 0, 2>,  cudaFuncAttributeMaxDynamicSharedMemorySize, SMEMH(128, 128, true));
        cudaFuncSetAttribute(gemmH<64, 128, false, 1, 0, 3>,  cudaFuncAttributeMaxDynamicSharedMemorySize, SMEMH(64, 128, false));
        cudaFuncSetAttribute(gemmH<64, 128, false, 0, 0, 3>,  cudaFuncAttributeMaxDynamicSharedMemorySize, SMEMH(64, 128, false));
    }

    const float inv_sqrt_d = 1.0f / sqrtf((float)DIM);

    const long long LLND = ND_ELEMS;
    const long long QKVE = (long long)NTOK * 3 * DIM;
    float* rsumC = p_rsum;
    float* rsumM = p_rsum + EXP * NTOK;

    // launches 1-5 (6th = cross GEMM for ncu)
    zero_k<<<1, 256>>>(p_glog, EXP);
    zero_k<<<((EXP + EXP * NL) * NTOK + 255) / 256, 256>>>(p_rsum, (EXP + EXP * NL) * NTOK);
    ln_k<<<EXP * NTOK, 128>>>(tokens, h_xln);
    transpose_h<<<dim3(DIM / 32, EXP * NTOK / 32, 1), dim3(32, 8)>>>(
        h_xln, h_xlnT, EXP * NTOK, DIM, DIM, 0, 0);
    tohalf(ipw, h_ipw, (long long)EXP * 3 * DIM * DIM);

    // 1. cross logits -> exp(clip(.)) fp16 + rowsum  (MT=128)
    gemmH<128, 128, false, 1, 0, 2><<<dim3(48, 16, EXP), 256, SMEMH(128, 128, false)>>>(
        h_xln, h_xln, h_big, DIM, DIM, DIM, 3 * NTOK,
        LLND, 0, 0, 0, (long long)NTOK * 3 * NTOK, 0, 1,
        inv_sqrt_d, nullptr, 0, nullptr, 0, 0, 10.f, GFLAG_EXPOUT, -1, NTOK,
        rsumC, NTOK);

    tohalf(opw, h_opw, (long long)EXP * DIM * DIM);
    tohalf(w1, h_w1, (long long)EXP * FFD * DIM);
    tohalf(w2, h_w2, (long long)EXP * DIM * FFD);
    tohalf(aggw, h_aggw, (long long)DIM * NL * DIM);
    tohalf(memories, h_mem, (long long)LMD_ELEMS);
    transpose_fh<<<dim3(DIM / 32, MEMSZ / 32, NL), dim3(32, 8)>>>(
        memories, h_memT, MEMSZ, DIM, DIM, (long long)MEMSZ * DIM, (long long)MEMSZ * DIM);

    // 2. x = (expbig @ ctx)/rowsum + xln  (MT=128)
    gemmH<128, 128, false, 1, 1, 2><<<dim3(4, 16, EXP), 256, SMEMH(128, 128, false)>>>(
        h_big, h_xlnT, h_x4, 3 * NTOK, 3 * NTOK, EXP * NTOK, DIM,
        (long long)NTOK * 3 * NTOK, 0, 0, 0, LLND, 0, 1,
        1.f, nullptr, 0, h_xln, LLND, DIM, 0.f, GFLAG_KREMAP | GFLAG_RSCALE, -1, NTOK,
        rsumC, NTOK);
    // 3. qkv fp16 (MT=64)
    gemmH<64, 128, false, 1, 0, 3><<<dim3(12, 32, EXP), 256, SMEMH(64, 128, false)>>>(
        h_x4, h_ipw, h_qkv, DIM, DIM, DIM, 3 * DIM,
        LLND, 0, (long long)3 * DIM * DIM, 0, QKVE, 0, 1,
        1.f, ipb, 3 * DIM, nullptr, 0, 0, 0.f, 0, 0, 0, nullptr, 0);
    transpose_h<<<dim3(DIM / 32, NTOK / 32, EXP), dim3(32, 8)>>>(
        h_qkv + 2 * DIM, h_vT, NTOK, DIM, 3 * DIM, QKVE, LLND);
    // 4+5. flash attention
    flash_k<<<dim3(NTOK / 64, EXP * NH), 128>>>(h_qkv, h_vT, h_sa);
    // 6. out_proj fp32 out (MT=64)
    gemmH<64, 128, false, 0, 0, 3><<<dim3(4, 32, EXP), 256, SMEMH(64, 128, false)>>>(
        h_sa, h_opw, p_op4, DIM, DIM, DIM, DIM,
        LLND, 0, (long long)DIM * DIM, 0, LLND, 0, 1,
        1.f, opb, DIM, nullptr, 0, 0, 0.f, 0, 0, 0, nullptr, 0);
    ln_ra_k<1><<<EXP * NTOK, 128>>>(h_x4, p_op4, n1w, n1b, p_x14, h_x1r);
    // 7. ff1 relu fp16 (MT=128)
    gemmH<128, 128, false, 1, 0, 2><<<dim3(16, 16, EXP), 256, SMEMH(128, 128, false)>>>(
        h_x1r, h_w1, h_tmp, DIM, DIM, DIM, FFD,
        LLND, 0, (long long)FFD * DIM, 0, (long long)NTOK * FFD, 0, 1,
        1.f, b1, FFD, nullptr, 0, 0, 0.f, GFLAG_RELU, 0, 0, nullptr, 0);
    // 8. ff2 fp32 out (MT=64)
    gemmH<64, 128, false, 0, 0, 3><<<dim3(4, 32, EXP), 256, SMEMH(64, 128, false)>>>(
        h_tmp, h_w2, p_op4, FFD, FFD, FFD, DIM,
        (long long)NTOK * FFD, 0, (long long)DIM * FFD, 0, LLND, 0, 1,
        1.f, b2, DIM, nullptr, 0, 0, 0.f, 0, 0, 0, nullptr, 0);
    ln_ra_k<0><<<EXP * NTOK, 128>>>(p_x14, p_op4, n2w, n2b, p_out, h_xor);
    transpose_h<<<dim3(DIM / 32, NTOK / 32, EXP), dim3(32, 8)>>>(
        h_xor, h_xorT, NTOK, DIM, DIM, LLND, LLND);
    // 9. memory logits -> exp(clip(.)) fp16 + rowsum  (MT=128)
    gemmH<128, 128, false, 1, 0, 2><<<dim3(32, 16, EXP * NL), 256, SMEMH(128, 128, false)>>>(
        h_xor, h_mem, h_big, DIM, DIM, DIM, MEMSZ,
        LLND, 0, 0, (long long)MEMSZ * DIM, (long long)NL * NTOK * MEMSZ, (long long)NTOK * MEMSZ, NL,
        inv_sqrt_d, nullptr, 0, nullptr, 0, 0, 10.f, GFLAG_EXPOUT, 0, 0,
        rsumM, NTOK);
    // 9b. xorS = xorT * 4096/rowsum
    scalexor_k<<<(int)(((long long)EXP * NL * DIM * (NTOK / 2) + 255) / 256), 256>>>(
        (const __half2*)h_xorT, rsumM, (__half2*)h_xorS);
    // 10. retr = (expbig @ memT)/rowsum fp32 (MT=128)
    gemmH<128, 128, false, 0, 0, 2><<<dim3(4, 16, EXP * NL), 256, SMEMH(128, 128, false)>>>(
        h_big, h_memT, p_retr4, MEMSZ, MEMSZ, MEMSZ, DIM,
        (long long)NL * NTOK * MEMSZ, (long long)NTOK * MEMSZ, 0, (long long)MEMSZ * DIM,
        (long long)NL * NTOK * DIM, (long long)NTOK * DIM, NL,
        1.f, nullptr, 0, nullptr, 0, 0, 0.f, GFLAG_RSCALE, 0, 0,
        rsumM, NTOK);
    // 11. upd = clip((expbig^T @ xorS)/4096, 1) fp32 (MT=128 ATR)
    gemmH<128, 128, true, 0, 0, 2><<<dim3(4, 32, EXP * NL), 256, SMEMH(128, 128, true)>>>(
        h_big, h_xorS, p_upd4, NTOK, MEMSZ, NTOK, DIM,
        (long long)NL * NTOK * MEMSZ, (long long)NTOK * MEMSZ,
        (long long)NL * LLND, LLND,
        (long long)LMD_ELEMS, (long long)MEMSZ * DIM, NL,
        1.f / 4096.f, nullptr, 0, nullptr, 0, 0, 1.f, 0, 0, 0, nullptr, 0);
    permute_k<<<(EXP * NL * ND_ELEMS / 4 + 255) / 256, 256>>>((const float4*)p_retr4, (__half2*)h_retrp);
    // 12. outs += retrp @ aggw^T + aggb (MT=64)
    gemmH<64, 128, false, 0, 0, 3><<<dim3(4, 32, EXP), 256, SMEMH(64, 128, false)>>>(
        h_retrp, h_aggw, p_out, NL * DIM, NL * DIM, NL * DIM, DIM,
        (long long)NTOK * NL * DIM, 0, 0, 0, LLND, 0, 1,
        1.f, aggb, 0, p_out, LLND, DIM, 0.f, 0, 0, 0, nullptr, 0);

    dim3 ggrid(EXP, 16);
    gate_dot_k<<<ggrid, 256>>>(p_out, gg, p_glog);
    gate_softmax_k<<<1, 32>>>(p_glog, out_gw);
    fuse_k<<<(ND_ELEMS / 4 + 255) / 256, 256>>>((const float4*)p_out, out_gw, (float4*)out_fused);
    memupd_k<<<(LMD_ELEMS / 4 + 255) / 256, 256>>>((const float4*)memories, (const float4*)p_upd4, (float4*)out_mem);

    (void)in_sizes; (void)n_in; (void)out_size;
}